// round 6
// baseline (speedup 1.0000x reference)
#include <cuda_runtime.h>
#include <cuda_fp16.h>
#include <cstdint>

// Renderer_45612552684068 — round 5: conv1/conv2/conv3 on fp16 mma.m16n8k16
// (fp32 accum). fp16 mantissa == tf32 mantissa, but half the LDS per MAC.

static constexpr int NB   = 4;
static constexpr int NH   = 512;
static constexpr int NW   = 512;
static constexpr int HID  = 128;
static constexpr int CIN  = 29;   // DIM - 3
static constexpr int C1C  = 64;
static constexpr int C2C  = 128;

__device__ __align__(16) float g_x  [NB * CIN * NH * NW];
__device__ __align__(16) float g_rgb[NB * 3   * NH * NW];
__device__ __align__(16) float g_e1 [NB * C1C * NH * NW];
__device__ __align__(16) float g_d  [NB * C2C * (NH/2) * (NW/2)];
__device__ __align__(16) float g_m  [NB * C1C * NH * NW];

__device__ __forceinline__ void mma_f16(float c[4],
                                        uint32_t a0, uint32_t a1,
                                        uint32_t a2, uint32_t a3,
                                        uint32_t b0, uint32_t b1) {
    asm volatile(
        "mma.sync.aligned.m16n8k16.row.col.f32.f16.f16.f32 "
        "{%0,%1,%2,%3}, {%4,%5,%6,%7}, {%8,%9}, {%0,%1,%2,%3};"
        : "+f"(c[0]), "+f"(c[1]), "+f"(c[2]), "+f"(c[3])
        : "r"(a0), "r"(a1), "r"(a2), "r"(a3), "r"(b0), "r"(b1));
}

// ---------------------------------------------------------------------------
// MLP kernel (unchanged, passing).
static constexpr int MLP_SMEM_FLOATS = 16384 + 16512 + 16384 + 1024 + 128 + 128;
static constexpr int MLP_SMEM_BYTES  = MLP_SMEM_FLOATS * 4;

__global__ __launch_bounds__(256, 1)
void mlp_kernel(const float* __restrict__ zbuf, const float* __restrict__ ray,
                const float* __restrict__ w0, const float* __restrict__ b0,
                const float* __restrict__ w1, const float* __restrict__ b1,
                const float* __restrict__ w2, const float* __restrict__ b2)
{
    extern __shared__ float sm[];
    float* sh_h1  = sm;
    float* sh_h2  = sh_h1 + 16384;
    float* sh_w   = sh_h2 + 16512;
    float* sh_fin = sh_w  + 16384;
    float* sh_z   = sh_fin + 1024;
    float* sh_b1  = sh_z + 128;

    const int tid   = threadIdx.x;
    const int pbase = blockIdx.x * 128;

    {
        #pragma unroll 8
        for (int t = tid; t < 16384; t += 256) sh_w[t] = w1[t];
        if (tid < 128) sh_b1[tid] = b1[tid];
    }

    if (tid < 128) {
        int pix = pbase + tid;
        int b = pix >> 18;
        int y = (pix >> 9) & 511;
        int x = pix & 511;
        int pi = (b * NH + y) * NW + x;
        float z = zbuf[pi];
        const float* r = ray + pi * 7;
        float t  = z / r[6];
        float d0 = r[3], d1 = r[4], d2 = r[5];
        sh_fin[tid * 8 + 0] = fmaf(d0, t, r[0]);
        sh_fin[tid * 8 + 1] = fmaf(d1, t, r[1]);
        sh_fin[tid * 8 + 2] = fmaf(d2, t, r[2]);
        sh_fin[tid * 8 + 3] = d0;
        sh_fin[tid * 8 + 4] = d1;
        sh_fin[tid * 8 + 5] = d2;
        sh_z[tid] = z;
    }
    __syncthreads();

    {
        const int p  = tid & 127;
        const int ob = (tid >> 7) * 64;
        float f0 = sh_fin[p*8+0], f1 = sh_fin[p*8+1], f2 = sh_fin[p*8+2];
        float f3 = sh_fin[p*8+3], f4 = sh_fin[p*8+4], f5 = sh_fin[p*8+5];
        #pragma unroll 8
        for (int o = ob; o < ob + 64; o++) {
            float acc = b0[o];
            acc = fmaf(f0, w0[0*HID + o], acc);
            acc = fmaf(f1, w0[1*HID + o], acc);
            acc = fmaf(f2, w0[2*HID + o], acc);
            acc = fmaf(f3, w0[3*HID + o], acc);
            acc = fmaf(f4, w0[4*HID + o], acc);
            acc = fmaf(f5, w0[5*HID + o], acc);
            sh_h1[o * 128 + p] = fmaxf(acc, 0.f);
        }
    }
    __syncthreads();

    const int tx = tid & 15;
    const int ty = tid >> 4;
    {
        float c[8][8];
        #pragma unroll
        for (int i = 0; i < 8; i++)
            #pragma unroll
            for (int j = 0; j < 8; j++) c[i][j] = 0.f;

        #pragma unroll 2
        for (int k = 0; k < 128; k++) {
            float a[8], bv[8];
            float4 t0 = *(const float4*)&sh_h1[k*128 + ty*8];
            float4 t1 = *(const float4*)&sh_h1[k*128 + ty*8 + 4];
            a[0]=t0.x; a[1]=t0.y; a[2]=t0.z; a[3]=t0.w;
            a[4]=t1.x; a[5]=t1.y; a[6]=t1.z; a[7]=t1.w;
            float4 u0 = *(const float4*)&sh_w[k*128 + tx*8];
            float4 u1 = *(const float4*)&sh_w[k*128 + tx*8 + 4];
            bv[0]=u0.x; bv[1]=u0.y; bv[2]=u0.z; bv[3]=u0.w;
            bv[4]=u1.x; bv[5]=u1.y; bv[6]=u1.z; bv[7]=u1.w;
            #pragma unroll
            for (int i = 0; i < 8; i++)
                #pragma unroll
                for (int j = 0; j < 8; j++)
                    c[i][j] = fmaf(a[i], bv[j], c[i][j]);
        }
        #pragma unroll
        for (int j = 0; j < 8; j++) {
            float bb = sh_b1[tx*8 + j];
            #pragma unroll
            for (int i = 0; i < 8; i++)
                sh_h2[(tx*8 + j) * 129 + (ty*8 + i)] = fmaxf(c[i][j] + bb, 0.f);
        }
    }
    __syncthreads();

    {
        for (int t = tid; t < 128*32; t += 256) sh_w[t] = w2[t];
    }
    __syncthreads();

    {
        const int p  = tid & 127;
        const int ob = (tid >> 7) * 16;
        float f[16];
        #pragma unroll
        for (int j = 0; j < 16; j++) f[j] = b2[ob + j];
        for (int k = 0; k < 128; k++) {
            float a = sh_h2[k * 129 + p];
            #pragma unroll
            for (int g = 0; g < 4; g++) {
                float4 wv = *(const float4*)&sh_w[k*32 + ob + g*4];
                f[g*4+0] = fmaf(a, wv.x, f[g*4+0]);
                f[g*4+1] = fmaf(a, wv.y, f[g*4+1]);
                f[g*4+2] = fmaf(a, wv.z, f[g*4+2]);
                f[g*4+3] = fmaf(a, wv.w, f[g*4+3]);
            }
        }
        int pix = pbase + p;
        int b = pix >> 18;
        int y = (pix >> 9) & 511;
        int x = pix & 511;
        bool mask = sh_z[p] > 0.f;
        #pragma unroll
        for (int j = 0; j < 16; j++) {
            int cch = ob + j;
            float v = mask ? f[j] : 1.0f;
            if (cch < CIN)
                g_x[((b*CIN + cch) * NH + y) * NW + x] = v;
            else
                g_rgb[((b*3 + (cch - CIN)) * NH + y) * NW + x] = v;
        }
    }
}

// ---------------------------------------------------------------------------
// Unified fp16 3x3 SAME conv (stride 1): mode 0 = conv1 (g_x, cin 29 -> g_e1),
// mode 1 = conv3 (upsampled g_d ++ g_e1, cin 192 -> g_m). 64 cout. relu.
// CTA 256 thr (8 warps), tile 16x16 px. warp = 2 y-rows, 8 nt (64 co).
// smem: in_s half[18][18][24] (ci-pad 24 halves -> conflict-free A loads),
//       w_s  half[9][64][24]  (co-stride 24 halves -> conflict-free B loads).
static constexpr int CP   = 24;                   // ci pad (halves)
static constexpr int C13_INS_HALVES = 18 * 18 * CP;    // 7776
static constexpr int C13_WS_HALVES  = 9 * 64 * CP;     // 13824
static constexpr int C13_SMEM_BYTES = (C13_INS_HALVES + C13_WS_HALVES) * 2; // 43200

__global__ __launch_bounds__(256)
void conv13_f16_kernel(const float* __restrict__ wk, int cin_total, int mode)
{
    extern __shared__ __half c13sm[];
    __half* in_s = c13sm;                    // [(yy*18+xx)*24 + ci]
    __half* w_s  = c13sm + C13_INS_HALVES;   // [tap*64*24 + co*24 + k]

    const int tid  = threadIdx.x;
    const int w    = tid >> 5;
    const int lane = tid & 31;
    const int gid  = lane >> 2;
    const int tig  = lane & 3;

    const int x0 = blockIdx.x * 16, y0 = blockIdx.y * 16, b = blockIdx.z;

    float c[2][8][4];
    #pragma unroll
    for (int mt = 0; mt < 2; mt++)
        #pragma unroll
        for (int nt = 0; nt < 8; nt++)
            #pragma unroll
            for (int q = 0; q < 4; q++) c[mt][nt][q] = 0.f;

    const int wrow = cin_total;   // weight ci-stride

    for (int ci0 = 0; ci0 < cin_total; ci0 += 16) {
        __syncthreads();
        // stage input 18x18 x 16ci -> half
        for (int t = tid; t < 18 * 18 * 16; t += 256) {
            int ci = t & 15;
            int pos = t >> 4;
            int yy = pos / 18, xx = pos - yy * 18;
            int iy = y0 - 1 + yy, ix = x0 - 1 + xx;
            int cin = ci0 + ci;
            float v = 0.f;
            if (cin < cin_total && iy >= 0 && iy < NH && ix >= 0 && ix < NW) {
                if (mode == 0) {
                    v = g_x[((b*CIN + cin) * NH + iy) * NW + ix];
                } else {
                    if (cin < C2C)
                        v = g_d[((b*C2C + cin) * (NH/2) + (iy >> 1)) * (NW/2) + (ix >> 1)];
                    else
                        v = g_e1[((b*C1C + (cin - C2C)) * NH + iy) * NW + ix];
                }
            }
            in_s[pos * CP + ci] = __float2half(v);
        }
        // stage weights: 64co x 16k x 9tap
        for (int t = tid; t < 1024; t += 256) {
            int co = t & 63, k = t >> 6;
            int cin = ci0 + k;
            if (cin < cin_total) {
                const float* src = wk + (co * wrow + cin) * 9;
                #pragma unroll
                for (int tap = 0; tap < 9; tap++)
                    w_s[(tap * 64 + co) * CP + k] = __float2half(src[tap]);
            } else {
                #pragma unroll
                for (int tap = 0; tap < 9; tap++)
                    w_s[(tap * 64 + co) * CP + k] = __half(0.f);
            }
        }
        __syncthreads();

        #pragma unroll
        for (int tap = 0; tap < 9; tap++) {
            const int ky = tap / 3, kx = tap - 3 * (tap / 3);
            uint32_t a[2][4];
            #pragma unroll
            for (int mt = 0; mt < 2; mt++) {
                const int yl = 2 * w + mt;
                const __half* base = in_s + ((yl + ky) * 18 + kx) * CP;
                const __half* p0 = base + gid * CP + 2 * tig;        // row gid
                const __half* p1 = base + (gid + 8) * CP + 2 * tig;  // row gid+8
                a[mt][0] = *(const uint32_t*)(p0);
                a[mt][1] = *(const uint32_t*)(p1);
                a[mt][2] = *(const uint32_t*)(p0 + 8);
                a[mt][3] = *(const uint32_t*)(p1 + 8);
            }
            const __half* wb = w_s + (tap * 64 + gid) * CP + 2 * tig;
            #pragma unroll
            for (int nt = 0; nt < 8; nt++) {
                const __half* pb = wb + nt * 8 * CP;
                uint32_t b0 = *(const uint32_t*)(pb);
                uint32_t b1 = *(const uint32_t*)(pb + 8);
                mma_f16(c[0][nt], a[0][0], a[0][1], a[0][2], a[0][3], b0, b1);
                mma_f16(c[1][nt], a[1][0], a[1][1], a[1][2], a[1][3], b0, b1);
            }
        }
    }

    float* dst = (mode == 0) ? g_e1 : g_m;
    #pragma unroll
    for (int mt = 0; mt < 2; mt++) {
        const int y = y0 + 2 * w + mt;
        #pragma unroll
        for (int nt = 0; nt < 8; nt++) {
            const int co = 8 * nt + 2 * tig;
            const int x1 = x0 + gid, x2 = x0 + gid + 8;
            dst[((b*C1C + co    ) * NH + y) * NW + x1] = fmaxf(c[mt][nt][0], 0.f);
            dst[((b*C1C + co + 1) * NH + y) * NW + x1] = fmaxf(c[mt][nt][1], 0.f);
            dst[((b*C1C + co    ) * NH + y) * NW + x2] = fmaxf(c[mt][nt][2], 0.f);
            dst[((b*C1C + co + 1) * NH + y) * NW + x2] = fmaxf(c[mt][nt][3], 0.f);
        }
    }
}

// ---------------------------------------------------------------------------
// conv2 fp16: 64 -> 128, 3x3 stride 2, SAME (pad_lo=0), relu. out 256x256.
// CTA 512 thr (16 warps), tile 16x16 out px, 128 co.
// warp: coh = w>>3 (co 0..63 / 64..127), wy = w&7 (rows 2wy, 2wy+1).
// smem: in_s half[33][33][20] (ci-pad 20 halves: x-stride 2 in A loads still
//       hits 32 distinct banks), w_s half[9][128][24].
static constexpr int C2P = 20;
static constexpr int C2_INS_HALVES = 33 * 33 * C2P;     // 21780
static constexpr int C2_WS_HALVES  = 9 * 128 * 24;      // 27648
static constexpr int C2_SMEM_BYTES = (C2_INS_HALVES + C2_WS_HALVES) * 2; // 98856

__global__ __launch_bounds__(512)
void conv2_f16_kernel(const float* __restrict__ wk)
{
    extern __shared__ __half c2sm[];
    __half* in_s = c2sm;                    // [(yy*33+xx)*20 + ci]
    __half* w_s  = c2sm + C2_INS_HALVES;    // [tap*128*24 + co*24 + k]

    const int tid  = threadIdx.x;
    const int w    = tid >> 5;
    const int lane = tid & 31;
    const int gid  = lane >> 2;
    const int tig  = lane & 3;
    const int coh  = w >> 3;       // co half
    const int wy   = w & 7;        // y pair

    const int x0 = blockIdx.x * 16, y0 = blockIdx.y * 16, b = blockIdx.z;

    float c[2][8][4];
    #pragma unroll
    for (int mt = 0; mt < 2; mt++)
        #pragma unroll
        for (int nt = 0; nt < 8; nt++)
            #pragma unroll
            for (int q = 0; q < 4; q++) c[mt][nt][q] = 0.f;

    for (int ci0 = 0; ci0 < C1C; ci0 += 16) {
        __syncthreads();
        // stage input 33x33 x 16ci (in coords 2*y0 .. 2*y0+32; pad_lo = 0)
        for (int t = tid; t < 33 * 33 * 16; t += 512) {
            int ci = t & 15;
            int pos = t >> 4;
            int yy = pos / 33, xx = pos - yy * 33;
            int iy = 2 * y0 + yy, ix = 2 * x0 + xx;
            float v = 0.f;
            if (iy < NH && ix < NW)
                v = g_e1[((b*C1C + ci0 + ci) * NH + iy) * NW + ix];
            in_s[pos * C2P + ci] = __float2half(v);
        }
        // stage weights: 128co x 16k x 9tap
        for (int t = tid; t < 2048; t += 512) {
            int co = t & 127, k = t >> 7;
            const float* src = wk + (co * C1C + ci0 + k) * 9;
            #pragma unroll
            for (int tap = 0; tap < 9; tap++)
                w_s[(tap * 128 + co) * 24 + k] = __float2half(src[tap]);
        }
        __syncthreads();

        #pragma unroll
        for (int tap = 0; tap < 9; tap++) {
            const int ky = tap / 3, kx = tap - 3 * (tap / 3);
            uint32_t a[2][4];
            #pragma unroll
            for (int mt = 0; mt < 2; mt++) {
                const int yl = 2 * wy + mt;                  // out row
                const __half* base = in_s + ((2 * yl + ky) * 33 + kx) * C2P;
                const __half* p0 = base + (2 * gid) * C2P + 2 * tig;
                const __half* p1 = base + (2 * gid + 16) * C2P + 2 * tig;
                a[mt][0] = *(const uint32_t*)(p0);
                a[mt][1] = *(const uint32_t*)(p1);
                a[mt][2] = *(const uint32_t*)(p0 + 8);
                a[mt][3] = *(const uint32_t*)(p1 + 8);
            }
            const __half* wb = w_s + (tap * 128 + coh * 64 + gid) * 24 + 2 * tig;
            #pragma unroll
            for (int nt = 0; nt < 8; nt++) {
                const __half* pb = wb + nt * 8 * 24;
                uint32_t b0 = *(const uint32_t*)(pb);
                uint32_t b1 = *(const uint32_t*)(pb + 8);
                mma_f16(c[0][nt], a[0][0], a[0][1], a[0][2], a[0][3], b0, b1);
                mma_f16(c[1][nt], a[1][0], a[1][1], a[1][2], a[1][3], b0, b1);
            }
        }
    }

    #pragma unroll
    for (int mt = 0; mt < 2; mt++) {
        const int y = y0 + 2 * wy + mt;
        #pragma unroll
        for (int nt = 0; nt < 8; nt++) {
            const int co = coh * 64 + 8 * nt + 2 * tig;
            const int x1 = x0 + gid, x2 = x0 + gid + 8;
            g_d[((b*C2C + co    ) * (NH/2) + y) * (NW/2) + x1] = fmaxf(c[mt][nt][0], 0.f);
            g_d[((b*C2C + co + 1) * (NH/2) + y) * (NW/2) + x1] = fmaxf(c[mt][nt][1], 0.f);
            g_d[((b*C2C + co    ) * (NH/2) + y) * (NW/2) + x2] = fmaxf(c[mt][nt][2], 0.f);
            g_d[((b*C2C + co + 1) * (NH/2) + y) * (NW/2) + x2] = fmaxf(c[mt][nt][3], 0.f);
        }
    }
}

// ---------------------------------------------------------------------------
// conv4: 64->3, 3x3 SAME, + rgb_res. (unchanged, passing)
__global__ __launch_bounds__(256, 2)
void conv4_kernel(const float* __restrict__ wk, float* __restrict__ out)
{
    __shared__ __align__(16) float in_s[2][34][67];
    __shared__ __align__(16) float w_s[2][9][4];
    const int tid = threadIdx.x;
    const int xg = tid & 7, yy = tid >> 3;
    const int x0 = blockIdx.x * 64, y0 = blockIdx.y * 32, b = blockIdx.z;

    float acc[3][8];
    #pragma unroll
    for (int j = 0; j < 3; j++)
        #pragma unroll
        for (int i = 0; i < 8; i++) acc[j][i] = 0.f;

    for (int c0 = 0; c0 < C1C; c0 += 2) {
        __syncthreads();
        for (int t = tid; t < 2 * 34 * 66; t += 256) {
            int ci = t / 2244, rem = t - ci * 2244;
            int rr = rem / 66, cx = rem - rr * 66;
            int iy = y0 - 1 + rr, ix = x0 - 1 + cx;
            float v = 0.f;
            if (iy >= 0 && iy < NH && ix >= 0 && ix < NW)
                v = g_m[((b*C1C + c0 + ci) * NH + iy) * NW + ix];
            in_s[ci][rr][cx] = v;
        }
        if (tid < 2 * 27) {
            int ci = tid / 27, rem = tid - ci * 27;
            int co = rem % 3, tap = rem / 3;
            w_s[ci][tap][co] = wk[(co * C1C + c0 + ci) * 9 + tap];
        }
        __syncthreads();
        #pragma unroll
        for (int ci = 0; ci < 2; ci++) {
            #pragma unroll
            for (int kh = 0; kh < 3; kh++) {
                float a[10];
                #pragma unroll
                for (int c = 0; c < 10; c++) a[c] = in_s[ci][yy + kh][xg*8 + c];
                #pragma unroll
                for (int kw = 0; kw < 3; kw++) {
                    int tap = kh*3 + kw;
                    float w0v = w_s[ci][tap][0];
                    float w1v = w_s[ci][tap][1];
                    float w2v = w_s[ci][tap][2];
                    #pragma unroll
                    for (int i = 0; i < 8; i++) {
                        acc[0][i] = fmaf(a[kw + i], w0v, acc[0][i]);
                        acc[1][i] = fmaf(a[kw + i], w1v, acc[1][i]);
                        acc[2][i] = fmaf(a[kw + i], w2v, acc[2][i]);
                    }
                }
            }
        }
    }
    const int y = y0 + yy, xb = x0 + xg*8;
    #pragma unroll
    for (int j = 0; j < 3; j++) {
        int base = ((b*3 + j) * NH + y) * NW + xb;
        float4 r0 = *(const float4*)&g_rgb[base];
        float4 r1 = *(const float4*)&g_rgb[base + 4];
        out[base + 0] = acc[j][0] + r0.x;
        out[base + 1] = acc[j][1] + r0.y;
        out[base + 2] = acc[j][2] + r0.z;
        out[base + 3] = acc[j][3] + r0.w;
        out[base + 4] = acc[j][4] + r1.x;
        out[base + 5] = acc[j][5] + r1.y;
        out[base + 6] = acc[j][6] + r1.z;
        out[base + 7] = acc[j][7] + r1.w;
    }
}

// ---------------------------------------------------------------------------
extern "C" void kernel_launch(void* const* d_in, const int* in_sizes, int n_in,
                              void* d_out, int out_size)
{
    const float* zbuf = (const float*)d_in[0];
    const float* ray  = (const float*)d_in[1];
    const float* w0 = (const float*)d_in[4];
    const float* b0 = (const float*)d_in[5];
    const float* w1 = (const float*)d_in[6];
    const float* b1 = (const float*)d_in[7];
    const float* w2 = (const float*)d_in[8];
    const float* b2 = (const float*)d_in[9];
    const float* k1 = (const float*)d_in[10];
    const float* k2 = (const float*)d_in[11];
    const float* k3 = (const float*)d_in[12];
    const float* k4 = (const float*)d_in[13];
    float* out = (float*)d_out;

    cudaFuncSetAttribute(mlp_kernel,
                         cudaFuncAttributeMaxDynamicSharedMemorySize,
                         MLP_SMEM_BYTES);
    cudaFuncSetAttribute(conv13_f16_kernel,
                         cudaFuncAttributeMaxDynamicSharedMemorySize,
                         C13_SMEM_BYTES);
    cudaFuncSetAttribute(conv2_f16_kernel,
                         cudaFuncAttributeMaxDynamicSharedMemorySize,
                         C2_SMEM_BYTES);

    mlp_kernel<<<(NB*NH*NW)/128, 256, MLP_SMEM_BYTES>>>(zbuf, ray,
                                                        w0, b0, w1, b1, w2, b2);
    conv13_f16_kernel<<<dim3(NW/16, NH/16, NB), 256, C13_SMEM_BYTES>>>(k1, CIN, 0);
    conv2_f16_kernel<<<dim3(16, 16, NB), 512, C2_SMEM_BYTES>>>(k2);
    conv13_f16_kernel<<<dim3(NW/16, NH/16, NB), 256, C13_SMEM_BYTES>>>(k3, C2C + C1C, 1);
    conv4_kernel<<<dim3(NW/64, NH/32, NB), 256>>>(k4, out);
}

// round 9
// speedup vs baseline: 3.4059x; 3.4059x over previous
#include <cuda_runtime.h>
#include <cuda_fp16.h>
#include <cstdint>

// Renderer_45612552684068 — round 7 (resubmit of round-6 design after infra
// failure): half NHWC activations, fp16 mma convs, coalesced staging,
// conflict-free smem pads.

static constexpr int NB   = 4;
static constexpr int NH   = 512;
static constexpr int NW   = 512;
static constexpr int HID  = 128;
static constexpr int CIN  = 29;
static constexpr int C1C  = 64;
static constexpr int C2C  = 128;

// activations (half NHWC) + rgb residual (float NCHW)
__device__ __align__(16) float  g_rgb[NB * 3 * NH * NW];
__device__ __align__(16) __half g_xh [NB * NH * NW * 32];
__device__ __align__(16) __half g_e1h[NB * NH * NW * 64];
__device__ __align__(16) __half g_dh [NB * (NH/2) * (NW/2) * 128];
__device__ __align__(16) __half g_mh [NB * NH * NW * 64];

// prepacked half weights
static constexpr int W1H_SZ = 9 * 64 * 40;            // [tap][co][40]
static constexpr int W2H_SZ = 4 * 9 * 128 * 24;       // [c][tap][co][24]
static constexpr int W3H_SZ = 6 * 9 * 64 * 40;        // [c][tap][co][40]
static constexpr int W4H_SZ = 4 * 9 * 8 * 24;         // [c][tap][co8][24]
__device__ __align__(16) __half w1h[W1H_SZ];
__device__ __align__(16) __half w2h[W2H_SZ];
__device__ __align__(16) __half w3h[W3H_SZ];
__device__ __align__(16) __half w4h[W4H_SZ];

__device__ __forceinline__ void mma_f16(float c[4],
                                        uint32_t a0, uint32_t a1,
                                        uint32_t a2, uint32_t a3,
                                        uint32_t b0, uint32_t b1) {
    asm volatile(
        "mma.sync.aligned.m16n8k16.row.col.f32.f16.f16.f32 "
        "{%0,%1,%2,%3}, {%4,%5,%6,%7}, {%8,%9}, {%0,%1,%2,%3};"
        : "+f"(c[0]), "+f"(c[1]), "+f"(c[2]), "+f"(c[3])
        : "r"(a0), "r"(a1), "r"(a2), "r"(a3), "r"(b0), "r"(b1));
}

// ---------------------------------------------------------------------------
// prep_weights: fp32 OIHW -> chunked half layouts (zero-padded).
__global__ void prep_weights(const float* __restrict__ k1, const float* __restrict__ k2,
                             const float* __restrict__ k3, const float* __restrict__ k4)
{
    int i = blockIdx.x * 256 + threadIdx.x;
    if (i < W1H_SZ) {
        int tap = i / 2560, r = i % 2560, co = r / 40, k = r % 40;
        w1h[i] = __float2half(k < CIN ? k1[(co * CIN + k) * 9 + tap] : 0.f);
        return;
    }
    i -= W1H_SZ;
    if (i < W2H_SZ) {
        int c = i / 27648, r = i % 27648;
        int tap = r / 3072, co = (r % 3072) / 24, k = r % 24;
        w2h[i] = __float2half(k < 16 ? k2[(co * C1C + c * 16 + k) * 9 + tap] : 0.f);
        return;
    }
    i -= W2H_SZ;
    if (i < W3H_SZ) {
        int c = i / 23040, r = i % 23040;
        int tap = r / 2560, co = (r % 2560) / 40, k = r % 40;
        w3h[i] = __float2half(k < 32 ? k3[(co * (C2C + C1C) + c * 32 + k) * 9 + tap] : 0.f);
        return;
    }
    i -= W3H_SZ;
    if (i < W4H_SZ) {
        int c = i / 1728, r = i % 1728;
        int tap = r / 192, co = (r % 192) / 24, k = r % 24;
        w4h[i] = __float2half((k < 16 && co < 3) ? k4[(co * C1C + c * 16 + k) * 9 + tap] : 0.f);
    }
}

// ---------------------------------------------------------------------------
// MLP (fp32; outputs g_xh half NHWC + g_rgb float NCHW)
static constexpr int MLP_SMEM_FLOATS = 16384 + 16512 + 16384 + 1024 + 128 + 128;
static constexpr int MLP_SMEM_BYTES  = MLP_SMEM_FLOATS * 4;

__global__ __launch_bounds__(256, 1)
void mlp_kernel(const float* __restrict__ zbuf, const float* __restrict__ ray,
                const float* __restrict__ w0, const float* __restrict__ b0,
                const float* __restrict__ w1, const float* __restrict__ b1,
                const float* __restrict__ w2, const float* __restrict__ b2)
{
    extern __shared__ float sm[];
    float* sh_h1  = sm;
    float* sh_h2  = sh_h1 + 16384;
    float* sh_w   = sh_h2 + 16512;
    float* sh_fin = sh_w  + 16384;
    float* sh_z   = sh_fin + 1024;
    float* sh_b1  = sh_z + 128;

    const int tid   = threadIdx.x;
    const int pbase = blockIdx.x * 128;

    {
        #pragma unroll 8
        for (int t = tid; t < 16384; t += 256) sh_w[t] = w1[t];
        if (tid < 128) sh_b1[tid] = b1[tid];
    }

    if (tid < 128) {
        int pix = pbase + tid;
        int b = pix >> 18;
        int y = (pix >> 9) & 511;
        int x = pix & 511;
        int pi = (b * NH + y) * NW + x;
        float z = zbuf[pi];
        const float* r = ray + pi * 7;
        float t  = z / r[6];
        float d0 = r[3], d1 = r[4], d2 = r[5];
        sh_fin[tid * 8 + 0] = fmaf(d0, t, r[0]);
        sh_fin[tid * 8 + 1] = fmaf(d1, t, r[1]);
        sh_fin[tid * 8 + 2] = fmaf(d2, t, r[2]);
        sh_fin[tid * 8 + 3] = d0;
        sh_fin[tid * 8 + 4] = d1;
        sh_fin[tid * 8 + 5] = d2;
        sh_z[tid] = z;
    }
    __syncthreads();

    {
        const int p  = tid & 127;
        const int ob = (tid >> 7) * 64;
        float f0 = sh_fin[p*8+0], f1 = sh_fin[p*8+1], f2 = sh_fin[p*8+2];
        float f3 = sh_fin[p*8+3], f4 = sh_fin[p*8+4], f5 = sh_fin[p*8+5];
        #pragma unroll 8
        for (int o = ob; o < ob + 64; o++) {
            float acc = b0[o];
            acc = fmaf(f0, w0[0*HID + o], acc);
            acc = fmaf(f1, w0[1*HID + o], acc);
            acc = fmaf(f2, w0[2*HID + o], acc);
            acc = fmaf(f3, w0[3*HID + o], acc);
            acc = fmaf(f4, w0[4*HID + o], acc);
            acc = fmaf(f5, w0[5*HID + o], acc);
            sh_h1[o * 128 + p] = fmaxf(acc, 0.f);
        }
    }
    __syncthreads();

    const int tx = tid & 15;
    const int ty = tid >> 4;
    {
        float c[8][8];
        #pragma unroll
        for (int i = 0; i < 8; i++)
            #pragma unroll
            for (int j = 0; j < 8; j++) c[i][j] = 0.f;

        #pragma unroll 2
        for (int k = 0; k < 128; k++) {
            float a[8], bv[8];
            float4 t0 = *(const float4*)&sh_h1[k*128 + ty*8];
            float4 t1 = *(const float4*)&sh_h1[k*128 + ty*8 + 4];
            a[0]=t0.x; a[1]=t0.y; a[2]=t0.z; a[3]=t0.w;
            a[4]=t1.x; a[5]=t1.y; a[6]=t1.z; a[7]=t1.w;
            float4 u0 = *(const float4*)&sh_w[k*128 + tx*8];
            float4 u1 = *(const float4*)&sh_w[k*128 + tx*8 + 4];
            bv[0]=u0.x; bv[1]=u0.y; bv[2]=u0.z; bv[3]=u0.w;
            bv[4]=u1.x; bv[5]=u1.y; bv[6]=u1.z; bv[7]=u1.w;
            #pragma unroll
            for (int i = 0; i < 8; i++)
                #pragma unroll
                for (int j = 0; j < 8; j++)
                    c[i][j] = fmaf(a[i], bv[j], c[i][j]);
        }
        #pragma unroll
        for (int j = 0; j < 8; j++) {
            float bb = sh_b1[tx*8 + j];
            #pragma unroll
            for (int i = 0; i < 8; i++)
                sh_h2[(tx*8 + j) * 129 + (ty*8 + i)] = fmaxf(c[i][j] + bb, 0.f);
        }
    }
    __syncthreads();

    {
        for (int t = tid; t < 128*32; t += 256) sh_w[t] = w2[t];
    }
    __syncthreads();

    {
        const int p  = tid & 127;
        const int ob = (tid >> 7) * 16;
        float f[16];
        #pragma unroll
        for (int j = 0; j < 16; j++) f[j] = b2[ob + j];
        for (int k = 0; k < 128; k++) {
            float a = sh_h2[k * 129 + p];
            #pragma unroll
            for (int g = 0; g < 4; g++) {
                float4 wv = *(const float4*)&sh_w[k*32 + ob + g*4];
                f[g*4+0] = fmaf(a, wv.x, f[g*4+0]);
                f[g*4+1] = fmaf(a, wv.y, f[g*4+1]);
                f[g*4+2] = fmaf(a, wv.z, f[g*4+2]);
                f[g*4+3] = fmaf(a, wv.w, f[g*4+3]);
            }
        }
        int pix = pbase + p;
        int b = pix >> 18;
        int y = (pix >> 9) & 511;
        int x = pix & 511;
        bool mask = sh_z[p] > 0.f;
        float vv[16];
        #pragma unroll
        for (int j = 0; j < 16; j++) vv[j] = mask ? f[j] : 1.0f;
        #pragma unroll
        for (int jj = 0; jj < 8; jj++) {
            int c0 = ob + 2 * jj;
            float v0 = (c0     < CIN) ? vv[2*jj]     : 0.f;
            float v1 = (c0 + 1 < CIN) ? vv[2*jj + 1] : 0.f;
            *(__half2*)(g_xh + (size_t)pix * 32 + c0) = __floats2half2_rn(v0, v1);
        }
        if (ob == 16) {
            #pragma unroll
            for (int j = 13; j < 16; j++) {
                int cch = 16 + j;          // 29..31
                g_rgb[((b*3 + (cch - CIN)) * NH + y) * NW + x] = vv[j];
            }
        }
    }
}

// ---------------------------------------------------------------------------
// conv13: 3x3 SAME stride-1 fp16 mma conv, 64 cout, relu, half NHWC in/out.
// mode 0 = conv1 (g_xh, 1 chunk of 32) ; mode 1 = conv3 (g_dh up ++ g_e1h,
// 6 chunks of 32). CTA 256 thr, tile 16x16. smem in_s[324][40], w_s[9*64][40].
static constexpr int C13_SMEM_BYTES = (324 * 40 + 9 * 64 * 40) * 2;  // 72000

__global__ __launch_bounds__(256)
void conv13_kernel(int nchunks, int mode)
{
    extern __shared__ __half c13sm[];
    __half* in_s = c13sm;               // [pos(324)][40]
    __half* w_s  = c13sm + 324 * 40;    // [tap*64+co][40]

    const int tid  = threadIdx.x;
    const int w    = tid >> 5;
    const int lane = tid & 31;
    const int gid  = lane >> 2;
    const int tig  = lane & 3;

    const int x0 = blockIdx.x * 16, y0 = blockIdx.y * 16, b = blockIdx.z;

    float c[2][8][4];
    #pragma unroll
    for (int mt = 0; mt < 2; mt++)
        #pragma unroll
        for (int nt = 0; nt < 8; nt++)
            #pragma unroll
            for (int q = 0; q < 4; q++) c[mt][nt][q] = 0.f;

    const __half* wsrc = (mode == 0) ? w1h : w3h;

    for (int ch = 0; ch < nchunks; ch++) {
        __syncthreads();
        for (int t = tid; t < 324 * 8; t += 256) {
            int tpx = t >> 3, ci4 = t & 7;
            int yy = tpx / 18, xx = tpx - yy * 18;
            int iy = y0 - 1 + yy, ix = x0 - 1 + xx;
            uint2 v = make_uint2(0u, 0u);
            if (iy >= 0 && iy < NH && ix >= 0 && ix < NW) {
                if (mode == 0) {
                    size_t pix = ((size_t)(b * NH + iy) * NW + ix);
                    v = *(const uint2*)(g_xh + pix * 32 + ci4 * 4);
                } else {
                    int ci = ch * 32 + ci4 * 4;
                    if (ci < C2C) {
                        size_t pixd = ((size_t)(b * (NH/2) + (iy >> 1)) * (NW/2) + (ix >> 1));
                        v = *(const uint2*)(g_dh + pixd * 128 + ci);
                    } else {
                        size_t pix = ((size_t)(b * NH + iy) * NW + ix);
                        v = *(const uint2*)(g_e1h + pix * 64 + (ci - C2C));
                    }
                }
            }
            *(uint2*)(in_s + tpx * 40 + ci4 * 4) = v;
        }
        {
            const uint4* src = (const uint4*)(wsrc + ch * 23040);
            uint4* dst = (uint4*)w_s;
            for (int t = tid; t < 2880; t += 256) dst[t] = src[t];
        }
        __syncthreads();

        #pragma unroll
        for (int tap = 0; tap < 9; tap++) {
            const int ky = tap / 3, kx = tap - 3 * (tap / 3);
            #pragma unroll
            for (int g = 0; g < 2; g++) {
                uint32_t a[2][4];
                #pragma unroll
                for (int mt = 0; mt < 2; mt++) {
                    const int yl = 2 * w + mt;
                    const __half* base = in_s + ((yl + ky) * 18 + kx) * 40 + 16 * g + 2 * tig;
                    a[mt][0] = *(const uint32_t*)(base + gid * 40);
                    a[mt][1] = *(const uint32_t*)(base + (gid + 8) * 40);
                    a[mt][2] = *(const uint32_t*)(base + gid * 40 + 8);
                    a[mt][3] = *(const uint32_t*)(base + (gid + 8) * 40 + 8);
                }
                const __half* wb = w_s + (tap * 64 + gid) * 40 + 16 * g + 2 * tig;
                #pragma unroll
                for (int nt = 0; nt < 8; nt++) {
                    const __half* pb = wb + nt * 8 * 40;
                    uint32_t b0 = *(const uint32_t*)(pb);
                    uint32_t b1 = *(const uint32_t*)(pb + 8);
                    mma_f16(c[0][nt], a[0][0], a[0][1], a[0][2], a[0][3], b0, b1);
                    mma_f16(c[1][nt], a[1][0], a[1][1], a[1][2], a[1][3], b0, b1);
                }
            }
        }
    }

    __half* dst = (mode == 0) ? g_e1h : g_mh;
    #pragma unroll
    for (int mt = 0; mt < 2; mt++) {
        const int y = y0 + 2 * w + mt;
        #pragma unroll
        for (int nt = 0; nt < 8; nt++) {
            const int co = 8 * nt + 2 * tig;
            size_t p1 = ((size_t)(b * NH + y) * NW + x0 + gid) * 64 + co;
            size_t p2 = ((size_t)(b * NH + y) * NW + x0 + gid + 8) * 64 + co;
            *(__half2*)(dst + p1) = __floats2half2_rn(fmaxf(c[mt][nt][0], 0.f),
                                                      fmaxf(c[mt][nt][1], 0.f));
            *(__half2*)(dst + p2) = __floats2half2_rn(fmaxf(c[mt][nt][2], 0.f),
                                                      fmaxf(c[mt][nt][3], 0.f));
        }
    }
}

// ---------------------------------------------------------------------------
// conv2: 64->128 3x3 stride-2 SAME (pad_lo=0) fp16 mma, half NHWC in/out.
// CTA 512 thr, out tile 16x16 at 256x256. Parity-plane window layout.
static constexpr int C2_SMEM_BYTES = (1089 * 24 + 9 * 128 * 24) * 2;  // 107568

__global__ __launch_bounds__(512)
void conv2_kernel()
{
    extern __shared__ __half c2sm[];
    __half* in_s = c2sm;                 // [pos(1089)][24]
    __half* w_s  = c2sm + 1089 * 24;     // [tap*128+co][24]

    const int tid  = threadIdx.x;
    const int w    = tid >> 5;
    const int lane = tid & 31;
    const int gid  = lane >> 2;
    const int tig  = lane & 3;
    const int coh  = w >> 3;
    const int wy   = w & 7;

    const int x0 = blockIdx.x * 16, y0 = blockIdx.y * 16, b = blockIdx.z;

    float c[2][8][4];
    #pragma unroll
    for (int mt = 0; mt < 2; mt++)
        #pragma unroll
        for (int nt = 0; nt < 8; nt++)
            #pragma unroll
            for (int q = 0; q < 4; q++) c[mt][nt][q] = 0.f;

    for (int ch = 0; ch < 4; ch++) {
        __syncthreads();
        for (int t = tid; t < 1089 * 4; t += 512) {
            int tpx = t >> 2, ci4 = t & 3;
            int yy = tpx / 33, xx = tpx - yy * 33;
            int iy = 2 * y0 + yy, ix = 2 * x0 + xx;    // pad_lo = 0
            int pos = yy * 33 + ((xx & 1) ? 17 + (xx >> 1) : (xx >> 1));
            uint2 v = make_uint2(0u, 0u);
            if (iy < NH && ix < NW) {
                size_t pix = ((size_t)(b * NH + iy) * NW + ix);
                v = *(const uint2*)(g_e1h + pix * 64 + ch * 16 + ci4 * 4);
            }
            *(uint2*)(in_s + pos * 24 + ci4 * 4) = v;
        }
        {
            const uint4* src = (const uint4*)(w2h + ch * 27648);
            uint4* dst = (uint4*)w_s;
            for (int t = tid; t < 3456; t += 512) dst[t] = src[t];
        }
        __syncthreads();

        #pragma unroll
        for (int tap = 0; tap < 9; tap++) {
            const int ky = tap / 3, kx = tap - 3 * (tap / 3);
            const int colbase = (kx == 1) ? 17 : (kx >> 1);
            uint32_t a[2][4];
            #pragma unroll
            for (int mt = 0; mt < 2; mt++) {
                const int yl = 2 * wy + mt;
                const __half* base = in_s + ((2 * yl + ky) * 33 + colbase) * 24 + 2 * tig;
                a[mt][0] = *(const uint32_t*)(base + gid * 24);
                a[mt][1] = *(const uint32_t*)(base + (gid + 8) * 24);
                a[mt][2] = *(const uint32_t*)(base + gid * 24 + 8);
                a[mt][3] = *(const uint32_t*)(base + (gid + 8) * 24 + 8);
            }
            const __half* wb = w_s + (tap * 128 + coh * 64 + gid) * 24 + 2 * tig;
            #pragma unroll
            for (int nt = 0; nt < 8; nt++) {
                const __half* pb = wb + nt * 8 * 24;
                uint32_t b0 = *(const uint32_t*)(pb);
                uint32_t b1 = *(const uint32_t*)(pb + 8);
                mma_f16(c[0][nt], a[0][0], a[0][1], a[0][2], a[0][3], b0, b1);
                mma_f16(c[1][nt], a[1][0], a[1][1], a[1][2], a[1][3], b0, b1);
            }
        }
    }

    #pragma unroll
    for (int mt = 0; mt < 2; mt++) {
        const int y = y0 + 2 * wy + mt;
        #pragma unroll
        for (int nt = 0; nt < 8; nt++) {
            const int co = coh * 64 + 8 * nt + 2 * tig;
            size_t p1 = ((size_t)(b * (NH/2) + y) * (NW/2) + x0 + gid) * 128 + co;
            size_t p2 = ((size_t)(b * (NH/2) + y) * (NW/2) + x0 + gid + 8) * 128 + co;
            *(__half2*)(g_dh + p1) = __floats2half2_rn(fmaxf(c[mt][nt][0], 0.f),
                                                       fmaxf(c[mt][nt][1], 0.f));
            *(__half2*)(g_dh + p2) = __floats2half2_rn(fmaxf(c[mt][nt][2], 0.f),
                                                       fmaxf(c[mt][nt][3], 0.f));
        }
    }
}

// ---------------------------------------------------------------------------
// conv4: 64->3 3x3 SAME fp16 mma (N=8, 3 live), + rgb residual, fp32 NCHW out.
static constexpr int C4_SMEM_BYTES = (324 * 24 + 9 * 8 * 24) * 2;  // 19008

__global__ __launch_bounds__(256)
void conv4_kernel(float* __restrict__ out)
{
    extern __shared__ __half c4sm[];
    __half* in_s = c4sm;               // [pos(324)][24]
    __half* w_s  = c4sm + 324 * 24;    // [tap*8+co][24]

    const int tid  = threadIdx.x;
    const int w    = tid >> 5;
    const int lane = tid & 31;
    const int gid  = lane >> 2;
    const int tig  = lane & 3;

    const int x0 = blockIdx.x * 16, y0 = blockIdx.y * 16, b = blockIdx.z;

    float c[2][4];
    #pragma unroll
    for (int mt = 0; mt < 2; mt++)
        #pragma unroll
        for (int q = 0; q < 4; q++) c[mt][q] = 0.f;

    for (int ch = 0; ch < 4; ch++) {
        __syncthreads();
        for (int t = tid; t < 324 * 4; t += 256) {
            int tpx = t >> 2, ci4 = t & 3;
            int yy = tpx / 18, xx = tpx - yy * 18;
            int iy = y0 - 1 + yy, ix = x0 - 1 + xx;
            uint2 v = make_uint2(0u, 0u);
            if (iy >= 0 && iy < NH && ix >= 0 && ix < NW) {
                size_t pix = ((size_t)(b * NH + iy) * NW + ix);
                v = *(const uint2*)(g_mh + pix * 64 + ch * 16 + ci4 * 4);
            }
            *(uint2*)(in_s + tpx * 24 + ci4 * 4) = v;
        }
        {
            const uint4* src = (const uint4*)(w4h + ch * 1728);
            uint4* dst = (uint4*)w_s;
            for (int t = tid; t < 216; t += 256) dst[t] = src[t];
        }
        __syncthreads();

        #pragma unroll
        for (int tap = 0; tap < 9; tap++) {
            const int ky = tap / 3, kx = tap - 3 * (tap / 3);
            const __half* wb = w_s + (tap * 8 + gid) * 24 + 2 * tig;
            uint32_t b0 = *(const uint32_t*)(wb);
            uint32_t b1 = *(const uint32_t*)(wb + 8);
            #pragma unroll
            for (int mt = 0; mt < 2; mt++) {
                const int yl = 2 * w + mt;
                const __half* base = in_s + ((yl + ky) * 18 + kx) * 24 + 2 * tig;
                uint32_t a0 = *(const uint32_t*)(base + gid * 24);
                uint32_t a1 = *(const uint32_t*)(base + (gid + 8) * 24);
                uint32_t a2 = *(const uint32_t*)(base + gid * 24 + 8);
                uint32_t a3 = *(const uint32_t*)(base + (gid + 8) * 24 + 8);
                mma_f16(c[mt], a0, a1, a2, a3, b0, b1);
            }
        }
    }

    if (tig < 2) {
        #pragma unroll
        for (int mt = 0; mt < 2; mt++) {
            const int y = y0 + 2 * w + mt;
            const int co0 = 2 * tig;
            const int x1 = x0 + gid, x2 = x0 + gid + 8;
            {
                int base = ((b*3 + co0) * NH + y) * NW;
                out[base + x1] = c[mt][0] + g_rgb[base + x1];
                out[base + x2] = c[mt][2] + g_rgb[base + x2];
            }
            if (co0 + 1 < 3) {
                int base = ((b*3 + co0 + 1) * NH + y) * NW;
                out[base + x1] = c[mt][1] + g_rgb[base + x1];
                out[base + x2] = c[mt][3] + g_rgb[base + x2];
            }
        }
    }
}

// ---------------------------------------------------------------------------
extern "C" void kernel_launch(void* const* d_in, const int* in_sizes, int n_in,
                              void* d_out, int out_size)
{
    const float* zbuf = (const float*)d_in[0];
    const float* ray  = (const float*)d_in[1];
    const float* w0 = (const float*)d_in[4];
    const float* b0 = (const float*)d_in[5];
    const float* w1 = (const float*)d_in[6];
    const float* b1 = (const float*)d_in[7];
    const float* w2 = (const float*)d_in[8];
    const float* b2 = (const float*)d_in[9];
    const float* k1 = (const float*)d_in[10];
    const float* k2 = (const float*)d_in[11];
    const float* k3 = (const float*)d_in[12];
    const float* k4 = (const float*)d_in[13];
    float* out = (float*)d_out;

    cudaFuncSetAttribute(mlp_kernel,
                         cudaFuncAttributeMaxDynamicSharedMemorySize, MLP_SMEM_BYTES);
    cudaFuncSetAttribute(conv13_kernel,
                         cudaFuncAttributeMaxDynamicSharedMemorySize, C13_SMEM_BYTES);
    cudaFuncSetAttribute(conv2_kernel,
                         cudaFuncAttributeMaxDynamicSharedMemorySize, C2_SMEM_BYTES);
    cudaFuncSetAttribute(conv4_kernel,
                         cudaFuncAttributeMaxDynamicSharedMemorySize, C4_SMEM_BYTES);

    const int prep_total = W1H_SZ + W2H_SZ + W3H_SZ + W4H_SZ;
    prep_weights<<<(prep_total + 255) / 256, 256>>>(k1, k2, k3, k4);

    mlp_kernel<<<(NB*NH*NW)/128, 256, MLP_SMEM_BYTES>>>(zbuf, ray,
                                                        w0, b0, w1, b1, w2, b2);
    conv13_kernel<<<dim3(NW/16, NH/16, NB), 256, C13_SMEM_BYTES>>>(1, 0);
    conv2_kernel <<<dim3(16, 16, NB), 512, C2_SMEM_BYTES>>>();
    conv13_kernel<<<dim3(NW/16, NH/16, NB), 256, C13_SMEM_BYTES>>>(6, 1);
    conv4_kernel <<<dim3(NW/16, NH/16, NB), 256, C4_SMEM_BYTES>>>(out);
}

// round 10
// speedup vs baseline: 4.2637x; 1.2518x over previous
#include <cuda_runtime.h>
#include <cuda_fp16.h>
#include <cstdint>

// Renderer_45612552684068 — round 9: MLP layers 1/2 moved to fp16 mma
// (layer0 stays fp32 scalar). Convs unchanged from passing R8 kernel.

static constexpr int NB   = 4;
static constexpr int NH   = 512;
static constexpr int NW   = 512;
static constexpr int HID  = 128;
static constexpr int CIN  = 29;
static constexpr int C1C  = 64;
static constexpr int C2C  = 128;

// activations (half NHWC) + rgb residual (float NCHW)
__device__ __align__(16) float  g_rgb[NB * 3 * NH * NW];
__device__ __align__(16) __half g_xh [NB * NH * NW * 32];
__device__ __align__(16) __half g_e1h[NB * NH * NW * 64];
__device__ __align__(16) __half g_dh [NB * (NH/2) * (NW/2) * 128];
__device__ __align__(16) __half g_mh [NB * NH * NW * 64];

// prepacked half weights (convs)
static constexpr int W1H_SZ = 9 * 64 * 40;
static constexpr int W2H_SZ = 4 * 9 * 128 * 24;
static constexpr int W3H_SZ = 6 * 9 * 64 * 40;
static constexpr int W4H_SZ = 4 * 9 * 8 * 24;
__device__ __align__(16) __half w1h[W1H_SZ];
__device__ __align__(16) __half w2h[W2H_SZ];
__device__ __align__(16) __half w3h[W3H_SZ];
__device__ __align__(16) __half w4h[W4H_SZ];
// prepacked half MLP weights: [n][kpad=136]
static constexpr int W1M_SZ = 128 * 136;
static constexpr int W2M_SZ = 32 * 136;
__device__ __align__(16) __half w1mh[W1M_SZ];
__device__ __align__(16) __half w2mh[W2M_SZ];

__device__ __forceinline__ void mma_f16(float c[4],
                                        uint32_t a0, uint32_t a1,
                                        uint32_t a2, uint32_t a3,
                                        uint32_t b0, uint32_t b1) {
    asm volatile(
        "mma.sync.aligned.m16n8k16.row.col.f32.f16.f16.f32 "
        "{%0,%1,%2,%3}, {%4,%5,%6,%7}, {%8,%9}, {%0,%1,%2,%3};"
        : "+f"(c[0]), "+f"(c[1]), "+f"(c[2]), "+f"(c[3])
        : "r"(a0), "r"(a1), "r"(a2), "r"(a3), "r"(b0), "r"(b1));
}

// ---------------------------------------------------------------------------
// prep_weights: fp32 -> chunked half layouts (zero-padded, transposed for mma).
__global__ void prep_weights(const float* __restrict__ k1, const float* __restrict__ k2,
                             const float* __restrict__ k3, const float* __restrict__ k4,
                             const float* __restrict__ mw1, const float* __restrict__ mw2)
{
    int i = blockIdx.x * 256 + threadIdx.x;
    if (i < W1H_SZ) {
        int tap = i / 2560, r = i % 2560, co = r / 40, k = r % 40;
        w1h[i] = __float2half(k < CIN ? k1[(co * CIN + k) * 9 + tap] : 0.f);
        return;
    }
    i -= W1H_SZ;
    if (i < W2H_SZ) {
        int c = i / 27648, r = i % 27648;
        int tap = r / 3072, co = (r % 3072) / 24, k = r % 24;
        w2h[i] = __float2half(k < 16 ? k2[(co * C1C + c * 16 + k) * 9 + tap] : 0.f);
        return;
    }
    i -= W2H_SZ;
    if (i < W3H_SZ) {
        int c = i / 23040, r = i % 23040;
        int tap = r / 2560, co = (r % 2560) / 40, k = r % 40;
        w3h[i] = __float2half(k < 32 ? k3[(co * (C2C + C1C) + c * 32 + k) * 9 + tap] : 0.f);
        return;
    }
    i -= W3H_SZ;
    if (i < W4H_SZ) {
        int c = i / 1728, r = i % 1728;
        int tap = r / 192, co = (r % 192) / 24, k = r % 24;
        w4h[i] = __float2half((k < 16 && co < 3) ? k4[(co * C1C + c * 16 + k) * 9 + tap] : 0.f);
        return;
    }
    i -= W4H_SZ;
    if (i < W1M_SZ) {
        int n = i / 136, k = i % 136;
        w1mh[i] = __float2half(k < HID ? mw1[k * HID + n] : 0.f);
        return;
    }
    i -= W1M_SZ;
    if (i < W2M_SZ) {
        int n = i / 136, k = i % 136;
        w2mh[i] = __float2half(k < HID ? mw2[k * 32 + n] : 0.f);
    }
}

// ---------------------------------------------------------------------------
// MLP: 128 px / block, 256 thr (8 warps). Layer0 fp32 scalar; layers 1/2 fp16
// mma m16n8k16 with fp32 accum. smem strides 136 halves (conflict-free frags).
static constexpr int MLP_H1_OFF  = 0;                       // half[128][136]
static constexpr int MLP_W1_OFF  = 34816;                   // half[128][136]
static constexpr int MLP_W2_OFF  = 69632;                   // half[32][136]
static constexpr int MLP_W0_OFF  = 78336;                   // float[6][128]
static constexpr int MLP_FIN_OFF = 81408;                   // float[128][8]
static constexpr int MLP_Z_OFF   = 85504;                   // float[128]
static constexpr int MLP_B0_OFF  = 86016;                   // float[128]
static constexpr int MLP_B1_OFF  = 86528;                   // float[128]
static constexpr int MLP_B2_OFF  = 87040;                   // float[32]
static constexpr int MLP_SMEM_BYTES = 87168;

__global__ __launch_bounds__(256)
void mlp_kernel(const float* __restrict__ zbuf, const float* __restrict__ ray,
                const float* __restrict__ w0, const float* __restrict__ b0,
                const float* __restrict__ b1, const float* __restrict__ b2)
{
    extern __shared__ __align__(16) char msm[];
    __half* sh_h1 = (__half*)(msm + MLP_H1_OFF);
    __half* sh_w1 = (__half*)(msm + MLP_W1_OFF);
    __half* sh_w2 = (__half*)(msm + MLP_W2_OFF);
    float*  sh_w0 = (float*)(msm + MLP_W0_OFF);
    float*  sh_fin= (float*)(msm + MLP_FIN_OFF);
    float*  sh_z  = (float*)(msm + MLP_Z_OFF);
    float*  sh_b0 = (float*)(msm + MLP_B0_OFF);
    float*  sh_b1 = (float*)(msm + MLP_B1_OFF);
    float*  sh_b2 = (float*)(msm + MLP_B2_OFF);

    const int tid   = threadIdx.x;
    const int w     = tid >> 5;
    const int lane  = tid & 31;
    const int gid   = lane >> 2;
    const int tig   = lane & 3;
    const int pbase = blockIdx.x * 128;

    // stage prepacked weights (flat uint4) + fp32 vectors
    {
        const uint4* s1 = (const uint4*)w1mh;
        uint4* d1 = (uint4*)sh_w1;
        for (int t = tid; t < W1M_SZ / 8; t += 256) d1[t] = s1[t];
        const uint4* s2 = (const uint4*)w2mh;
        uint4* d2 = (uint4*)sh_w2;
        for (int t = tid; t < W2M_SZ / 8; t += 256) d2[t] = s2[t];
        for (int t = tid; t < 768; t += 256) sh_w0[t] = w0[t];
        if (tid < 128) { sh_b0[tid] = b0[tid]; sh_b1[tid] = b1[tid]; }
        if (tid < 32)  sh_b2[tid] = b2[tid];
    }

    // fin
    if (tid < 128) {
        int pix = pbase + tid;
        int b = pix >> 18;
        int y = (pix >> 9) & 511;
        int x = pix & 511;
        int pi = (b * NH + y) * NW + x;
        float z = zbuf[pi];
        const float* r = ray + pi * 7;
        float t  = z / r[6];
        float d0 = r[3], d1 = r[4], d2 = r[5];
        sh_fin[tid * 8 + 0] = fmaf(d0, t, r[0]);
        sh_fin[tid * 8 + 1] = fmaf(d1, t, r[1]);
        sh_fin[tid * 8 + 2] = fmaf(d2, t, r[2]);
        sh_fin[tid * 8 + 3] = d0;
        sh_fin[tid * 8 + 4] = d1;
        sh_fin[tid * 8 + 5] = d2;
        sh_z[tid] = z;
    }
    __syncthreads();

    // layer0: h1 = relu(fin@w0 + b0) -> half sh_h1[p][136]
    {
        const int p  = tid & 127;
        const int ob = (tid >> 7) * 64;
        float f0 = sh_fin[p*8+0], f1 = sh_fin[p*8+1], f2 = sh_fin[p*8+2];
        float f3 = sh_fin[p*8+3], f4 = sh_fin[p*8+4], f5 = sh_fin[p*8+5];
        #pragma unroll 8
        for (int o = ob; o < ob + 64; o += 2) {
            float a0 = sh_b0[o],     a1 = sh_b0[o+1];
            a0 = fmaf(f0, sh_w0[0*HID + o], a0);  a1 = fmaf(f0, sh_w0[0*HID + o+1], a1);
            a0 = fmaf(f1, sh_w0[1*HID + o], a0);  a1 = fmaf(f1, sh_w0[1*HID + o+1], a1);
            a0 = fmaf(f2, sh_w0[2*HID + o], a0);  a1 = fmaf(f2, sh_w0[2*HID + o+1], a1);
            a0 = fmaf(f3, sh_w0[3*HID + o], a0);  a1 = fmaf(f3, sh_w0[3*HID + o+1], a1);
            a0 = fmaf(f4, sh_w0[4*HID + o], a0);  a1 = fmaf(f4, sh_w0[4*HID + o+1], a1);
            a0 = fmaf(f5, sh_w0[5*HID + o], a0);  a1 = fmaf(f5, sh_w0[5*HID + o+1], a1);
            *(__half2*)(sh_h1 + p * 136 + o) =
                __floats2half2_rn(fmaxf(a0, 0.f), fmaxf(a1, 0.f));
        }
    }
    __syncthreads();

    // layer1: h2 = relu(h1 @ w1 + b1). warp (mw,nw): 32px x 64n.
    const int mw = w & 3, nw = w >> 2;
    const int mbase = 32 * mw, nbase = 64 * nw;
    float c1[2][8][4];
    #pragma unroll
    for (int mt = 0; mt < 2; mt++)
        #pragma unroll
        for (int nt = 0; nt < 8; nt++)
            #pragma unroll
            for (int q = 0; q < 4; q++) c1[mt][nt][q] = 0.f;

    #pragma unroll
    for (int ks = 0; ks < 8; ks++) {
        const int kofs = 16 * ks;
        uint32_t a[2][4];
        #pragma unroll
        for (int mt = 0; mt < 2; mt++) {
            const __half* pa = sh_h1 + (mbase + 16*mt + gid) * 136 + kofs + 2*tig;
            a[mt][0] = *(const uint32_t*)(pa);
            a[mt][1] = *(const uint32_t*)(pa + 8 * 136);
            a[mt][2] = *(const uint32_t*)(pa + 8);
            a[mt][3] = *(const uint32_t*)(pa + 8 * 136 + 8);
        }
        #pragma unroll
        for (int nt = 0; nt < 8; nt++) {
            const __half* pb = sh_w1 + (nbase + 8*nt + gid) * 136 + kofs + 2*tig;
            uint32_t b0v = *(const uint32_t*)(pb);
            uint32_t b1v = *(const uint32_t*)(pb + 8);
            mma_f16(c1[0][nt], a[0][0], a[0][1], a[0][2], a[0][3], b0v, b1v);
            mma_f16(c1[1][nt], a[1][0], a[1][1], a[1][2], a[1][3], b0v, b1v);
        }
    }
    __syncthreads();   // all reads of h1 done before overwrite

    // store h2 over sh_h1 (relu + bias), half2
    #pragma unroll
    for (int nt = 0; nt < 8; nt++) {
        const int n0 = nbase + 8*nt + 2*tig;
        float bb0 = sh_b1[n0], bb1 = sh_b1[n0 + 1];
        #pragma unroll
        for (int mt = 0; mt < 2; mt++) {
            int p0 = mbase + 16*mt + gid;
            *(__half2*)(sh_h1 + p0 * 136 + n0) =
                __floats2half2_rn(fmaxf(c1[mt][nt][0] + bb0, 0.f),
                                  fmaxf(c1[mt][nt][1] + bb1, 0.f));
            *(__half2*)(sh_h1 + (p0 + 8) * 136 + n0) =
                __floats2half2_rn(fmaxf(c1[mt][nt][2] + bb0, 0.f),
                                  fmaxf(c1[mt][nt][3] + bb1, 0.f));
        }
    }
    __syncthreads();

    // layer2: feat = h2 @ w2 + b2. warp w: 16 px rows, N=32.
    float d2[4][4];
    #pragma unroll
    for (int nt = 0; nt < 4; nt++)
        #pragma unroll
        for (int q = 0; q < 4; q++) d2[nt][q] = 0.f;

    #pragma unroll
    for (int ks = 0; ks < 8; ks++) {
        const int kofs = 16 * ks;
        const __half* pa = sh_h1 + (16*w + gid) * 136 + kofs + 2*tig;
        uint32_t a0 = *(const uint32_t*)(pa);
        uint32_t a1 = *(const uint32_t*)(pa + 8 * 136);
        uint32_t a2 = *(const uint32_t*)(pa + 8);
        uint32_t a3 = *(const uint32_t*)(pa + 8 * 136 + 8);
        #pragma unroll
        for (int nt = 0; nt < 4; nt++) {
            const __half* pb = sh_w2 + (8*nt + gid) * 136 + kofs + 2*tig;
            uint32_t b0v = *(const uint32_t*)(pb);
            uint32_t b1v = *(const uint32_t*)(pb + 8);
            mma_f16(d2[nt], a0, a1, a2, a3, b0v, b1v);
        }
    }

    // epilogue: bias + mask + half NHWC store (+ rgb residual float NCHW)
    #pragma unroll
    for (int nt = 0; nt < 4; nt++) {
        const int n0 = 8*nt + 2*tig;
        const float bb0 = sh_b2[n0], bb1 = sh_b2[n0 + 1];
        #pragma unroll
        for (int rr = 0; rr < 2; rr++) {
            const int p = 16*w + gid + 8*rr;
            const int pix = pbase + p;
            const bool mask = sh_z[p] > 0.f;
            float v0 = mask ? (d2[nt][2*rr]     + bb0) : 1.0f;
            float v1 = mask ? (d2[nt][2*rr + 1] + bb1) : 1.0f;
            float x0 = (n0     < CIN) ? v0 : 0.f;
            float x1 = (n0 + 1 < CIN) ? v1 : 0.f;
            *(__half2*)(g_xh + (size_t)pix * 32 + n0) = __floats2half2_rn(x0, x1);
            if (n0 + 1 >= CIN) {
                int b = pix >> 18;
                int y = (pix >> 9) & 511;
                int x = pix & 511;
                if (n0 >= CIN)
                    g_rgb[((b*3 + (n0 - CIN)) * NH + y) * NW + x] = v0;
                g_rgb[((b*3 + (n0 + 1 - CIN)) * NH + y) * NW + x] = v1;
            }
        }
    }
}

// ---------------------------------------------------------------------------
// conv13: 3x3 SAME stride-1 fp16 mma conv, 64 cout, relu, half NHWC in/out.
static constexpr int C13_SMEM_BYTES = (324 * 40 + 9 * 64 * 40) * 2;  // 72000

__global__ __launch_bounds__(256)
void conv13_kernel(int nchunks, int mode)
{
    extern __shared__ __half c13sm[];
    __half* in_s = c13sm;               // [pos(324)][40]
    __half* w_s  = c13sm + 324 * 40;    // [tap*64+co][40]

    const int tid  = threadIdx.x;
    const int w    = tid >> 5;
    const int lane = tid & 31;
    const int gid  = lane >> 2;
    const int tig  = lane & 3;

    const int x0 = blockIdx.x * 16, y0 = blockIdx.y * 16, b = blockIdx.z;

    float c[2][8][4];
    #pragma unroll
    for (int mt = 0; mt < 2; mt++)
        #pragma unroll
        for (int nt = 0; nt < 8; nt++)
            #pragma unroll
            for (int q = 0; q < 4; q++) c[mt][nt][q] = 0.f;

    const __half* wsrc = (mode == 0) ? w1h : w3h;

    for (int ch = 0; ch < nchunks; ch++) {
        __syncthreads();
        for (int t = tid; t < 324 * 8; t += 256) {
            int tpx = t >> 3, ci4 = t & 7;
            int yy = tpx / 18, xx = tpx - yy * 18;
            int iy = y0 - 1 + yy, ix = x0 - 1 + xx;
            uint2 v = make_uint2(0u, 0u);
            if (iy >= 0 && iy < NH && ix >= 0 && ix < NW) {
                if (mode == 0) {
                    size_t pix = ((size_t)(b * NH + iy) * NW + ix);
                    v = *(const uint2*)(g_xh + pix * 32 + ci4 * 4);
                } else {
                    int ci = ch * 32 + ci4 * 4;
                    if (ci < C2C) {
                        size_t pixd = ((size_t)(b * (NH/2) + (iy >> 1)) * (NW/2) + (ix >> 1));
                        v = *(const uint2*)(g_dh + pixd * 128 + ci);
                    } else {
                        size_t pix = ((size_t)(b * NH + iy) * NW + ix);
                        v = *(const uint2*)(g_e1h + pix * 64 + (ci - C2C));
                    }
                }
            }
            *(uint2*)(in_s + tpx * 40 + ci4 * 4) = v;
        }
        {
            const uint4* src = (const uint4*)(wsrc + ch * 23040);
            uint4* dst = (uint4*)w_s;
            for (int t = tid; t < 2880; t += 256) dst[t] = src[t];
        }
        __syncthreads();

        #pragma unroll
        for (int tap = 0; tap < 9; tap++) {
            const int ky = tap / 3, kx = tap - 3 * (tap / 3);
            #pragma unroll
            for (int g = 0; g < 2; g++) {
                uint32_t a[2][4];
                #pragma unroll
                for (int mt = 0; mt < 2; mt++) {
                    const int yl = 2 * w + mt;
                    const __half* base = in_s + ((yl + ky) * 18 + kx) * 40 + 16 * g + 2 * tig;
                    a[mt][0] = *(const uint32_t*)(base + gid * 40);
                    a[mt][1] = *(const uint32_t*)(base + (gid + 8) * 40);
                    a[mt][2] = *(const uint32_t*)(base + gid * 40 + 8);
                    a[mt][3] = *(const uint32_t*)(base + (gid + 8) * 40 + 8);
                }
                const __half* wb = w_s + (tap * 64 + gid) * 40 + 16 * g + 2 * tig;
                #pragma unroll
                for (int nt = 0; nt < 8; nt++) {
                    const __half* pb = wb + nt * 8 * 40;
                    uint32_t b0 = *(const uint32_t*)(pb);
                    uint32_t b1 = *(const uint32_t*)(pb + 8);
                    mma_f16(c[0][nt], a[0][0], a[0][1], a[0][2], a[0][3], b0, b1);
                    mma_f16(c[1][nt], a[1][0], a[1][1], a[1][2], a[1][3], b0, b1);
                }
            }
        }
    }

    __half* dst = (mode == 0) ? g_e1h : g_mh;
    #pragma unroll
    for (int mt = 0; mt < 2; mt++) {
        const int y = y0 + 2 * w + mt;
        #pragma unroll
        for (int nt = 0; nt < 8; nt++) {
            const int co = 8 * nt + 2 * tig;
            size_t p1 = ((size_t)(b * NH + y) * NW + x0 + gid) * 64 + co;
            size_t p2 = ((size_t)(b * NH + y) * NW + x0 + gid + 8) * 64 + co;
            *(__half2*)(dst + p1) = __floats2half2_rn(fmaxf(c[mt][nt][0], 0.f),
                                                      fmaxf(c[mt][nt][1], 0.f));
            *(__half2*)(dst + p2) = __floats2half2_rn(fmaxf(c[mt][nt][2], 0.f),
                                                      fmaxf(c[mt][nt][3], 0.f));
        }
    }
}

// ---------------------------------------------------------------------------
// conv2: 64->128 3x3 stride-2 SAME (pad_lo=0) fp16 mma, half NHWC in/out.
static constexpr int C2_SMEM_BYTES = (1089 * 24 + 9 * 128 * 24) * 2;  // 107568

__global__ __launch_bounds__(512)
void conv2_kernel()
{
    extern __shared__ __half c2sm[];
    __half* in_s = c2sm;                 // [pos(1089)][24]
    __half* w_s  = c2sm + 1089 * 24;     // [tap*128+co][24]

    const int tid  = threadIdx.x;
    const int w    = tid >> 5;
    const int lane = tid & 31;
    const int gid  = lane >> 2;
    const int tig  = lane & 3;
    const int coh  = w >> 3;
    const int wy   = w & 7;

    const int x0 = blockIdx.x * 16, y0 = blockIdx.y * 16, b = blockIdx.z;

    float c[2][8][4];
    #pragma unroll
    for (int mt = 0; mt < 2; mt++)
        #pragma unroll
        for (int nt = 0; nt < 8; nt++)
            #pragma unroll
            for (int q = 0; q < 4; q++) c[mt][nt][q] = 0.f;

    for (int ch = 0; ch < 4; ch++) {
        __syncthreads();
        for (int t = tid; t < 1089 * 4; t += 512) {
            int tpx = t >> 2, ci4 = t & 3;
            int yy = tpx / 33, xx = tpx - yy * 33;
            int iy = 2 * y0 + yy, ix = 2 * x0 + xx;    // pad_lo = 0
            int pos = yy * 33 + ((xx & 1) ? 17 + (xx >> 1) : (xx >> 1));
            uint2 v = make_uint2(0u, 0u);
            if (iy < NH && ix < NW) {
                size_t pix = ((size_t)(b * NH + iy) * NW + ix);
                v = *(const uint2*)(g_e1h + pix * 64 + ch * 16 + ci4 * 4);
            }
            *(uint2*)(in_s + pos * 24 + ci4 * 4) = v;
        }
        {
            const uint4* src = (const uint4*)(w2h + ch * 27648);
            uint4* dst = (uint4*)w_s;
            for (int t = tid; t < 3456; t += 512) dst[t] = src[t];
        }
        __syncthreads();

        #pragma unroll
        for (int tap = 0; tap < 9; tap++) {
            const int ky = tap / 3, kx = tap - 3 * (tap / 3);
            const int colbase = (kx == 1) ? 17 : (kx >> 1);
            uint32_t a[2][4];
            #pragma unroll
            for (int mt = 0; mt < 2; mt++) {
                const int yl = 2 * wy + mt;
                const __half* base = in_s + ((2 * yl + ky) * 33 + colbase) * 24 + 2 * tig;
                a[mt][0] = *(const uint32_t*)(base + gid * 24);
                a[mt][1] = *(const uint32_t*)(base + (gid + 8) * 24);
                a[mt][2] = *(const uint32_t*)(base + gid * 24 + 8);
                a[mt][3] = *(const uint32_t*)(base + (gid + 8) * 24 + 8);
            }
            const __half* wb = w_s + (tap * 128 + coh * 64 + gid) * 24 + 2 * tig;
            #pragma unroll
            for (int nt = 0; nt < 8; nt++) {
                const __half* pb = wb + nt * 8 * 24;
                uint32_t b0 = *(const uint32_t*)(pb);
                uint32_t b1 = *(const uint32_t*)(pb + 8);
                mma_f16(c[0][nt], a[0][0], a[0][1], a[0][2], a[0][3], b0, b1);
                mma_f16(c[1][nt], a[1][0], a[1][1], a[1][2], a[1][3], b0, b1);
            }
        }
    }

    #pragma unroll
    for (int mt = 0; mt < 2; mt++) {
        const int y = y0 + 2 * wy + mt;
        #pragma unroll
        for (int nt = 0; nt < 8; nt++) {
            const int co = coh * 64 + 8 * nt + 2 * tig;
            size_t p1 = ((size_t)(b * (NH/2) + y) * (NW/2) + x0 + gid) * 128 + co;
            size_t p2 = ((size_t)(b * (NH/2) + y) * (NW/2) + x0 + gid + 8) * 128 + co;
            *(__half2*)(g_dh + p1) = __floats2half2_rn(fmaxf(c[mt][nt][0], 0.f),
                                                       fmaxf(c[mt][nt][1], 0.f));
            *(__half2*)(g_dh + p2) = __floats2half2_rn(fmaxf(c[mt][nt][2], 0.f),
                                                       fmaxf(c[mt][nt][3], 0.f));
        }
    }
}

// ---------------------------------------------------------------------------
// conv4: 64->3 3x3 SAME fp16 mma (N=8, 3 live), + rgb residual, fp32 NCHW out.
static constexpr int C4_SMEM_BYTES = (324 * 24 + 9 * 8 * 24) * 2;  // 19008

__global__ __launch_bounds__(256)
void conv4_kernel(float* __restrict__ out)
{
    extern __shared__ __half c4sm[];
    __half* in_s = c4sm;               // [pos(324)][24]
    __half* w_s  = c4sm + 324 * 24;    // [tap*8+co][24]

    const int tid  = threadIdx.x;
    const int w    = tid >> 5;
    const int lane = tid & 31;
    const int gid  = lane >> 2;
    const int tig  = lane & 3;

    const int x0 = blockIdx.x * 16, y0 = blockIdx.y * 16, b = blockIdx.z;

    float c[2][4];
    #pragma unroll
    for (int mt = 0; mt < 2; mt++)
        #pragma unroll
        for (int q = 0; q < 4; q++) c[mt][q] = 0.f;

    for (int ch = 0; ch < 4; ch++) {
        __syncthreads();
        for (int t = tid; t < 324 * 4; t += 256) {
            int tpx = t >> 2, ci4 = t & 3;
            int yy = tpx / 18, xx = tpx - yy * 18;
            int iy = y0 - 1 + yy, ix = x0 - 1 + xx;
            uint2 v = make_uint2(0u, 0u);
            if (iy >= 0 && iy < NH && ix >= 0 && ix < NW) {
                size_t pix = ((size_t)(b * NH + iy) * NW + ix);
                v = *(const uint2*)(g_mh + pix * 64 + ch * 16 + ci4 * 4);
            }
            *(uint2*)(in_s + tpx * 24 + ci4 * 4) = v;
        }
        {
            const uint4* src = (const uint4*)(w4h + ch * 1728);
            uint4* dst = (uint4*)w_s;
            for (int t = tid; t < 216; t += 256) dst[t] = src[t];
        }
        __syncthreads();

        #pragma unroll
        for (int tap = 0; tap < 9; tap++) {
            const int ky = tap / 3, kx = tap - 3 * (tap / 3);
            const __half* wb = w_s + (tap * 8 + gid) * 24 + 2 * tig;
            uint32_t b0 = *(const uint32_t*)(wb);
            uint32_t b1 = *(const uint32_t*)(wb + 8);
            #pragma unroll
            for (int mt = 0; mt < 2; mt++) {
                const int yl = 2 * w + mt;
                const __half* base = in_s + ((yl + ky) * 18 + kx) * 24 + 2 * tig;
                uint32_t a0 = *(const uint32_t*)(base + gid * 24);
                uint32_t a1 = *(const uint32_t*)(base + (gid + 8) * 24);
                uint32_t a2 = *(const uint32_t*)(base + gid * 24 + 8);
                uint32_t a3 = *(const uint32_t*)(base + (gid + 8) * 24 + 8);
                mma_f16(c[mt], a0, a1, a2, a3, b0, b1);
            }
        }
    }

    if (tig < 2) {
        #pragma unroll
        for (int mt = 0; mt < 2; mt++) {
            const int y = y0 + 2 * w + mt;
            const int co0 = 2 * tig;
            const int x1 = x0 + gid, x2 = x0 + gid + 8;
            {
                int base = ((b*3 + co0) * NH + y) * NW;
                out[base + x1] = c[mt][0] + g_rgb[base + x1];
                out[base + x2] = c[mt][2] + g_rgb[base + x2];
            }
            if (co0 + 1 < 3) {
                int base = ((b*3 + co0 + 1) * NH + y) * NW;
                out[base + x1] = c[mt][1] + g_rgb[base + x1];
                out[base + x2] = c[mt][3] + g_rgb[base + x2];
            }
        }
    }
}

// ---------------------------------------------------------------------------
extern "C" void kernel_launch(void* const* d_in, const int* in_sizes, int n_in,
                              void* d_out, int out_size)
{
    const float* zbuf = (const float*)d_in[0];
    const float* ray  = (const float*)d_in[1];
    const float* w0 = (const float*)d_in[4];
    const float* b0 = (const float*)d_in[5];
    const float* w1 = (const float*)d_in[6];
    const float* b1 = (const float*)d_in[7];
    const float* w2 = (const float*)d_in[8];
    const float* b2 = (const float*)d_in[9];
    const float* k1 = (const float*)d_in[10];
    const float* k2 = (const float*)d_in[11];
    const float* k3 = (const float*)d_in[12];
    const float* k4 = (const float*)d_in[13];
    float* out = (float*)d_out;

    cudaFuncSetAttribute(mlp_kernel,
                         cudaFuncAttributeMaxDynamicSharedMemorySize, MLP_SMEM_BYTES);
    cudaFuncSetAttribute(conv13_kernel,
                         cudaFuncAttributeMaxDynamicSharedMemorySize, C13_SMEM_BYTES);
    cudaFuncSetAttribute(conv2_kernel,
                         cudaFuncAttributeMaxDynamicSharedMemorySize, C2_SMEM_BYTES);
    cudaFuncSetAttribute(conv4_kernel,
                         cudaFuncAttributeMaxDynamicSharedMemorySize, C4_SMEM_BYTES);

    const int prep_total = W1H_SZ + W2H_SZ + W3H_SZ + W4H_SZ + W1M_SZ + W2M_SZ;
    prep_weights<<<(prep_total + 255) / 256, 256>>>(k1, k2, k3, k4, w1, w2);

    mlp_kernel<<<(NB*NH*NW)/128, 256, MLP_SMEM_BYTES>>>(zbuf, ray, w0, b0, b1, b2);
    conv13_kernel<<<dim3(NW/16, NH/16, NB), 256, C13_SMEM_BYTES>>>(1, 0);
    conv2_kernel <<<dim3(16, 16, NB), 512, C2_SMEM_BYTES>>>();
    conv13_kernel<<<dim3(NW/16, NH/16, NB), 256, C13_SMEM_BYTES>>>(6, 1);
    conv4_kernel <<<dim3(NW/16, NH/16, NB), 256, C4_SMEM_BYTES>>>(out);
}

// round 12
// speedup vs baseline: 4.5939x; 1.0775x over previous
#include <cuda_runtime.h>
#include <cuda_fp16.h>
#include <cstdint>

// Renderer_45612552684068 — round 10: ldmatrix.x4 fragment loads everywhere
// (conv13, conv2, MLP layers 1/2). Math identical to passing R9 kernel.

static constexpr int NB   = 4;
static constexpr int NH   = 512;
static constexpr int NW   = 512;
static constexpr int HID  = 128;
static constexpr int CIN  = 29;
static constexpr int C1C  = 64;
static constexpr int C2C  = 128;

__device__ __align__(16) float  g_rgb[NB * 3 * NH * NW];
__device__ __align__(16) __half g_xh [NB * NH * NW * 32];
__device__ __align__(16) __half g_e1h[NB * NH * NW * 64];
__device__ __align__(16) __half g_dh [NB * (NH/2) * (NW/2) * 128];
__device__ __align__(16) __half g_mh [NB * NH * NW * 64];

static constexpr int W1H_SZ = 9 * 64 * 40;
static constexpr int W2H_SZ = 4 * 9 * 128 * 24;
static constexpr int W3H_SZ = 6 * 9 * 64 * 40;
static constexpr int W4H_SZ = 4 * 9 * 8 * 24;
__device__ __align__(16) __half w1h[W1H_SZ];
__device__ __align__(16) __half w2h[W2H_SZ];
__device__ __align__(16) __half w3h[W3H_SZ];
__device__ __align__(16) __half w4h[W4H_SZ];
static constexpr int W1M_SZ = 128 * 136;
static constexpr int W2M_SZ = 32 * 136;
__device__ __align__(16) __half w1mh[W1M_SZ];
__device__ __align__(16) __half w2mh[W2M_SZ];

__device__ __forceinline__ void mma_f16(float c[4],
                                        uint32_t a0, uint32_t a1,
                                        uint32_t a2, uint32_t a3,
                                        uint32_t b0, uint32_t b1) {
    asm volatile(
        "mma.sync.aligned.m16n8k16.row.col.f32.f16.f16.f32 "
        "{%0,%1,%2,%3}, {%4,%5,%6,%7}, {%8,%9}, {%0,%1,%2,%3};"
        : "+f"(c[0]), "+f"(c[1]), "+f"(c[2]), "+f"(c[3])
        : "r"(a0), "r"(a1), "r"(a2), "r"(a3), "r"(b0), "r"(b1));
}

__device__ __forceinline__ void ldsm4(uint32_t& r0, uint32_t& r1,
                                      uint32_t& r2, uint32_t& r3,
                                      const __half* p) {
    uint32_t a = (uint32_t)__cvta_generic_to_shared(p);
    asm volatile("ldmatrix.sync.aligned.m8n8.x4.shared.b16 {%0,%1,%2,%3}, [%4];"
                 : "=r"(r0), "=r"(r1), "=r"(r2), "=r"(r3) : "r"(a));
}

// ---------------------------------------------------------------------------
__global__ void prep_weights(const float* __restrict__ k1, const float* __restrict__ k2,
                             const float* __restrict__ k3, const float* __restrict__ k4,
                             const float* __restrict__ mw1, const float* __restrict__ mw2)
{
    int i = blockIdx.x * 256 + threadIdx.x;
    if (i < W1H_SZ) {
        int tap = i / 2560, r = i % 2560, co = r / 40, k = r % 40;
        w1h[i] = __float2half(k < CIN ? k1[(co * CIN + k) * 9 + tap] : 0.f);
        return;
    }
    i -= W1H_SZ;
    if (i < W2H_SZ) {
        int c = i / 27648, r = i % 27648;
        int tap = r / 3072, co = (r % 3072) / 24, k = r % 24;
        w2h[i] = __float2half(k < 16 ? k2[(co * C1C + c * 16 + k) * 9 + tap] : 0.f);
        return;
    }
    i -= W2H_SZ;
    if (i < W3H_SZ) {
        int c = i / 23040, r = i % 23040;
        int tap = r / 2560, co = (r % 2560) / 40, k = r % 40;
        w3h[i] = __float2half(k < 32 ? k3[(co * (C2C + C1C) + c * 32 + k) * 9 + tap] : 0.f);
        return;
    }
    i -= W3H_SZ;
    if (i < W4H_SZ) {
        int c = i / 1728, r = i % 1728;
        int tap = r / 192, co = (r % 192) / 24, k = r % 24;
        w4h[i] = __float2half((k < 16 && co < 3) ? k4[(co * C1C + c * 16 + k) * 9 + tap] : 0.f);
        return;
    }
    i -= W4H_SZ;
    if (i < W1M_SZ) {
        int n = i / 136, k = i % 136;
        w1mh[i] = __float2half(k < HID ? mw1[k * HID + n] : 0.f);
        return;
    }
    i -= W1M_SZ;
    if (i < W2M_SZ) {
        int n = i / 136, k = i % 136;
        w2mh[i] = __float2half(k < HID ? mw2[k * 32 + n] : 0.f);
    }
}

// ---------------------------------------------------------------------------
// MLP: layer0 fp32 scalar; layers 1/2 fp16 mma via ldmatrix.
static constexpr int MLP_H1_OFF  = 0;
static constexpr int MLP_W1_OFF  = 34816;
static constexpr int MLP_W2_OFF  = 69632;
static constexpr int MLP_W0_OFF  = 78336;
static constexpr int MLP_FIN_OFF = 81408;
static constexpr int MLP_Z_OFF   = 85504;
static constexpr int MLP_B0_OFF  = 86016;
static constexpr int MLP_B1_OFF  = 86528;
static constexpr int MLP_B2_OFF  = 87040;
static constexpr int MLP_SMEM_BYTES = 87168;

__global__ __launch_bounds__(256)
void mlp_kernel(const float* __restrict__ zbuf, const float* __restrict__ ray,
                const float* __restrict__ w0, const float* __restrict__ b0,
                const float* __restrict__ b1, const float* __restrict__ b2)
{
    extern __shared__ __align__(16) char msm[];
    __half* sh_h1 = (__half*)(msm + MLP_H1_OFF);
    __half* sh_w1 = (__half*)(msm + MLP_W1_OFF);
    __half* sh_w2 = (__half*)(msm + MLP_W2_OFF);
    float*  sh_w0 = (float*)(msm + MLP_W0_OFF);
    float*  sh_fin= (float*)(msm + MLP_FIN_OFF);
    float*  sh_z  = (float*)(msm + MLP_Z_OFF);
    float*  sh_b0 = (float*)(msm + MLP_B0_OFF);
    float*  sh_b1 = (float*)(msm + MLP_B1_OFF);
    float*  sh_b2 = (float*)(msm + MLP_B2_OFF);

    const int tid   = threadIdx.x;
    const int w     = tid >> 5;
    const int lane  = tid & 31;
    const int gid   = lane >> 2;
    const int tig   = lane & 3;
    const int aRow  = lane & 15;
    const int aCol  = (lane >> 4) * 8;
    const int bRow  = (lane & 7) + 8 * (lane >> 4);
    const int bCol  = 8 * ((lane >> 3) & 1);
    const int pbase = blockIdx.x * 128;

    {
        const uint4* s1 = (const uint4*)w1mh;
        uint4* d1 = (uint4*)sh_w1;
        for (int t = tid; t < W1M_SZ / 8; t += 256) d1[t] = s1[t];
        const uint4* s2 = (const uint4*)w2mh;
        uint4* d2 = (uint4*)sh_w2;
        for (int t = tid; t < W2M_SZ / 8; t += 256) d2[t] = s2[t];
        for (int t = tid; t < 768; t += 256) sh_w0[t] = w0[t];
        if (tid < 128) { sh_b0[tid] = b0[tid]; sh_b1[tid] = b1[tid]; }
        if (tid < 32)  sh_b2[tid] = b2[tid];
    }

    if (tid < 128) {
        int pix = pbase + tid;
        int b = pix >> 18;
        int y = (pix >> 9) & 511;
        int x = pix & 511;
        int pi = (b * NH + y) * NW + x;
        float z = zbuf[pi];
        const float* r = ray + pi * 7;
        float t  = z / r[6];
        float d0 = r[3], d1 = r[4], d2 = r[5];
        sh_fin[tid * 8 + 0] = fmaf(d0, t, r[0]);
        sh_fin[tid * 8 + 1] = fmaf(d1, t, r[1]);
        sh_fin[tid * 8 + 2] = fmaf(d2, t, r[2]);
        sh_fin[tid * 8 + 3] = d0;
        sh_fin[tid * 8 + 4] = d1;
        sh_fin[tid * 8 + 5] = d2;
        sh_z[tid] = z;
    }
    __syncthreads();

    // layer0
    {
        const int p  = tid & 127;
        const int ob = (tid >> 7) * 64;
        float f0 = sh_fin[p*8+0], f1 = sh_fin[p*8+1], f2 = sh_fin[p*8+2];
        float f3 = sh_fin[p*8+3], f4 = sh_fin[p*8+4], f5 = sh_fin[p*8+5];
        #pragma unroll 8
        for (int o = ob; o < ob + 64; o += 2) {
            float a0 = sh_b0[o],     a1 = sh_b0[o+1];
            a0 = fmaf(f0, sh_w0[0*HID + o], a0);  a1 = fmaf(f0, sh_w0[0*HID + o+1], a1);
            a0 = fmaf(f1, sh_w0[1*HID + o], a0);  a1 = fmaf(f1, sh_w0[1*HID + o+1], a1);
            a0 = fmaf(f2, sh_w0[2*HID + o], a0);  a1 = fmaf(f2, sh_w0[2*HID + o+1], a1);
            a0 = fmaf(f3, sh_w0[3*HID + o], a0);  a1 = fmaf(f3, sh_w0[3*HID + o+1], a1);
            a0 = fmaf(f4, sh_w0[4*HID + o], a0);  a1 = fmaf(f4, sh_w0[4*HID + o+1], a1);
            a0 = fmaf(f5, sh_w0[5*HID + o], a0);  a1 = fmaf(f5, sh_w0[5*HID + o+1], a1);
            *(__half2*)(sh_h1 + p * 136 + o) =
                __floats2half2_rn(fmaxf(a0, 0.f), fmaxf(a1, 0.f));
        }
    }
    __syncthreads();

    // layer1: 32px x 64n per warp, ldmatrix fragments
    const int mw = w & 3, nw = w >> 2;
    const int mbase = 32 * mw, nbase = 64 * nw;
    float c1[2][8][4];
    #pragma unroll
    for (int mt = 0; mt < 2; mt++)
        #pragma unroll
        for (int nt = 0; nt < 8; nt++)
            #pragma unroll
            for (int q = 0; q < 4; q++) c1[mt][nt][q] = 0.f;

    #pragma unroll
    for (int ks = 0; ks < 8; ks++) {
        const int kofs = 16 * ks;
        uint32_t a[2][4];
        #pragma unroll
        for (int mt = 0; mt < 2; mt++)
            ldsm4(a[mt][0], a[mt][1], a[mt][2], a[mt][3],
                  sh_h1 + (mbase + 16*mt + aRow) * 136 + kofs + aCol);
        #pragma unroll
        for (int p = 0; p < 4; p++) {
            uint32_t bb[4];
            ldsm4(bb[0], bb[1], bb[2], bb[3],
                  sh_w1 + (nbase + 16*p + bRow) * 136 + kofs + bCol);
            mma_f16(c1[0][2*p],   a[0][0], a[0][1], a[0][2], a[0][3], bb[0], bb[1]);
            mma_f16(c1[1][2*p],   a[1][0], a[1][1], a[1][2], a[1][3], bb[0], bb[1]);
            mma_f16(c1[0][2*p+1], a[0][0], a[0][1], a[0][2], a[0][3], bb[2], bb[3]);
            mma_f16(c1[1][2*p+1], a[1][0], a[1][1], a[1][2], a[1][3], bb[2], bb[3]);
        }
    }
    __syncthreads();

    #pragma unroll
    for (int nt = 0; nt < 8; nt++) {
        const int n0 = nbase + 8*nt + 2*tig;
        float bb0 = sh_b1[n0], bb1 = sh_b1[n0 + 1];
        #pragma unroll
        for (int mt = 0; mt < 2; mt++) {
            int p0 = mbase + 16*mt + gid;
            *(__half2*)(sh_h1 + p0 * 136 + n0) =
                __floats2half2_rn(fmaxf(c1[mt][nt][0] + bb0, 0.f),
                                  fmaxf(c1[mt][nt][1] + bb1, 0.f));
            *(__half2*)(sh_h1 + (p0 + 8) * 136 + n0) =
                __floats2half2_rn(fmaxf(c1[mt][nt][2] + bb0, 0.f),
                                  fmaxf(c1[mt][nt][3] + bb1, 0.f));
        }
    }
    __syncthreads();

    // layer2: 16px per warp, N=32
    float d2[4][4];
    #pragma unroll
    for (int nt = 0; nt < 4; nt++)
        #pragma unroll
        for (int q = 0; q < 4; q++) d2[nt][q] = 0.f;

    #pragma unroll
    for (int ks = 0; ks < 8; ks++) {
        const int kofs = 16 * ks;
        uint32_t a0, a1, a2, a3;
        ldsm4(a0, a1, a2, a3, sh_h1 + (16*w + aRow) * 136 + kofs + aCol);
        #pragma unroll
        for (int p = 0; p < 2; p++) {
            uint32_t bb[4];
            ldsm4(bb[0], bb[1], bb[2], bb[3],
                  sh_w2 + (16*p + bRow) * 136 + kofs + bCol);
            mma_f16(d2[2*p],   a0, a1, a2, a3, bb[0], bb[1]);
            mma_f16(d2[2*p+1], a0, a1, a2, a3, bb[2], bb[3]);
        }
    }

    #pragma unroll
    for (int nt = 0; nt < 4; nt++) {
        const int n0 = 8*nt + 2*tig;
        const float bb0 = sh_b2[n0], bb1 = sh_b2[n0 + 1];
        #pragma unroll
        for (int rr = 0; rr < 2; rr++) {
            const int p = 16*w + gid + 8*rr;
            const int pix = pbase + p;
            const bool mask = sh_z[p] > 0.f;
            float v0 = mask ? (d2[nt][2*rr]     + bb0) : 1.0f;
            float v1 = mask ? (d2[nt][2*rr + 1] + bb1) : 1.0f;
            float x0 = (n0     < CIN) ? v0 : 0.f;
            float x1 = (n0 + 1 < CIN) ? v1 : 0.f;
            *(__half2*)(g_xh + (size_t)pix * 32 + n0) = __floats2half2_rn(x0, x1);
            if (n0 + 1 >= CIN) {
                int b = pix >> 18;
                int y = (pix >> 9) & 511;
                int x = pix & 511;
                if (n0 >= CIN)
                    g_rgb[((b*3 + (n0 - CIN)) * NH + y) * NW + x] = v0;
                g_rgb[((b*3 + (n0 + 1 - CIN)) * NH + y) * NW + x] = v1;
            }
        }
    }
}

// ---------------------------------------------------------------------------
// conv13: 3x3 SAME stride-1, ldmatrix fragments.
static constexpr int C13_SMEM_BYTES = (324 * 40 + 9 * 64 * 40) * 2;  // 72000

__global__ __launch_bounds__(256)
void conv13_kernel(int nchunks, int mode)
{
    extern __shared__ __half c13sm[];
    __half* in_s = c13sm;               // [pos(324)][40]
    __half* w_s  = c13sm + 324 * 40;    // [tap*64+co][40]

    const int tid  = threadIdx.x;
    const int w    = tid >> 5;
    const int lane = tid & 31;
    const int gid  = lane >> 2;
    const int tig  = lane & 3;
    const int aRow = lane & 15;
    const int aCol = (lane >> 4) * 8;
    const int bRow = (lane & 7) + 8 * (lane >> 4);
    const int bCol = 8 * ((lane >> 3) & 1);

    const int x0 = blockIdx.x * 16, y0 = blockIdx.y * 16, b = blockIdx.z;

    float c[2][8][4];
    #pragma unroll
    for (int mt = 0; mt < 2; mt++)
        #pragma unroll
        for (int nt = 0; nt < 8; nt++)
            #pragma unroll
            for (int q = 0; q < 4; q++) c[mt][nt][q] = 0.f;

    const __half* wsrc = (mode == 0) ? w1h : w3h;

    for (int ch = 0; ch < nchunks; ch++) {
        __syncthreads();
        for (int t = tid; t < 324 * 8; t += 256) {
            int tpx = t >> 3, ci4 = t & 7;
            int yy = tpx / 18, xx = tpx - yy * 18;
            int iy = y0 - 1 + yy, ix = x0 - 1 + xx;
            uint2 v = make_uint2(0u, 0u);
            if (iy >= 0 && iy < NH && ix >= 0 && ix < NW) {
                if (mode == 0) {
                    size_t pix = ((size_t)(b * NH + iy) * NW + ix);
                    v = *(const uint2*)(g_xh + pix * 32 + ci4 * 4);
                } else {
                    int ci = ch * 32 + ci4 * 4;
                    if (ci < C2C) {
                        size_t pixd = ((size_t)(b * (NH/2) + (iy >> 1)) * (NW/2) + (ix >> 1));
                        v = *(const uint2*)(g_dh + pixd * 128 + ci);
                    } else {
                        size_t pix = ((size_t)(b * NH + iy) * NW + ix);
                        v = *(const uint2*)(g_e1h + pix * 64 + (ci - C2C));
                    }
                }
            }
            *(uint2*)(in_s + tpx * 40 + ci4 * 4) = v;
        }
        {
            const uint4* src = (const uint4*)(wsrc + ch * 23040);
            uint4* dst = (uint4*)w_s;
            for (int t = tid; t < 2880; t += 256) dst[t] = src[t];
        }
        __syncthreads();

        #pragma unroll
        for (int tap = 0; tap < 9; tap++) {
            const int ky = tap / 3, kx = tap - 3 * (tap / 3);
            #pragma unroll
            for (int g = 0; g < 2; g++) {
                uint32_t a[2][4];
                #pragma unroll
                for (int mt = 0; mt < 2; mt++)
                    ldsm4(a[mt][0], a[mt][1], a[mt][2], a[mt][3],
                          in_s + ((2*w + mt + ky) * 18 + kx + aRow) * 40 + 16*g + aCol);
                #pragma unroll
                for (int p = 0; p < 4; p++) {
                    uint32_t bb[4];
                    ldsm4(bb[0], bb[1], bb[2], bb[3],
                          w_s + (tap * 64 + 16*p + bRow) * 40 + 16*g + bCol);
                    mma_f16(c[0][2*p],   a[0][0], a[0][1], a[0][2], a[0][3], bb[0], bb[1]);
                    mma_f16(c[1][2*p],   a[1][0], a[1][1], a[1][2], a[1][3], bb[0], bb[1]);
                    mma_f16(c[0][2*p+1], a[0][0], a[0][1], a[0][2], a[0][3], bb[2], bb[3]);
                    mma_f16(c[1][2*p+1], a[1][0], a[1][1], a[1][2], a[1][3], bb[2], bb[3]);
                }
            }
        }
    }

    __half* dst = (mode == 0) ? g_e1h : g_mh;
    #pragma unroll
    for (int mt = 0; mt < 2; mt++) {
        const int y = y0 + 2 * w + mt;
        #pragma unroll
        for (int nt = 0; nt < 8; nt++) {
            const int co = 8 * nt + 2 * tig;
            size_t p1 = ((size_t)(b * NH + y) * NW + x0 + gid) * 64 + co;
            size_t p2 = ((size_t)(b * NH + y) * NW + x0 + gid + 8) * 64 + co;
            *(__half2*)(dst + p1) = __floats2half2_rn(fmaxf(c[mt][nt][0], 0.f),
                                                      fmaxf(c[mt][nt][1], 0.f));
            *(__half2*)(dst + p2) = __floats2half2_rn(fmaxf(c[mt][nt][2], 0.f),
                                                      fmaxf(c[mt][nt][3], 0.f));
        }
    }
}

// ---------------------------------------------------------------------------
// conv2: 64->128 stride-2 (pad_lo=0), parity-plane smem, ldmatrix fragments.
static constexpr int C2_SMEM_BYTES = (1089 * 24 + 9 * 128 * 24) * 2;  // 107568

__global__ __launch_bounds__(512)
void conv2_kernel()
{
    extern __shared__ __half c2sm[];
    __half* in_s = c2sm;                 // [pos(1089)][24]
    __half* w_s  = c2sm + 1089 * 24;     // [tap*128+co][24]

    const int tid  = threadIdx.x;
    const int w    = tid >> 5;
    const int lane = tid & 31;
    const int gid  = lane >> 2;
    const int tig  = lane & 3;
    const int aRow = lane & 15;
    const int aCol = (lane >> 4) * 8;
    const int bRow = (lane & 7) + 8 * (lane >> 4);
    const int bCol = 8 * ((lane >> 3) & 1);
    const int coh  = w >> 3;
    const int wy   = w & 7;

    const int x0 = blockIdx.x * 16, y0 = blockIdx.y * 16, b = blockIdx.z;

    float c[2][8][4];
    #pragma unroll
    for (int mt = 0; mt < 2; mt++)
        #pragma unroll
        for (int nt = 0; nt < 8; nt++)
            #pragma unroll
            for (int q = 0; q < 4; q++) c[mt][nt][q] = 0.f;

    for (int ch = 0; ch < 4; ch++) {
        __syncthreads();
        for (int t = tid; t < 1089 * 4; t += 512) {
            int tpx = t >> 2, ci4 = t & 3;
            int yy = tpx / 33, xx = tpx - yy * 33;
            int iy = 2 * y0 + yy, ix = 2 * x0 + xx;    // pad_lo = 0
            int pos = yy * 33 + ((xx & 1) ? 17 + (xx >> 1) : (xx >> 1));
            uint2 v = make_uint2(0u, 0u);
            if (iy < NH && ix < NW) {
                size_t pix = ((size_t)(b * NH + iy) * NW + ix);
                v = *(const uint2*)(g_e1h + pix * 64 + ch * 16 + ci4 * 4);
            }
            *(uint2*)(in_s + pos * 24 + ci4 * 4) = v;
        }
        {
            const uint4* src = (const uint4*)(w2h + ch * 27648);
            uint4* dst = (uint4*)w_s;
            for (int t = tid; t < 3456; t += 512) dst[t] = src[t];
        }
        __syncthreads();

        #pragma unroll
        for (int tap = 0; tap < 9; tap++) {
            const int ky = tap / 3, kx = tap - 3 * (tap / 3);
            const int colbase = (kx == 1) ? 17 : (kx >> 1);
            uint32_t a[2][4];
            #pragma unroll
            for (int mt = 0; mt < 2; mt++)
                ldsm4(a[mt][0], a[mt][1], a[mt][2], a[mt][3],
                      in_s + ((2*(2*wy + mt) + ky) * 33 + colbase + aRow) * 24 + aCol);
            #pragma unroll
            for (int p = 0; p < 4; p++) {
                uint32_t bb[4];
                ldsm4(bb[0], bb[1], bb[2], bb[3],
                      w_s + (tap * 128 + coh * 64 + 16*p + bRow) * 24 + bCol);
                mma_f16(c[0][2*p],   a[0][0], a[0][1], a[0][2], a[0][3], bb[0], bb[1]);
                mma_f16(c[1][2*p],   a[1][0], a[1][1], a[1][2], a[1][3], bb[0], bb[1]);
                mma_f16(c[0][2*p+1], a[0][0], a[0][1], a[0][2], a[0][3], bb[2], bb[3]);
                mma_f16(c[1][2*p+1], a[1][0], a[1][1], a[1][2], a[1][3], bb[2], bb[3]);
            }
        }
    }

    #pragma unroll
    for (int mt = 0; mt < 2; mt++) {
        const int y = y0 + 2 * wy + mt;
        #pragma unroll
        for (int nt = 0; nt < 8; nt++) {
            const int co = coh * 64 + 8 * nt + 2 * tig;
            size_t p1 = ((size_t)(b * (NH/2) + y) * (NW/2) + x0 + gid) * 128 + co;
            size_t p2 = ((size_t)(b * (NH/2) + y) * (NW/2) + x0 + gid + 8) * 128 + co;
            *(__half2*)(g_dh + p1) = __floats2half2_rn(fmaxf(c[mt][nt][0], 0.f),
                                                       fmaxf(c[mt][nt][1], 0.f));
            *(__half2*)(g_dh + p2) = __floats2half2_rn(fmaxf(c[mt][nt][2], 0.f),
                                                       fmaxf(c[mt][nt][3], 0.f));
        }
    }
}

// ---------------------------------------------------------------------------
// conv4: unchanged (passing, ~60us).
static constexpr int C4_SMEM_BYTES = (324 * 24 + 9 * 8 * 24) * 2;  // 19008

__global__ __launch_bounds__(256)
void conv4_kernel(float* __restrict__ out)
{
    extern __shared__ __half c4sm[];
    __half* in_s = c4sm;
    __half* w_s  = c4sm + 324 * 24;

    const int tid  = threadIdx.x;
    const int w    = tid >> 5;
    const int lane = tid & 31;
    const int gid  = lane >> 2;
    const int tig  = lane & 3;

    const int x0 = blockIdx.x * 16, y0 = blockIdx.y * 16, b = blockIdx.z;

    float c[2][4];
    #pragma unroll
    for (int mt = 0; mt < 2; mt++)
        #pragma unroll
        for (int q = 0; q < 4; q++) c[mt][q] = 0.f;

    for (int ch = 0; ch < 4; ch++) {
        __syncthreads();
        for (int t = tid; t < 324 * 4; t += 256) {
            int tpx = t >> 2, ci4 = t & 3;
            int yy = tpx / 18, xx = tpx - yy * 18;
            int iy = y0 - 1 + yy, ix = x0 - 1 + xx;
            uint2 v = make_uint2(0u, 0u);
            if (iy >= 0 && iy < NH && ix >= 0 && ix < NW) {
                size_t pix = ((size_t)(b * NH + iy) * NW + ix);
                v = *(const uint2*)(g_mh + pix * 64 + ch * 16 + ci4 * 4);
            }
            *(uint2*)(in_s + tpx * 24 + ci4 * 4) = v;
        }
        {
            const uint4* src = (const uint4*)(w4h + ch * 1728);
            uint4* dst = (uint4*)w_s;
            for (int t = tid; t < 216; t += 256) dst[t] = src[t];
        }
        __syncthreads();

        #pragma unroll
        for (int tap = 0; tap < 9; tap++) {
            const int ky = tap / 3, kx = tap - 3 * (tap / 3);
            const __half* wb = w_s + (tap * 8 + gid) * 24 + 2 * tig;
            uint32_t b0 = *(const uint32_t*)(wb);
            uint32_t b1 = *(const uint32_t*)(wb + 8);
            #pragma unroll
            for (int mt = 0; mt < 2; mt++) {
                const int yl = 2 * w + mt;
                const __half* base = in_s + ((yl + ky) * 18 + kx) * 24 + 2 * tig;
                uint32_t a0 = *(const uint32_t*)(base + gid * 24);
                uint32_t a1 = *(const uint32_t*)(base + (gid + 8) * 24);
                uint32_t a2 = *(const uint32_t*)(base + gid * 24 + 8);
                uint32_t a3 = *(const uint32_t*)(base + (gid + 8) * 24 + 8);
                mma_f16(c[mt], a0, a1, a2, a3, b0, b1);
            }
        }
    }

    if (tig < 2) {
        #pragma unroll
        for (int mt = 0; mt < 2; mt++) {
            const int y = y0 + 2 * w + mt;
            const int co0 = 2 * tig;
            const int x1 = x0 + gid, x2 = x0 + gid + 8;
            {
                int base = ((b*3 + co0) * NH + y) * NW;
                out[base + x1] = c[mt][0] + g_rgb[base + x1];
                out[base + x2] = c[mt][2] + g_rgb[base + x2];
            }
            if (co0 + 1 < 3) {
                int base = ((b*3 + co0 + 1) * NH + y) * NW;
                out[base + x1] = c[mt][1] + g_rgb[base + x1];
                out[base + x2] = c[mt][3] + g_rgb[base + x2];
            }
        }
    }
}

// ---------------------------------------------------------------------------
extern "C" void kernel_launch(void* const* d_in, const int* in_sizes, int n_in,
                              void* d_out, int out_size)
{
    const float* zbuf = (const float*)d_in[0];
    const float* ray  = (const float*)d_in[1];
    const float* w0 = (const float*)d_in[4];
    const float* b0 = (const float*)d_in[5];
    const float* w1 = (const float*)d_in[6];
    const float* b1 = (const float*)d_in[7];
    const float* w2 = (const float*)d_in[8];
    const float* b2 = (const float*)d_in[9];
    const float* k1 = (const float*)d_in[10];
    const float* k2 = (const float*)d_in[11];
    const float* k3 = (const float*)d_in[12];
    const float* k4 = (const float*)d_in[13];
    float* out = (float*)d_out;

    cudaFuncSetAttribute(mlp_kernel,
                         cudaFuncAttributeMaxDynamicSharedMemorySize, MLP_SMEM_BYTES);
    cudaFuncSetAttribute(conv13_kernel,
                         cudaFuncAttributeMaxDynamicSharedMemorySize, C13_SMEM_BYTES);
    cudaFuncSetAttribute(conv2_kernel,
                         cudaFuncAttributeMaxDynamicSharedMemorySize, C2_SMEM_BYTES);
    cudaFuncSetAttribute(conv4_kernel,
                         cudaFuncAttributeMaxDynamicSharedMemorySize, C4_SMEM_BYTES);

    const int prep_total = W1H_SZ + W2H_SZ + W3H_SZ + W4H_SZ + W1M_SZ + W2M_SZ;
    prep_weights<<<(prep_total + 255) / 256, 256>>>(k1, k2, k3, k4, w1, w2);

    mlp_kernel<<<(NB*NH*NW)/128, 256, MLP_SMEM_BYTES>>>(zbuf, ray, w0, b0, b1, b2);
    conv13_kernel<<<dim3(NW/16, NH/16, NB), 256, C13_SMEM_BYTES>>>(1, 0);
    conv2_kernel <<<dim3(16, 16, NB), 512, C2_SMEM_BYTES>>>();
    conv13_kernel<<<dim3(NW/16, NH/16, NB), 256, C13_SMEM_BYTES>>>(6, 1);
    conv4_kernel <<<dim3(NW/16, NH/16, NB), 256, C4_SMEM_BYTES>>>(out);
}

// round 13
// speedup vs baseline: 4.9212x; 1.0712x over previous
#include <cuda_runtime.h>
#include <cuda_fp16.h>
#include <cstdint>

// Renderer_45612552684068 — round 12: conv13 M-tile per warp 2->4 rows
// (CTA tile 16x32): 33% fewer LDSM/mma, 2x weight-staging amortization.
// conv2/conv4/MLP unchanged from passing R11.

static constexpr int NB   = 4;
static constexpr int NH   = 512;
static constexpr int NW   = 512;
static constexpr int HID  = 128;
static constexpr int CIN  = 29;
static constexpr int C1C  = 64;
static constexpr int C2C  = 128;

__device__ __align__(16) float  g_rgb[NB * 3 * NH * NW];
__device__ __align__(16) __half g_xh [NB * NH * NW * 32];
__device__ __align__(16) __half g_e1h[NB * NH * NW * 64];
__device__ __align__(16) __half g_dh [NB * (NH/2) * (NW/2) * 128];
__device__ __align__(16) __half g_mh [NB * NH * NW * 64];

static constexpr int W1H_SZ = 9 * 64 * 40;
static constexpr int W2H_SZ = 4 * 9 * 128 * 24;
static constexpr int W3H_SZ = 6 * 9 * 64 * 40;
static constexpr int W4H_SZ = 4 * 9 * 8 * 24;
__device__ __align__(16) __half w1h[W1H_SZ];
__device__ __align__(16) __half w2h[W2H_SZ];
__device__ __align__(16) __half w3h[W3H_SZ];
__device__ __align__(16) __half w4h[W4H_SZ];
static constexpr int W1M_SZ = 128 * 136;
static constexpr int W2M_SZ = 32 * 136;
__device__ __align__(16) __half w1mh[W1M_SZ];
__device__ __align__(16) __half w2mh[W2M_SZ];

__device__ __forceinline__ void mma_f16(float c[4],
                                        uint32_t a0, uint32_t a1,
                                        uint32_t a2, uint32_t a3,
                                        uint32_t b0, uint32_t b1) {
    asm volatile(
        "mma.sync.aligned.m16n8k16.row.col.f32.f16.f16.f32 "
        "{%0,%1,%2,%3}, {%4,%5,%6,%7}, {%8,%9}, {%0,%1,%2,%3};"
        : "+f"(c[0]), "+f"(c[1]), "+f"(c[2]), "+f"(c[3])
        : "r"(a0), "r"(a1), "r"(a2), "r"(a3), "r"(b0), "r"(b1));
}

__device__ __forceinline__ void ldsm4(uint32_t& r0, uint32_t& r1,
                                      uint32_t& r2, uint32_t& r3,
                                      const __half* p) {
    uint32_t a = (uint32_t)__cvta_generic_to_shared(p);
    asm volatile("ldmatrix.sync.aligned.m8n8.x4.shared.b16 {%0,%1,%2,%3}, [%4];"
                 : "=r"(r0), "=r"(r1), "=r"(r2), "=r"(r3) : "r"(a));
}

// ---------------------------------------------------------------------------
__global__ void prep_weights(const float* __restrict__ k1, const float* __restrict__ k2,
                             const float* __restrict__ k3, const float* __restrict__ k4,
                             const float* __restrict__ mw1, const float* __restrict__ mw2)
{
    int i = blockIdx.x * 256 + threadIdx.x;
    if (i < W1H_SZ) {
        int tap = i / 2560, r = i % 2560, co = r / 40, k = r % 40;
        w1h[i] = __float2half(k < CIN ? k1[(co * CIN + k) * 9 + tap] : 0.f);
        return;
    }
    i -= W1H_SZ;
    if (i < W2H_SZ) {
        int c = i / 27648, r = i % 27648;
        int tap = r / 3072, co = (r % 3072) / 24, k = r % 24;
        w2h[i] = __float2half(k < 16 ? k2[(co * C1C + c * 16 + k) * 9 + tap] : 0.f);
        return;
    }
    i -= W2H_SZ;
    if (i < W3H_SZ) {
        int c = i / 23040, r = i % 23040;
        int tap = r / 2560, co = (r % 2560) / 40, k = r % 40;
        w3h[i] = __float2half(k < 32 ? k3[(co * (C2C + C1C) + c * 32 + k) * 9 + tap] : 0.f);
        return;
    }
    i -= W3H_SZ;
    if (i < W4H_SZ) {
        int c = i / 1728, r = i % 1728;
        int tap = r / 192, co = (r % 192) / 24, k = r % 24;
        w4h[i] = __float2half((k < 16 && co < 3) ? k4[(co * C1C + c * 16 + k) * 9 + tap] : 0.f);
        return;
    }
    i -= W4H_SZ;
    if (i < W1M_SZ) {
        int n = i / 136, k = i % 136;
        w1mh[i] = __float2half(k < HID ? mw1[k * HID + n] : 0.f);
        return;
    }
    i -= W1M_SZ;
    if (i < W2M_SZ) {
        int n = i / 136, k = i % 136;
        w2mh[i] = __float2half(k < HID ? mw2[k * 32 + n] : 0.f);
    }
}

// ---------------------------------------------------------------------------
// MLP (unchanged from passing R11)
static constexpr int MLP_H1_OFF  = 0;
static constexpr int MLP_W1_OFF  = 34816;
static constexpr int MLP_W2_OFF  = 69632;
static constexpr int MLP_W0_OFF  = 78336;
static constexpr int MLP_FIN_OFF = 81408;
static constexpr int MLP_Z_OFF   = 85504;
static constexpr int MLP_B0_OFF  = 86016;
static constexpr int MLP_B1_OFF  = 86528;
static constexpr int MLP_B2_OFF  = 87040;
static constexpr int MLP_SMEM_BYTES = 87168;

__global__ __launch_bounds__(256)
void mlp_kernel(const float* __restrict__ zbuf, const float* __restrict__ ray,
                const float* __restrict__ w0, const float* __restrict__ b0,
                const float* __restrict__ b1, const float* __restrict__ b2)
{
    extern __shared__ __align__(16) char msm[];
    __half* sh_h1 = (__half*)(msm + MLP_H1_OFF);
    __half* sh_w1 = (__half*)(msm + MLP_W1_OFF);
    __half* sh_w2 = (__half*)(msm + MLP_W2_OFF);
    float*  sh_w0 = (float*)(msm + MLP_W0_OFF);
    float*  sh_fin= (float*)(msm + MLP_FIN_OFF);
    float*  sh_z  = (float*)(msm + MLP_Z_OFF);
    float*  sh_b0 = (float*)(msm + MLP_B0_OFF);
    float*  sh_b1 = (float*)(msm + MLP_B1_OFF);
    float*  sh_b2 = (float*)(msm + MLP_B2_OFF);

    const int tid   = threadIdx.x;
    const int w     = tid >> 5;
    const int lane  = tid & 31;
    const int gid   = lane >> 2;
    const int tig   = lane & 3;
    const int aRow  = lane & 15;
    const int aCol  = (lane >> 4) * 8;
    const int bRow  = (lane & 7) + 8 * (lane >> 4);
    const int bCol  = 8 * ((lane >> 3) & 1);
    const int pbase = blockIdx.x * 128;

    {
        const uint4* s1 = (const uint4*)w1mh;
        uint4* d1 = (uint4*)sh_w1;
        for (int t = tid; t < W1M_SZ / 8; t += 256) d1[t] = s1[t];
        const uint4* s2 = (const uint4*)w2mh;
        uint4* d2 = (uint4*)sh_w2;
        for (int t = tid; t < W2M_SZ / 8; t += 256) d2[t] = s2[t];
        for (int t = tid; t < 768; t += 256) sh_w0[t] = w0[t];
        if (tid < 128) { sh_b0[tid] = b0[tid]; sh_b1[tid] = b1[tid]; }
        if (tid < 32)  sh_b2[tid] = b2[tid];
    }

    if (tid < 128) {
        int pix = pbase + tid;
        int b = pix >> 18;
        int y = (pix >> 9) & 511;
        int x = pix & 511;
        int pi = (b * NH + y) * NW + x;
        float z = zbuf[pi];
        const float* r = ray + pi * 7;
        float t  = z / r[6];
        float d0 = r[3], d1 = r[4], d2 = r[5];
        sh_fin[tid * 8 + 0] = fmaf(d0, t, r[0]);
        sh_fin[tid * 8 + 1] = fmaf(d1, t, r[1]);
        sh_fin[tid * 8 + 2] = fmaf(d2, t, r[2]);
        sh_fin[tid * 8 + 3] = d0;
        sh_fin[tid * 8 + 4] = d1;
        sh_fin[tid * 8 + 5] = d2;
        sh_z[tid] = z;
    }
    __syncthreads();

    {
        const int p  = tid & 127;
        const int ob = (tid >> 7) * 64;
        float f0 = sh_fin[p*8+0], f1 = sh_fin[p*8+1], f2 = sh_fin[p*8+2];
        float f3 = sh_fin[p*8+3], f4 = sh_fin[p*8+4], f5 = sh_fin[p*8+5];
        #pragma unroll 8
        for (int o = ob; o < ob + 64; o += 2) {
            float a0 = sh_b0[o],     a1 = sh_b0[o+1];
            a0 = fmaf(f0, sh_w0[0*HID + o], a0);  a1 = fmaf(f0, sh_w0[0*HID + o+1], a1);
            a0 = fmaf(f1, sh_w0[1*HID + o], a0);  a1 = fmaf(f1, sh_w0[1*HID + o+1], a1);
            a0 = fmaf(f2, sh_w0[2*HID + o], a0);  a1 = fmaf(f2, sh_w0[2*HID + o+1], a1);
            a0 = fmaf(f3, sh_w0[3*HID + o], a0);  a1 = fmaf(f3, sh_w0[3*HID + o+1], a1);
            a0 = fmaf(f4, sh_w0[4*HID + o], a0);  a1 = fmaf(f4, sh_w0[4*HID + o+1], a1);
            a0 = fmaf(f5, sh_w0[5*HID + o], a0);  a1 = fmaf(f5, sh_w0[5*HID + o+1], a1);
            *(__half2*)(sh_h1 + p * 136 + o) =
                __floats2half2_rn(fmaxf(a0, 0.f), fmaxf(a1, 0.f));
        }
    }
    __syncthreads();

    const int mw = w & 3, nw = w >> 2;
    const int mbase = 32 * mw, nbase = 64 * nw;
    float c1[2][8][4];
    #pragma unroll
    for (int mt = 0; mt < 2; mt++)
        #pragma unroll
        for (int nt = 0; nt < 8; nt++)
            #pragma unroll
            for (int q = 0; q < 4; q++) c1[mt][nt][q] = 0.f;

    #pragma unroll
    for (int ks = 0; ks < 8; ks++) {
        const int kofs = 16 * ks;
        uint32_t a[2][4];
        #pragma unroll
        for (int mt = 0; mt < 2; mt++)
            ldsm4(a[mt][0], a[mt][1], a[mt][2], a[mt][3],
                  sh_h1 + (mbase + 16*mt + aRow) * 136 + kofs + aCol);
        #pragma unroll
        for (int p = 0; p < 4; p++) {
            uint32_t bb[4];
            ldsm4(bb[0], bb[1], bb[2], bb[3],
                  sh_w1 + (nbase + 16*p + bRow) * 136 + kofs + bCol);
            mma_f16(c1[0][2*p],   a[0][0], a[0][1], a[0][2], a[0][3], bb[0], bb[1]);
            mma_f16(c1[1][2*p],   a[1][0], a[1][1], a[1][2], a[1][3], bb[0], bb[1]);
            mma_f16(c1[0][2*p+1], a[0][0], a[0][1], a[0][2], a[0][3], bb[2], bb[3]);
            mma_f16(c1[1][2*p+1], a[1][0], a[1][1], a[1][2], a[1][3], bb[2], bb[3]);
        }
    }
    __syncthreads();

    #pragma unroll
    for (int nt = 0; nt < 8; nt++) {
        const int n0 = nbase + 8*nt + 2*tig;
        float bb0 = sh_b1[n0], bb1 = sh_b1[n0 + 1];
        #pragma unroll
        for (int mt = 0; mt < 2; mt++) {
            int p0 = mbase + 16*mt + gid;
            *(__half2*)(sh_h1 + p0 * 136 + n0) =
                __floats2half2_rn(fmaxf(c1[mt][nt][0] + bb0, 0.f),
                                  fmaxf(c1[mt][nt][1] + bb1, 0.f));
            *(__half2*)(sh_h1 + (p0 + 8) * 136 + n0) =
                __floats2half2_rn(fmaxf(c1[mt][nt][2] + bb0, 0.f),
                                  fmaxf(c1[mt][nt][3] + bb1, 0.f));
        }
    }
    __syncthreads();

    float d2[4][4];
    #pragma unroll
    for (int nt = 0; nt < 4; nt++)
        #pragma unroll
        for (int q = 0; q < 4; q++) d2[nt][q] = 0.f;

    #pragma unroll
    for (int ks = 0; ks < 8; ks++) {
        const int kofs = 16 * ks;
        uint32_t a0, a1, a2, a3;
        ldsm4(a0, a1, a2, a3, sh_h1 + (16*w + aRow) * 136 + kofs + aCol);
        #pragma unroll
        for (int p = 0; p < 2; p++) {
            uint32_t bb[4];
            ldsm4(bb[0], bb[1], bb[2], bb[3],
                  sh_w2 + (16*p + bRow) * 136 + kofs + bCol);
            mma_f16(d2[2*p],   a0, a1, a2, a3, bb[0], bb[1]);
            mma_f16(d2[2*p+1], a0, a1, a2, a3, bb[2], bb[3]);
        }
    }

    #pragma unroll
    for (int nt = 0; nt < 4; nt++) {
        const int n0 = 8*nt + 2*tig;
        const float bb0 = sh_b2[n0], bb1 = sh_b2[n0 + 1];
        #pragma unroll
        for (int rr = 0; rr < 2; rr++) {
            const int p = 16*w + gid + 8*rr;
            const int pix = pbase + p;
            const bool mask = sh_z[p] > 0.f;
            float v0 = mask ? (d2[nt][2*rr]     + bb0) : 1.0f;
            float v1 = mask ? (d2[nt][2*rr + 1] + bb1) : 1.0f;
            float x0 = (n0     < CIN) ? v0 : 0.f;
            float x1 = (n0 + 1 < CIN) ? v1 : 0.f;
            *(__half2*)(g_xh + (size_t)pix * 32 + n0) = __floats2half2_rn(x0, x1);
            if (n0 + 1 >= CIN) {
                int b = pix >> 18;
                int y = (pix >> 9) & 511;
                int x = pix & 511;
                if (n0 >= CIN)
                    g_rgb[((b*3 + (n0 - CIN)) * NH + y) * NW + x] = v0;
                g_rgb[((b*3 + (n0 + 1 - CIN)) * NH + y) * NW + x] = v1;
            }
        }
    }
}

// ---------------------------------------------------------------------------
// conv13: 3x3 SAME stride-1, tile 16x32 px, warp = 4 rows (mt=4), nt=8.
// smem: in_s[(34*18)=612 pos][40], w_s[9*64][40].  95,040 B.
static constexpr int C13_SMEM_BYTES = (612 * 40 + 9 * 64 * 40) * 2;  // 95040

__global__ __launch_bounds__(256, 1)
void conv13_kernel(int nchunks, int mode)
{
    extern __shared__ __half c13sm[];
    __half* in_s = c13sm;               // [pos(612)][40]
    __half* w_s  = c13sm + 612 * 40;    // [tap*64+co][40]

    const int tid  = threadIdx.x;
    const int w    = tid >> 5;
    const int lane = tid & 31;
    const int gid  = lane >> 2;
    const int tig  = lane & 3;
    const int aRow = lane & 15;
    const int aCol = (lane >> 4) * 8;
    const int bRow = (lane & 7) + 8 * (lane >> 4);
    const int bCol = 8 * ((lane >> 3) & 1);

    const int x0 = blockIdx.x * 16, y0 = blockIdx.y * 32, b = blockIdx.z;

    float c[4][8][4];
    #pragma unroll
    for (int mt = 0; mt < 4; mt++)
        #pragma unroll
        for (int nt = 0; nt < 8; nt++)
            #pragma unroll
            for (int q = 0; q < 4; q++) c[mt][nt][q] = 0.f;

    const __half* wsrc = (mode == 0) ? w1h : w3h;

    for (int ch = 0; ch < nchunks; ch++) {
        __syncthreads();
        // input staging: 612 pos (34 rows x 18 cols) x 32 ci
        for (int t = tid; t < 612 * 8; t += 256) {
            int tpx = t >> 3, ci4 = t & 7;
            int yy = tpx / 18, xx = tpx - yy * 18;
            int iy = y0 - 1 + yy, ix = x0 - 1 + xx;
            uint2 v = make_uint2(0u, 0u);
            if (iy >= 0 && iy < NH && ix >= 0 && ix < NW) {
                if (mode == 0) {
                    size_t pix = ((size_t)(b * NH + iy) * NW + ix);
                    v = *(const uint2*)(g_xh + pix * 32 + ci4 * 4);
                } else {
                    int ci = ch * 32 + ci4 * 4;
                    if (ci < C2C) {
                        size_t pixd = ((size_t)(b * (NH/2) + (iy >> 1)) * (NW/2) + (ix >> 1));
                        v = *(const uint2*)(g_dh + pixd * 128 + ci);
                    } else {
                        size_t pix = ((size_t)(b * NH + iy) * NW + ix);
                        v = *(const uint2*)(g_e1h + pix * 64 + (ci - C2C));
                    }
                }
            }
            *(uint2*)(in_s + tpx * 40 + ci4 * 4) = v;
        }
        {
            const uint4* src = (const uint4*)(wsrc + ch * 23040);
            uint4* dst = (uint4*)w_s;
            for (int t = tid; t < 2880; t += 256) dst[t] = src[t];
        }
        __syncthreads();

        #pragma unroll
        for (int tap = 0; tap < 9; tap++) {
            const int ky = tap / 3, kx = tap - 3 * (tap / 3);
            #pragma unroll
            for (int g = 0; g < 2; g++) {
                // B fragments: 64 co x 16 k (4 ldsm.x4), reused across mt=4
                uint32_t bb[4][4];
                #pragma unroll
                for (int p = 0; p < 4; p++)
                    ldsm4(bb[p][0], bb[p][1], bb[p][2], bb[p][3],
                          w_s + (tap * 64 + 16*p + bRow) * 40 + 16*g + bCol);
                #pragma unroll
                for (int mt = 0; mt < 4; mt++) {
                    uint32_t a0, a1, a2, a3;
                    ldsm4(a0, a1, a2, a3,
                          in_s + ((4*w + mt + ky) * 18 + kx + aRow) * 40 + 16*g + aCol);
                    #pragma unroll
                    for (int p = 0; p < 4; p++) {
                        mma_f16(c[mt][2*p],   a0, a1, a2, a3, bb[p][0], bb[p][1]);
                        mma_f16(c[mt][2*p+1], a0, a1, a2, a3, bb[p][2], bb[p][3]);
                    }
                }
            }
        }
    }

    __half* dst = (mode == 0) ? g_e1h : g_mh;
    #pragma unroll
    for (int mt = 0; mt < 4; mt++) {
        const int y = y0 + 4 * w + mt;
        #pragma unroll
        for (int nt = 0; nt < 8; nt++) {
            const int co = 8 * nt + 2 * tig;
            size_t p1 = ((size_t)(b * NH + y) * NW + x0 + gid) * 64 + co;
            size_t p2 = ((size_t)(b * NH + y) * NW + x0 + gid + 8) * 64 + co;
            *(__half2*)(dst + p1) = __floats2half2_rn(fmaxf(c[mt][nt][0], 0.f),
                                                      fmaxf(c[mt][nt][1], 0.f));
            *(__half2*)(dst + p2) = __floats2half2_rn(fmaxf(c[mt][nt][2], 0.f),
                                                      fmaxf(c[mt][nt][3], 0.f));
        }
    }
}

// ---------------------------------------------------------------------------
// conv2: unchanged (passing R11).
static constexpr int C2_SMEM_BYTES = (1089 * 24 + 9 * 128 * 24) * 2;  // 107568

__global__ __launch_bounds__(512)
void conv2_kernel()
{
    extern __shared__ __half c2sm[];
    __half* in_s = c2sm;
    __half* w_s  = c2sm + 1089 * 24;

    const int tid  = threadIdx.x;
    const int w    = tid >> 5;
    const int lane = tid & 31;
    const int gid  = lane >> 2;
    const int tig  = lane & 3;
    const int aRow = lane & 15;
    const int aCol = (lane >> 4) * 8;
    const int bRow = (lane & 7) + 8 * (lane >> 4);
    const int bCol = 8 * ((lane >> 3) & 1);
    const int coh  = w >> 3;
    const int wy   = w & 7;

    const int x0 = blockIdx.x * 16, y0 = blockIdx.y * 16, b = blockIdx.z;

    float c[2][8][4];
    #pragma unroll
    for (int mt = 0; mt < 2; mt++)
        #pragma unroll
        for (int nt = 0; nt < 8; nt++)
            #pragma unroll
            for (int q = 0; q < 4; q++) c[mt][nt][q] = 0.f;

    for (int ch = 0; ch < 4; ch++) {
        __syncthreads();
        for (int t = tid; t < 1089 * 4; t += 512) {
            int tpx = t >> 2, ci4 = t & 3;
            int yy = tpx / 33, xx = tpx - yy * 33;
            int iy = 2 * y0 + yy, ix = 2 * x0 + xx;
            int pos = yy * 33 + ((xx & 1) ? 17 + (xx >> 1) : (xx >> 1));
            uint2 v = make_uint2(0u, 0u);
            if (iy < NH && ix < NW) {
                size_t pix = ((size_t)(b * NH + iy) * NW + ix);
                v = *(const uint2*)(g_e1h + pix * 64 + ch * 16 + ci4 * 4);
            }
            *(uint2*)(in_s + pos * 24 + ci4 * 4) = v;
        }
        {
            const uint4* src = (const uint4*)(w2h + ch * 27648);
            uint4* dst = (uint4*)w_s;
            for (int t = tid; t < 3456; t += 512) dst[t] = src[t];
        }
        __syncthreads();

        #pragma unroll
        for (int tap = 0; tap < 9; tap++) {
            const int ky = tap / 3, kx = tap - 3 * (tap / 3);
            const int colbase = (kx == 1) ? 17 : (kx >> 1);
            uint32_t a[2][4];
            #pragma unroll
            for (int mt = 0; mt < 2; mt++)
                ldsm4(a[mt][0], a[mt][1], a[mt][2], a[mt][3],
                      in_s + ((2*(2*wy + mt) + ky) * 33 + colbase + aRow) * 24 + aCol);
            #pragma unroll
            for (int p = 0; p < 4; p++) {
                uint32_t bb[4];
                ldsm4(bb[0], bb[1], bb[2], bb[3],
                      w_s + (tap * 128 + coh * 64 + 16*p + bRow) * 24 + bCol);
                mma_f16(c[0][2*p],   a[0][0], a[0][1], a[0][2], a[0][3], bb[0], bb[1]);
                mma_f16(c[1][2*p],   a[1][0], a[1][1], a[1][2], a[1][3], bb[0], bb[1]);
                mma_f16(c[0][2*p+1], a[0][0], a[0][1], a[0][2], a[0][3], bb[2], bb[3]);
                mma_f16(c[1][2*p+1], a[1][0], a[1][1], a[1][2], a[1][3], bb[2], bb[3]);
            }
        }
    }

    #pragma unroll
    for (int mt = 0; mt < 2; mt++) {
        const int y = y0 + 2 * wy + mt;
        #pragma unroll
        for (int nt = 0; nt < 8; nt++) {
            const int co = coh * 64 + 8 * nt + 2 * tig;
            size_t p1 = ((size_t)(b * (NH/2) + y) * (NW/2) + x0 + gid) * 128 + co;
            size_t p2 = ((size_t)(b * (NH/2) + y) * (NW/2) + x0 + gid + 8) * 128 + co;
            *(__half2*)(g_dh + p1) = __floats2half2_rn(fmaxf(c[mt][nt][0], 0.f),
                                                       fmaxf(c[mt][nt][1], 0.f));
            *(__half2*)(g_dh + p2) = __floats2half2_rn(fmaxf(c[mt][nt][2], 0.f),
                                                       fmaxf(c[mt][nt][3], 0.f));
        }
    }
}

// ---------------------------------------------------------------------------
// conv4: unchanged (passing).
static constexpr int C4_SMEM_BYTES = (324 * 24 + 9 * 8 * 24) * 2;  // 19008

__global__ __launch_bounds__(256)
void conv4_kernel(float* __restrict__ out)
{
    extern __shared__ __half c4sm[];
    __half* in_s = c4sm;
    __half* w_s  = c4sm + 324 * 24;

    const int tid  = threadIdx.x;
    const int w    = tid >> 5;
    const int lane = tid & 31;
    const int gid  = lane >> 2;
    const int tig  = lane & 3;

    const int x0 = blockIdx.x * 16, y0 = blockIdx.y * 16, b = blockIdx.z;

    float c[2][4];
    #pragma unroll
    for (int mt = 0; mt < 2; mt++)
        #pragma unroll
        for (int q = 0; q < 4; q++) c[mt][q] = 0.f;

    for (int ch = 0; ch < 4; ch++) {
        __syncthreads();
        for (int t = tid; t < 324 * 4; t += 256) {
            int tpx = t >> 2, ci4 = t & 3;
            int yy = tpx / 18, xx = tpx - yy * 18;
            int iy = y0 - 1 + yy, ix = x0 - 1 + xx;
            uint2 v = make_uint2(0u, 0u);
            if (iy >= 0 && iy < NH && ix >= 0 && ix < NW) {
                size_t pix = ((size_t)(b * NH + iy) * NW + ix);
                v = *(const uint2*)(g_mh + pix * 64 + ch * 16 + ci4 * 4);
            }
            *(uint2*)(in_s + tpx * 24 + ci4 * 4) = v;
        }
        {
            const uint4* src = (const uint4*)(w4h + ch * 1728);
            uint4* dst = (uint4*)w_s;
            for (int t = tid; t < 216; t += 256) dst[t] = src[t];
        }
        __syncthreads();

        #pragma unroll
        for (int tap = 0; tap < 9; tap++) {
            const int ky = tap / 3, kx = tap - 3 * (tap / 3);
            const __half* wb = w_s + (tap * 8 + gid) * 24 + 2 * tig;
            uint32_t b0 = *(const uint32_t*)(wb);
            uint32_t b1 = *(const uint32_t*)(wb + 8);
            #pragma unroll
            for (int mt = 0; mt < 2; mt++) {
                const int yl = 2 * w + mt;
                const __half* base = in_s + ((yl + ky) * 18 + kx) * 24 + 2 * tig;
                uint32_t a0 = *(const uint32_t*)(base + gid * 24);
                uint32_t a1 = *(const uint32_t*)(base + (gid + 8) * 24);
                uint32_t a2 = *(const uint32_t*)(base + gid * 24 + 8);
                uint32_t a3 = *(const uint32_t*)(base + (gid + 8) * 24 + 8);
                mma_f16(c[mt], a0, a1, a2, a3, b0, b1);
            }
        }
    }

    if (tig < 2) {
        #pragma unroll
        for (int mt = 0; mt < 2; mt++) {
            const int y = y0 + 2 * w + mt;
            const int co0 = 2 * tig;
            const int x1 = x0 + gid, x2 = x0 + gid + 8;
            {
                int base = ((b*3 + co0) * NH + y) * NW;
                out[base + x1] = c[mt][0] + g_rgb[base + x1];
                out[base + x2] = c[mt][2] + g_rgb[base + x2];
            }
            if (co0 + 1 < 3) {
                int base = ((b*3 + co0 + 1) * NH + y) * NW;
                out[base + x1] = c[mt][1] + g_rgb[base + x1];
                out[base + x2] = c[mt][3] + g_rgb[base + x2];
            }
        }
    }
}

// ---------------------------------------------------------------------------
extern "C" void kernel_launch(void* const* d_in, const int* in_sizes, int n_in,
                              void* d_out, int out_size)
{
    const float* zbuf = (const float*)d_in[0];
    const float* ray  = (const float*)d_in[1];
    const float* w0 = (const float*)d_in[4];
    const float* b0 = (const float*)d_in[5];
    const float* w1 = (const float*)d_in[6];
    const float* b1 = (const float*)d_in[7];
    const float* w2 = (const float*)d_in[8];
    const float* b2 = (const float*)d_in[9];
    const float* k1 = (const float*)d_in[10];
    const float* k2 = (const float*)d_in[11];
    const float* k3 = (const float*)d_in[12];
    const float* k4 = (const float*)d_in[13];
    float* out = (float*)d_out;

    cudaFuncSetAttribute(mlp_kernel,
                         cudaFuncAttributeMaxDynamicSharedMemorySize, MLP_SMEM_BYTES);
    cudaFuncSetAttribute(conv13_kernel,
                         cudaFuncAttributeMaxDynamicSharedMemorySize, C13_SMEM_BYTES);
    cudaFuncSetAttribute(conv2_kernel,
                         cudaFuncAttributeMaxDynamicSharedMemorySize, C2_SMEM_BYTES);
    cudaFuncSetAttribute(conv4_kernel,
                         cudaFuncAttributeMaxDynamicSharedMemorySize, C4_SMEM_BYTES);

    const int prep_total = W1H_SZ + W2H_SZ + W3H_SZ + W4H_SZ + W1M_SZ + W2M_SZ;
    prep_weights<<<(prep_total + 255) / 256, 256>>>(k1, k2, k3, k4, w1, w2);

    mlp_kernel<<<(NB*NH*NW)/128, 256, MLP_SMEM_BYTES>>>(zbuf, ray, w0, b0, b1, b2);
    conv13_kernel<<<dim3(NW/16, NH/32, NB), 256, C13_SMEM_BYTES>>>(1, 0);
    conv2_kernel <<<dim3(16, 16, NB), 512, C2_SMEM_BYTES>>>();
    conv13_kernel<<<dim3(NW/16, NH/32, NB), 256, C13_SMEM_BYTES>>>(6, 1);
    conv4_kernel <<<dim3(NW/16, NH/16, NB), 256, C4_SMEM_BYTES>>>(out);
}

// round 14
// speedup vs baseline: 6.8124x; 1.3843x over previous
#include <cuda_runtime.h>
#include <cuda_fp16.h>
#include <cstdint>

// Renderer_45612552684068 — round 13: conv13 double-buffered with cp.async
// (stage chunk ch+1 while computing chunk ch). conv2/conv4/MLP unchanged.

static constexpr int NB   = 4;
static constexpr int NH   = 512;
static constexpr int NW   = 512;
static constexpr int HID  = 128;
static constexpr int CIN  = 29;
static constexpr int C1C  = 64;
static constexpr int C2C  = 128;

__device__ __align__(16) float  g_rgb[NB * 3 * NH * NW];
__device__ __align__(16) __half g_xh [NB * NH * NW * 32];
__device__ __align__(16) __half g_e1h[NB * NH * NW * 64];
__device__ __align__(16) __half g_dh [NB * (NH/2) * (NW/2) * 128];
__device__ __align__(16) __half g_mh [NB * NH * NW * 64];

static constexpr int W1H_SZ = 9 * 64 * 40;
static constexpr int W2H_SZ = 4 * 9 * 128 * 24;
static constexpr int W3H_SZ = 6 * 9 * 64 * 40;
static constexpr int W4H_SZ = 4 * 9 * 8 * 24;
__device__ __align__(16) __half w1h[W1H_SZ];
__device__ __align__(16) __half w2h[W2H_SZ];
__device__ __align__(16) __half w3h[W3H_SZ];
__device__ __align__(16) __half w4h[W4H_SZ];
static constexpr int W1M_SZ = 128 * 136;
static constexpr int W2M_SZ = 32 * 136;
__device__ __align__(16) __half w1mh[W1M_SZ];
__device__ __align__(16) __half w2mh[W2M_SZ];

__device__ __forceinline__ void mma_f16(float c[4],
                                        uint32_t a0, uint32_t a1,
                                        uint32_t a2, uint32_t a3,
                                        uint32_t b0, uint32_t b1) {
    asm volatile(
        "mma.sync.aligned.m16n8k16.row.col.f32.f16.f16.f32 "
        "{%0,%1,%2,%3}, {%4,%5,%6,%7}, {%8,%9}, {%0,%1,%2,%3};"
        : "+f"(c[0]), "+f"(c[1]), "+f"(c[2]), "+f"(c[3])
        : "r"(a0), "r"(a1), "r"(a2), "r"(a3), "r"(b0), "r"(b1));
}

__device__ __forceinline__ void ldsm4(uint32_t& r0, uint32_t& r1,
                                      uint32_t& r2, uint32_t& r3,
                                      const __half* p) {
    uint32_t a = (uint32_t)__cvta_generic_to_shared(p);
    asm volatile("ldmatrix.sync.aligned.m8n8.x4.shared.b16 {%0,%1,%2,%3}, [%4];"
                 : "=r"(r0), "=r"(r1), "=r"(r2), "=r"(r3) : "r"(a));
}

__device__ __forceinline__ void cp_async16(__half* smem_dst, const void* gsrc) {
    uint32_t d = (uint32_t)__cvta_generic_to_shared(smem_dst);
    asm volatile("cp.async.cg.shared.global [%0], [%1], 16;" :: "r"(d), "l"(gsrc));
}
__device__ __forceinline__ void cp_async8z(__half* smem_dst, const void* gsrc, bool valid) {
    uint32_t d = (uint32_t)__cvta_generic_to_shared(smem_dst);
    int sz = valid ? 8 : 0;
    asm volatile("cp.async.ca.shared.global [%0], [%1], 8, %2;"
                 :: "r"(d), "l"(gsrc), "r"(sz));
}
__device__ __forceinline__ void cp_commit() {
    asm volatile("cp.async.commit_group;");
}
template <int N>
__device__ __forceinline__ void cp_wait() {
    asm volatile("cp.async.wait_group %0;" :: "n"(N));
}

// ---------------------------------------------------------------------------
__global__ void prep_weights(const float* __restrict__ k1, const float* __restrict__ k2,
                             const float* __restrict__ k3, const float* __restrict__ k4,
                             const float* __restrict__ mw1, const float* __restrict__ mw2)
{
    int i = blockIdx.x * 256 + threadIdx.x;
    if (i < W1H_SZ) {
        int tap = i / 2560, r = i % 2560, co = r / 40, k = r % 40;
        w1h[i] = __float2half(k < CIN ? k1[(co * CIN + k) * 9 + tap] : 0.f);
        return;
    }
    i -= W1H_SZ;
    if (i < W2H_SZ) {
        int c = i / 27648, r = i % 27648;
        int tap = r / 3072, co = (r % 3072) / 24, k = r % 24;
        w2h[i] = __float2half(k < 16 ? k2[(co * C1C + c * 16 + k) * 9 + tap] : 0.f);
        return;
    }
    i -= W2H_SZ;
    if (i < W3H_SZ) {
        int c = i / 23040, r = i % 23040;
        int tap = r / 2560, co = (r % 2560) / 40, k = r % 40;
        w3h[i] = __float2half(k < 32 ? k3[(co * (C2C + C1C) + c * 32 + k) * 9 + tap] : 0.f);
        return;
    }
    i -= W3H_SZ;
    if (i < W4H_SZ) {
        int c = i / 1728, r = i % 1728;
        int tap = r / 192, co = (r % 192) / 24, k = r % 24;
        w4h[i] = __float2half((k < 16 && co < 3) ? k4[(co * C1C + c * 16 + k) * 9 + tap] : 0.f);
        return;
    }
    i -= W4H_SZ;
    if (i < W1M_SZ) {
        int n = i / 136, k = i % 136;
        w1mh[i] = __float2half(k < HID ? mw1[k * HID + n] : 0.f);
        return;
    }
    i -= W1M_SZ;
    if (i < W2M_SZ) {
        int n = i / 136, k = i % 136;
        w2mh[i] = __float2half(k < HID ? mw2[k * 32 + n] : 0.f);
    }
}

// ---------------------------------------------------------------------------
// MLP (unchanged from passing R12)
static constexpr int MLP_H1_OFF  = 0;
static constexpr int MLP_W1_OFF  = 34816;
static constexpr int MLP_W2_OFF  = 69632;
static constexpr int MLP_W0_OFF  = 78336;
static constexpr int MLP_FIN_OFF = 81408;
static constexpr int MLP_Z_OFF   = 85504;
static constexpr int MLP_B0_OFF  = 86016;
static constexpr int MLP_B1_OFF  = 86528;
static constexpr int MLP_B2_OFF  = 87040;
static constexpr int MLP_SMEM_BYTES = 87168;

__global__ __launch_bounds__(256)
void mlp_kernel(const float* __restrict__ zbuf, const float* __restrict__ ray,
                const float* __restrict__ w0, const float* __restrict__ b0,
                const float* __restrict__ b1, const float* __restrict__ b2)
{
    extern __shared__ __align__(16) char msm[];
    __half* sh_h1 = (__half*)(msm + MLP_H1_OFF);
    __half* sh_w1 = (__half*)(msm + MLP_W1_OFF);
    __half* sh_w2 = (__half*)(msm + MLP_W2_OFF);
    float*  sh_w0 = (float*)(msm + MLP_W0_OFF);
    float*  sh_fin= (float*)(msm + MLP_FIN_OFF);
    float*  sh_z  = (float*)(msm + MLP_Z_OFF);
    float*  sh_b0 = (float*)(msm + MLP_B0_OFF);
    float*  sh_b1 = (float*)(msm + MLP_B1_OFF);
    float*  sh_b2 = (float*)(msm + MLP_B2_OFF);

    const int tid   = threadIdx.x;
    const int w     = tid >> 5;
    const int lane  = tid & 31;
    const int gid   = lane >> 2;
    const int tig   = lane & 3;
    const int aRow  = lane & 15;
    const int aCol  = (lane >> 4) * 8;
    const int bRow  = (lane & 7) + 8 * (lane >> 4);
    const int bCol  = 8 * ((lane >> 3) & 1);
    const int pbase = blockIdx.x * 128;

    {
        const uint4* s1 = (const uint4*)w1mh;
        uint4* d1 = (uint4*)sh_w1;
        for (int t = tid; t < W1M_SZ / 8; t += 256) d1[t] = s1[t];
        const uint4* s2 = (const uint4*)w2mh;
        uint4* d2 = (uint4*)sh_w2;
        for (int t = tid; t < W2M_SZ / 8; t += 256) d2[t] = s2[t];
        for (int t = tid; t < 768; t += 256) sh_w0[t] = w0[t];
        if (tid < 128) { sh_b0[tid] = b0[tid]; sh_b1[tid] = b1[tid]; }
        if (tid < 32)  sh_b2[tid] = b2[tid];
    }

    if (tid < 128) {
        int pix = pbase + tid;
        int b = pix >> 18;
        int y = (pix >> 9) & 511;
        int x = pix & 511;
        int pi = (b * NH + y) * NW + x;
        float z = zbuf[pi];
        const float* r = ray + pi * 7;
        float t  = z / r[6];
        float d0 = r[3], d1 = r[4], d2 = r[5];
        sh_fin[tid * 8 + 0] = fmaf(d0, t, r[0]);
        sh_fin[tid * 8 + 1] = fmaf(d1, t, r[1]);
        sh_fin[tid * 8 + 2] = fmaf(d2, t, r[2]);
        sh_fin[tid * 8 + 3] = d0;
        sh_fin[tid * 8 + 4] = d1;
        sh_fin[tid * 8 + 5] = d2;
        sh_z[tid] = z;
    }
    __syncthreads();

    {
        const int p  = tid & 127;
        const int ob = (tid >> 7) * 64;
        float f0 = sh_fin[p*8+0], f1 = sh_fin[p*8+1], f2 = sh_fin[p*8+2];
        float f3 = sh_fin[p*8+3], f4 = sh_fin[p*8+4], f5 = sh_fin[p*8+5];
        #pragma unroll 8
        for (int o = ob; o < ob + 64; o += 2) {
            float a0 = sh_b0[o],     a1 = sh_b0[o+1];
            a0 = fmaf(f0, sh_w0[0*HID + o], a0);  a1 = fmaf(f0, sh_w0[0*HID + o+1], a1);
            a0 = fmaf(f1, sh_w0[1*HID + o], a0);  a1 = fmaf(f1, sh_w0[1*HID + o+1], a1);
            a0 = fmaf(f2, sh_w0[2*HID + o], a0);  a1 = fmaf(f2, sh_w0[2*HID + o+1], a1);
            a0 = fmaf(f3, sh_w0[3*HID + o], a0);  a1 = fmaf(f3, sh_w0[3*HID + o+1], a1);
            a0 = fmaf(f4, sh_w0[4*HID + o], a0);  a1 = fmaf(f4, sh_w0[4*HID + o+1], a1);
            a0 = fmaf(f5, sh_w0[5*HID + o], a0);  a1 = fmaf(f5, sh_w0[5*HID + o+1], a1);
            *(__half2*)(sh_h1 + p * 136 + o) =
                __floats2half2_rn(fmaxf(a0, 0.f), fmaxf(a1, 0.f));
        }
    }
    __syncthreads();

    const int mw = w & 3, nw = w >> 2;
    const int mbase = 32 * mw, nbase = 64 * nw;
    float c1[2][8][4];
    #pragma unroll
    for (int mt = 0; mt < 2; mt++)
        #pragma unroll
        for (int nt = 0; nt < 8; nt++)
            #pragma unroll
            for (int q = 0; q < 4; q++) c1[mt][nt][q] = 0.f;

    #pragma unroll
    for (int ks = 0; ks < 8; ks++) {
        const int kofs = 16 * ks;
        uint32_t a[2][4];
        #pragma unroll
        for (int mt = 0; mt < 2; mt++)
            ldsm4(a[mt][0], a[mt][1], a[mt][2], a[mt][3],
                  sh_h1 + (mbase + 16*mt + aRow) * 136 + kofs + aCol);
        #pragma unroll
        for (int p = 0; p < 4; p++) {
            uint32_t bb[4];
            ldsm4(bb[0], bb[1], bb[2], bb[3],
                  sh_w1 + (nbase + 16*p + bRow) * 136 + kofs + bCol);
            mma_f16(c1[0][2*p],   a[0][0], a[0][1], a[0][2], a[0][3], bb[0], bb[1]);
            mma_f16(c1[1][2*p],   a[1][0], a[1][1], a[1][2], a[1][3], bb[0], bb[1]);
            mma_f16(c1[0][2*p+1], a[0][0], a[0][1], a[0][2], a[0][3], bb[2], bb[3]);
            mma_f16(c1[1][2*p+1], a[1][0], a[1][1], a[1][2], a[1][3], bb[2], bb[3]);
        }
    }
    __syncthreads();

    #pragma unroll
    for (int nt = 0; nt < 8; nt++) {
        const int n0 = nbase + 8*nt + 2*tig;
        float bb0 = sh_b1[n0], bb1 = sh_b1[n0 + 1];
        #pragma unroll
        for (int mt = 0; mt < 2; mt++) {
            int p0 = mbase + 16*mt + gid;
            *(__half2*)(sh_h1 + p0 * 136 + n0) =
                __floats2half2_rn(fmaxf(c1[mt][nt][0] + bb0, 0.f),
                                  fmaxf(c1[mt][nt][1] + bb1, 0.f));
            *(__half2*)(sh_h1 + (p0 + 8) * 136 + n0) =
                __floats2half2_rn(fmaxf(c1[mt][nt][2] + bb0, 0.f),
                                  fmaxf(c1[mt][nt][3] + bb1, 0.f));
        }
    }
    __syncthreads();

    float d2[4][4];
    #pragma unroll
    for (int nt = 0; nt < 4; nt++)
        #pragma unroll
        for (int q = 0; q < 4; q++) d2[nt][q] = 0.f;

    #pragma unroll
    for (int ks = 0; ks < 8; ks++) {
        const int kofs = 16 * ks;
        uint32_t a0, a1, a2, a3;
        ldsm4(a0, a1, a2, a3, sh_h1 + (16*w + aRow) * 136 + kofs + aCol);
        #pragma unroll
        for (int p = 0; p < 2; p++) {
            uint32_t bb[4];
            ldsm4(bb[0], bb[1], bb[2], bb[3],
                  sh_w2 + (16*p + bRow) * 136 + kofs + bCol);
            mma_f16(d2[2*p],   a0, a1, a2, a3, bb[0], bb[1]);
            mma_f16(d2[2*p+1], a0, a1, a2, a3, bb[2], bb[3]);
        }
    }

    #pragma unroll
    for (int nt = 0; nt < 4; nt++) {
        const int n0 = 8*nt + 2*tig;
        const float bb0 = sh_b2[n0], bb1 = sh_b2[n0 + 1];
        #pragma unroll
        for (int rr = 0; rr < 2; rr++) {
            const int p = 16*w + gid + 8*rr;
            const int pix = pbase + p;
            const bool mask = sh_z[p] > 0.f;
            float v0 = mask ? (d2[nt][2*rr]     + bb0) : 1.0f;
            float v1 = mask ? (d2[nt][2*rr + 1] + bb1) : 1.0f;
            float x0 = (n0     < CIN) ? v0 : 0.f;
            float x1 = (n0 + 1 < CIN) ? v1 : 0.f;
            *(__half2*)(g_xh + (size_t)pix * 32 + n0) = __floats2half2_rn(x0, x1);
            if (n0 + 1 >= CIN) {
                int b = pix >> 18;
                int y = (pix >> 9) & 511;
                int x = pix & 511;
                if (n0 >= CIN)
                    g_rgb[((b*3 + (n0 - CIN)) * NH + y) * NW + x] = v0;
                g_rgb[((b*3 + (n0 + 1 - CIN)) * NH + y) * NW + x] = v1;
            }
        }
    }
}

// ---------------------------------------------------------------------------
// conv13: 3x3 SAME stride-1, tile 16x32 px, warp = 4 rows, nt=8.
// Double-buffered cp.async pipeline over chunks.
// Per buffer: in_s 612*40 halves (48960 B) + w_s 9*64*40 (46080 B) = 95040 B.
static constexpr int C13_BUF_HALVES = 612 * 40 + 9 * 64 * 40;   // 47520
static constexpr int C13_SMEM_BYTES = C13_BUF_HALVES * 2 * 2;   // 190080

__global__ __launch_bounds__(256, 1)
void conv13_kernel(int nchunks, int mode)
{
    extern __shared__ __half c13sm[];

    const int tid  = threadIdx.x;
    const int w    = tid >> 5;
    const int lane = tid & 31;
    const int gid  = lane >> 2;
    const int tig  = lane & 3;
    const int aRow = lane & 15;
    const int aCol = (lane >> 4) * 8;
    const int bRow = (lane & 7) + 8 * (lane >> 4);
    const int bCol = 8 * ((lane >> 3) & 1);

    const int x0 = blockIdx.x * 16, y0 = blockIdx.y * 32, b = blockIdx.z;

    const __half* wsrc = (mode == 0) ? w1h : w3h;

    // stage chunk ch into buffer bsel (cp.async, not committed here)
    auto stage = [&](int ch, int bsel) {
        __half* in_s = c13sm + bsel * C13_BUF_HALVES;
        __half* w_s  = in_s + 612 * 40;
        for (int t = tid; t < 612 * 8; t += 256) {
            int tpx = t >> 3, ci4 = t & 7;
            int yy = tpx / 18, xx = tpx - yy * 18;
            int iy = y0 - 1 + yy, ix = x0 - 1 + xx;
            bool valid = (iy >= 0 && iy < NH && ix >= 0 && ix < NW);
            const __half* src;
            if (mode == 0) {
                size_t pix = valid ? ((size_t)(b * NH + iy) * NW + ix) : 0;
                src = g_xh + pix * 32 + ci4 * 4;
            } else {
                int ci = ch * 32 + ci4 * 4;
                if (ci < C2C) {
                    size_t pixd = valid ? ((size_t)(b * (NH/2) + (iy >> 1)) * (NW/2) + (ix >> 1)) : 0;
                    src = g_dh + pixd * 128 + ci;
                } else {
                    size_t pix = valid ? ((size_t)(b * NH + iy) * NW + ix) : 0;
                    src = g_e1h + pix * 64 + (ci - C2C);
                }
            }
            cp_async8z(in_s + tpx * 40 + ci4 * 4, src, valid);
        }
        const __half* wsrc_ch = wsrc + ch * 23040;
        for (int t = tid; t < 2880; t += 256)
            cp_async16(w_s + t * 8, wsrc_ch + t * 8);
    };

    float c[4][8][4];
    #pragma unroll
    for (int mt = 0; mt < 4; mt++)
        #pragma unroll
        for (int nt = 0; nt < 8; nt++)
            #pragma unroll
            for (int q = 0; q < 4; q++) c[mt][nt][q] = 0.f;

    stage(0, 0);
    cp_commit();

    for (int ch = 0; ch < nchunks; ch++) {
        const int bsel = ch & 1;
        if (ch + 1 < nchunks) {
            stage(ch + 1, bsel ^ 1);
            cp_commit();
            cp_wait<1>();
        } else {
            cp_wait<0>();
        }
        __syncthreads();

        const __half* in_s = c13sm + bsel * C13_BUF_HALVES;
        const __half* w_s  = in_s + 612 * 40;

        #pragma unroll
        for (int tap = 0; tap < 9; tap++) {
            const int ky = tap / 3, kx = tap - 3 * (tap / 3);
            #pragma unroll
            for (int g = 0; g < 2; g++) {
                uint32_t bb[4][4];
                #pragma unroll
                for (int p = 0; p < 4; p++)
                    ldsm4(bb[p][0], bb[p][1], bb[p][2], bb[p][3],
                          w_s + (tap * 64 + 16*p + bRow) * 40 + 16*g + bCol);
                #pragma unroll
                for (int mt = 0; mt < 4; mt++) {
                    uint32_t a0, a1, a2, a3;
                    ldsm4(a0, a1, a2, a3,
                          in_s + ((4*w + mt + ky) * 18 + kx + aRow) * 40 + 16*g + aCol);
                    #pragma unroll
                    for (int p = 0; p < 4; p++) {
                        mma_f16(c[mt][2*p],   a0, a1, a2, a3, bb[p][0], bb[p][1]);
                        mma_f16(c[mt][2*p+1], a0, a1, a2, a3, bb[p][2], bb[p][3]);
                    }
                }
            }
        }
        __syncthreads();   // buffer bsel free for reuse at ch+2
    }

    __half* dst = (mode == 0) ? g_e1h : g_mh;
    #pragma unroll
    for (int mt = 0; mt < 4; mt++) {
        const int y = y0 + 4 * w + mt;
        #pragma unroll
        for (int nt = 0; nt < 8; nt++) {
            const int co = 8 * nt + 2 * tig;
            size_t p1 = ((size_t)(b * NH + y) * NW + x0 + gid) * 64 + co;
            size_t p2 = ((size_t)(b * NH + y) * NW + x0 + gid + 8) * 64 + co;
            *(__half2*)(dst + p1) = __floats2half2_rn(fmaxf(c[mt][nt][0], 0.f),
                                                      fmaxf(c[mt][nt][1], 0.f));
            *(__half2*)(dst + p2) = __floats2half2_rn(fmaxf(c[mt][nt][2], 0.f),
                                                      fmaxf(c[mt][nt][3], 0.f));
        }
    }
}

// ---------------------------------------------------------------------------
// conv2: unchanged (passing R12).
static constexpr int C2_SMEM_BYTES = (1089 * 24 + 9 * 128 * 24) * 2;  // 107568

__global__ __launch_bounds__(512)
void conv2_kernel()
{
    extern __shared__ __half c2sm[];
    __half* in_s = c2sm;
    __half* w_s  = c2sm + 1089 * 24;

    const int tid  = threadIdx.x;
    const int w    = tid >> 5;
    const int lane = tid & 31;
    const int gid  = lane >> 2;
    const int tig  = lane & 3;
    const int aRow = lane & 15;
    const int aCol = (lane >> 4) * 8;
    const int bRow = (lane & 7) + 8 * (lane >> 4);
    const int bCol = 8 * ((lane >> 3) & 1);
    const int coh  = w >> 3;
    const int wy   = w & 7;

    const int x0 = blockIdx.x * 16, y0 = blockIdx.y * 16, b = blockIdx.z;

    float c[2][8][4];
    #pragma unroll
    for (int mt = 0; mt < 2; mt++)
        #pragma unroll
        for (int nt = 0; nt < 8; nt++)
            #pragma unroll
            for (int q = 0; q < 4; q++) c[mt][nt][q] = 0.f;

    for (int ch = 0; ch < 4; ch++) {
        __syncthreads();
        for (int t = tid; t < 1089 * 4; t += 512) {
            int tpx = t >> 2, ci4 = t & 3;
            int yy = tpx / 33, xx = tpx - yy * 33;
            int iy = 2 * y0 + yy, ix = 2 * x0 + xx;
            int pos = yy * 33 + ((xx & 1) ? 17 + (xx >> 1) : (xx >> 1));
            uint2 v = make_uint2(0u, 0u);
            if (iy < NH && ix < NW) {
                size_t pix = ((size_t)(b * NH + iy) * NW + ix);
                v = *(const uint2*)(g_e1h + pix * 64 + ch * 16 + ci4 * 4);
            }
            *(uint2*)(in_s + pos * 24 + ci4 * 4) = v;
        }
        {
            const uint4* src = (const uint4*)(w2h + ch * 27648);
            uint4* dst = (uint4*)w_s;
            for (int t = tid; t < 3456; t += 512) dst[t] = src[t];
        }
        __syncthreads();

        #pragma unroll
        for (int tap = 0; tap < 9; tap++) {
            const int ky = tap / 3, kx = tap - 3 * (tap / 3);
            const int colbase = (kx == 1) ? 17 : (kx >> 1);
            uint32_t a[2][4];
            #pragma unroll
            for (int mt = 0; mt < 2; mt++)
                ldsm4(a[mt][0], a[mt][1], a[mt][2], a[mt][3],
                      in_s + ((2*(2*wy + mt) + ky) * 33 + colbase + aRow) * 24 + aCol);
            #pragma unroll
            for (int p = 0; p < 4; p++) {
                uint32_t bb[4];
                ldsm4(bb[0], bb[1], bb[2], bb[3],
                      w_s + (tap * 128 + coh * 64 + 16*p + bRow) * 24 + bCol);
                mma_f16(c[0][2*p],   a[0][0], a[0][1], a[0][2], a[0][3], bb[0], bb[1]);
                mma_f16(c[1][2*p],   a[1][0], a[1][1], a[1][2], a[1][3], bb[0], bb[1]);
                mma_f16(c[0][2*p+1], a[0][0], a[0][1], a[0][2], a[0][3], bb[2], bb[3]);
                mma_f16(c[1][2*p+1], a[1][0], a[1][1], a[1][2], a[1][3], bb[2], bb[3]);
            }
        }
    }

    #pragma unroll
    for (int mt = 0; mt < 2; mt++) {
        const int y = y0 + 2 * wy + mt;
        #pragma unroll
        for (int nt = 0; nt < 8; nt++) {
            const int co = coh * 64 + 8 * nt + 2 * tig;
            size_t p1 = ((size_t)(b * (NH/2) + y) * (NW/2) + x0 + gid) * 128 + co;
            size_t p2 = ((size_t)(b * (NH/2) + y) * (NW/2) + x0 + gid + 8) * 128 + co;
            *(__half2*)(g_dh + p1) = __floats2half2_rn(fmaxf(c[mt][nt][0], 0.f),
                                                       fmaxf(c[mt][nt][1], 0.f));
            *(__half2*)(g_dh + p2) = __floats2half2_rn(fmaxf(c[mt][nt][2], 0.f),
                                                       fmaxf(c[mt][nt][3], 0.f));
        }
    }
}

// ---------------------------------------------------------------------------
// conv4: unchanged (passing).
static constexpr int C4_SMEM_BYTES = (324 * 24 + 9 * 8 * 24) * 2;  // 19008

__global__ __launch_bounds__(256)
void conv4_kernel(float* __restrict__ out)
{
    extern __shared__ __half c4sm[];
    __half* in_s = c4sm;
    __half* w_s  = c4sm + 324 * 24;

    const int tid  = threadIdx.x;
    const int w    = tid >> 5;
    const int lane = tid & 31;
    const int gid  = lane >> 2;
    const int tig  = lane & 3;

    const int x0 = blockIdx.x * 16, y0 = blockIdx.y * 16, b = blockIdx.z;

    float c[2][4];
    #pragma unroll
    for (int mt = 0; mt < 2; mt++)
        #pragma unroll
        for (int q = 0; q < 4; q++) c[mt][q] = 0.f;

    for (int ch = 0; ch < 4; ch++) {
        __syncthreads();
        for (int t = tid; t < 324 * 4; t += 256) {
            int tpx = t >> 2, ci4 = t & 3;
            int yy = tpx / 18, xx = tpx - yy * 18;
            int iy = y0 - 1 + yy, ix = x0 - 1 + xx;
            uint2 v = make_uint2(0u, 0u);
            if (iy >= 0 && iy < NH && ix >= 0 && ix < NW) {
                size_t pix = ((size_t)(b * NH + iy) * NW + ix);
                v = *(const uint2*)(g_mh + pix * 64 + ch * 16 + ci4 * 4);
            }
            *(uint2*)(in_s + tpx * 24 + ci4 * 4) = v;
        }
        {
            const uint4* src = (const uint4*)(w4h + ch * 1728);
            uint4* dst = (uint4*)w_s;
            for (int t = tid; t < 216; t += 256) dst[t] = src[t];
        }
        __syncthreads();

        #pragma unroll
        for (int tap = 0; tap < 9; tap++) {
            const int ky = tap / 3, kx = tap - 3 * (tap / 3);
            const __half* wb = w_s + (tap * 8 + gid) * 24 + 2 * tig;
            uint32_t b0 = *(const uint32_t*)(wb);
            uint32_t b1 = *(const uint32_t*)(wb + 8);
            #pragma unroll
            for (int mt = 0; mt < 2; mt++) {
                const int yl = 2 * w + mt;
                const __half* base = in_s + ((yl + ky) * 18 + kx) * 24 + 2 * tig;
                uint32_t a0 = *(const uint32_t*)(base + gid * 24);
                uint32_t a1 = *(const uint32_t*)(base + (gid + 8) * 24);
                uint32_t a2 = *(const uint32_t*)(base + gid * 24 + 8);
                uint32_t a3 = *(const uint32_t*)(base + (gid + 8) * 24 + 8);
                mma_f16(c[mt], a0, a1, a2, a3, b0, b1);
            }
        }
    }

    if (tig < 2) {
        #pragma unroll
        for (int mt = 0; mt < 2; mt++) {
            const int y = y0 + 2 * w + mt;
            const int co0 = 2 * tig;
            const int x1 = x0 + gid, x2 = x0 + gid + 8;
            {
                int base = ((b*3 + co0) * NH + y) * NW;
                out[base + x1] = c[mt][0] + g_rgb[base + x1];
                out[base + x2] = c[mt][2] + g_rgb[base + x2];
            }
            if (co0 + 1 < 3) {
                int base = ((b*3 + co0 + 1) * NH + y) * NW;
                out[base + x1] = c[mt][1] + g_rgb[base + x1];
                out[base + x2] = c[mt][3] + g_rgb[base + x2];
            }
        }
    }
}

// ---------------------------------------------------------------------------
extern "C" void kernel_launch(void* const* d_in, const int* in_sizes, int n_in,
                              void* d_out, int out_size)
{
    const float* zbuf = (const float*)d_in[0];
    const float* ray  = (const float*)d_in[1];
    const float* w0 = (const float*)d_in[4];
    const float* b0 = (const float*)d_in[5];
    const float* w1 = (const float*)d_in[6];
    const float* b1 = (const float*)d_in[7];
    const float* w2 = (const float*)d_in[8];
    const float* b2 = (const float*)d_in[9];
    const float* k1 = (const float*)d_in[10];
    const float* k2 = (const float*)d_in[11];
    const float* k3 = (const float*)d_in[12];
    const float* k4 = (const float*)d_in[13];
    float* out = (float*)d_out;

    cudaFuncSetAttribute(mlp_kernel,
                         cudaFuncAttributeMaxDynamicSharedMemorySize, MLP_SMEM_BYTES);
    cudaFuncSetAttribute(conv13_kernel,
                         cudaFuncAttributeMaxDynamicSharedMemorySize, C13_SMEM_BYTES);
    cudaFuncSetAttribute(conv2_kernel,
                         cudaFuncAttributeMaxDynamicSharedMemorySize, C2_SMEM_BYTES);
    cudaFuncSetAttribute(conv4_kernel,
                         cudaFuncAttributeMaxDynamicSharedMemorySize, C4_SMEM_BYTES);

    const int prep_total = W1H_SZ + W2H_SZ + W3H_SZ + W4H_SZ + W1M_SZ + W2M_SZ;
    prep_weights<<<(prep_total + 255) / 256, 256>>>(k1, k2, k3, k4, w1, w2);

    mlp_kernel<<<(NB*NH*NW)/128, 256, MLP_SMEM_BYTES>>>(zbuf, ray, w0, b0, b1, b2);
    conv13_kernel<<<dim3(NW/16, NH/32, NB), 256, C13_SMEM_BYTES>>>(1, 0);
    conv2_kernel <<<dim3(16, 16, NB), 512, C2_SMEM_BYTES>>>();
    conv13_kernel<<<dim3(NW/16, NH/32, NB), 256, C13_SMEM_BYTES>>>(6, 1);
    conv4_kernel <<<dim3(NW/16, NH/16, NB), 256, C4_SMEM_BYTES>>>(out);
}

// round 15
// speedup vs baseline: 6.9787x; 1.0244x over previous
#include <cuda_runtime.h>
#include <cuda_fp16.h>
#include <cstdint>

// Renderer_45612552684068 — round 14: conv2 + conv4 double-buffered with
// cp.async (same transform that won -28% on conv13 in R13). conv13/MLP
// unchanged from passing R13.

static constexpr int NB   = 4;
static constexpr int NH   = 512;
static constexpr int NW   = 512;
static constexpr int HID  = 128;
static constexpr int CIN  = 29;
static constexpr int C1C  = 64;
static constexpr int C2C  = 128;

__device__ __align__(16) float  g_rgb[NB * 3 * NH * NW];
__device__ __align__(16) __half g_xh [NB * NH * NW * 32];
__device__ __align__(16) __half g_e1h[NB * NH * NW * 64];
__device__ __align__(16) __half g_dh [NB * (NH/2) * (NW/2) * 128];
__device__ __align__(16) __half g_mh [NB * NH * NW * 64];

static constexpr int W1H_SZ = 9 * 64 * 40;
static constexpr int W2H_SZ = 4 * 9 * 128 * 24;
static constexpr int W3H_SZ = 6 * 9 * 64 * 40;
static constexpr int W4H_SZ = 4 * 9 * 8 * 24;
__device__ __align__(16) __half w1h[W1H_SZ];
__device__ __align__(16) __half w2h[W2H_SZ];
__device__ __align__(16) __half w3h[W3H_SZ];
__device__ __align__(16) __half w4h[W4H_SZ];
static constexpr int W1M_SZ = 128 * 136;
static constexpr int W2M_SZ = 32 * 136;
__device__ __align__(16) __half w1mh[W1M_SZ];
__device__ __align__(16) __half w2mh[W2M_SZ];

__device__ __forceinline__ void mma_f16(float c[4],
                                        uint32_t a0, uint32_t a1,
                                        uint32_t a2, uint32_t a3,
                                        uint32_t b0, uint32_t b1) {
    asm volatile(
        "mma.sync.aligned.m16n8k16.row.col.f32.f16.f16.f32 "
        "{%0,%1,%2,%3}, {%4,%5,%6,%7}, {%8,%9}, {%0,%1,%2,%3};"
        : "+f"(c[0]), "+f"(c[1]), "+f"(c[2]), "+f"(c[3])
        : "r"(a0), "r"(a1), "r"(a2), "r"(a3), "r"(b0), "r"(b1));
}

__device__ __forceinline__ void ldsm4(uint32_t& r0, uint32_t& r1,
                                      uint32_t& r2, uint32_t& r3,
                                      const __half* p) {
    uint32_t a = (uint32_t)__cvta_generic_to_shared(p);
    asm volatile("ldmatrix.sync.aligned.m8n8.x4.shared.b16 {%0,%1,%2,%3}, [%4];"
                 : "=r"(r0), "=r"(r1), "=r"(r2), "=r"(r3) : "r"(a));
}

__device__ __forceinline__ void cp_async16(__half* smem_dst, const void* gsrc) {
    uint32_t d = (uint32_t)__cvta_generic_to_shared(smem_dst);
    asm volatile("cp.async.cg.shared.global [%0], [%1], 16;" :: "r"(d), "l"(gsrc));
}
__device__ __forceinline__ void cp_async8z(__half* smem_dst, const void* gsrc, bool valid) {
    uint32_t d = (uint32_t)__cvta_generic_to_shared(smem_dst);
    int sz = valid ? 8 : 0;
    asm volatile("cp.async.ca.shared.global [%0], [%1], 8, %2;"
                 :: "r"(d), "l"(gsrc), "r"(sz));
}
__device__ __forceinline__ void cp_commit() {
    asm volatile("cp.async.commit_group;");
}
template <int N>
__device__ __forceinline__ void cp_wait() {
    asm volatile("cp.async.wait_group %0;" :: "n"(N));
}

// ---------------------------------------------------------------------------
__global__ void prep_weights(const float* __restrict__ k1, const float* __restrict__ k2,
                             const float* __restrict__ k3, const float* __restrict__ k4,
                             const float* __restrict__ mw1, const float* __restrict__ mw2)
{
    int i = blockIdx.x * 256 + threadIdx.x;
    if (i < W1H_SZ) {
        int tap = i / 2560, r = i % 2560, co = r / 40, k = r % 40;
        w1h[i] = __float2half(k < CIN ? k1[(co * CIN + k) * 9 + tap] : 0.f);
        return;
    }
    i -= W1H_SZ;
    if (i < W2H_SZ) {
        int c = i / 27648, r = i % 27648;
        int tap = r / 3072, co = (r % 3072) / 24, k = r % 24;
        w2h[i] = __float2half(k < 16 ? k2[(co * C1C + c * 16 + k) * 9 + tap] : 0.f);
        return;
    }
    i -= W2H_SZ;
    if (i < W3H_SZ) {
        int c = i / 23040, r = i % 23040;
        int tap = r / 2560, co = (r % 2560) / 40, k = r % 40;
        w3h[i] = __float2half(k < 32 ? k3[(co * (C2C + C1C) + c * 32 + k) * 9 + tap] : 0.f);
        return;
    }
    i -= W3H_SZ;
    if (i < W4H_SZ) {
        int c = i / 1728, r = i % 1728;
        int tap = r / 192, co = (r % 192) / 24, k = r % 24;
        w4h[i] = __float2half((k < 16 && co < 3) ? k4[(co * C1C + c * 16 + k) * 9 + tap] : 0.f);
        return;
    }
    i -= W4H_SZ;
    if (i < W1M_SZ) {
        int n = i / 136, k = i % 136;
        w1mh[i] = __float2half(k < HID ? mw1[k * HID + n] : 0.f);
        return;
    }
    i -= W1M_SZ;
    if (i < W2M_SZ) {
        int n = i / 136, k = i % 136;
        w2mh[i] = __float2half(k < HID ? mw2[k * 32 + n] : 0.f);
    }
}

// ---------------------------------------------------------------------------
// MLP (unchanged from passing R13)
static constexpr int MLP_H1_OFF  = 0;
static constexpr int MLP_W1_OFF  = 34816;
static constexpr int MLP_W2_OFF  = 69632;
static constexpr int MLP_W0_OFF  = 78336;
static constexpr int MLP_FIN_OFF = 81408;
static constexpr int MLP_Z_OFF   = 85504;
static constexpr int MLP_B0_OFF  = 86016;
static constexpr int MLP_B1_OFF  = 86528;
static constexpr int MLP_B2_OFF  = 87040;
static constexpr int MLP_SMEM_BYTES = 87168;

__global__ __launch_bounds__(256)
void mlp_kernel(const float* __restrict__ zbuf, const float* __restrict__ ray,
                const float* __restrict__ w0, const float* __restrict__ b0,
                const float* __restrict__ b1, const float* __restrict__ b2)
{
    extern __shared__ __align__(16) char msm[];
    __half* sh_h1 = (__half*)(msm + MLP_H1_OFF);
    __half* sh_w1 = (__half*)(msm + MLP_W1_OFF);
    __half* sh_w2 = (__half*)(msm + MLP_W2_OFF);
    float*  sh_w0 = (float*)(msm + MLP_W0_OFF);
    float*  sh_fin= (float*)(msm + MLP_FIN_OFF);
    float*  sh_z  = (float*)(msm + MLP_Z_OFF);
    float*  sh_b0 = (float*)(msm + MLP_B0_OFF);
    float*  sh_b1 = (float*)(msm + MLP_B1_OFF);
    float*  sh_b2 = (float*)(msm + MLP_B2_OFF);

    const int tid   = threadIdx.x;
    const int w     = tid >> 5;
    const int lane  = tid & 31;
    const int gid   = lane >> 2;
    const int tig   = lane & 3;
    const int aRow  = lane & 15;
    const int aCol  = (lane >> 4) * 8;
    const int bRow  = (lane & 7) + 8 * (lane >> 4);
    const int bCol  = 8 * ((lane >> 3) & 1);
    const int pbase = blockIdx.x * 128;

    {
        const uint4* s1 = (const uint4*)w1mh;
        uint4* d1 = (uint4*)sh_w1;
        for (int t = tid; t < W1M_SZ / 8; t += 256) d1[t] = s1[t];
        const uint4* s2 = (const uint4*)w2mh;
        uint4* d2 = (uint4*)sh_w2;
        for (int t = tid; t < W2M_SZ / 8; t += 256) d2[t] = s2[t];
        for (int t = tid; t < 768; t += 256) sh_w0[t] = w0[t];
        if (tid < 128) { sh_b0[tid] = b0[tid]; sh_b1[tid] = b1[tid]; }
        if (tid < 32)  sh_b2[tid] = b2[tid];
    }

    if (tid < 128) {
        int pix = pbase + tid;
        int b = pix >> 18;
        int y = (pix >> 9) & 511;
        int x = pix & 511;
        int pi = (b * NH + y) * NW + x;
        float z = zbuf[pi];
        const float* r = ray + pi * 7;
        float t  = z / r[6];
        float d0 = r[3], d1 = r[4], d2 = r[5];
        sh_fin[tid * 8 + 0] = fmaf(d0, t, r[0]);
        sh_fin[tid * 8 + 1] = fmaf(d1, t, r[1]);
        sh_fin[tid * 8 + 2] = fmaf(d2, t, r[2]);
        sh_fin[tid * 8 + 3] = d0;
        sh_fin[tid * 8 + 4] = d1;
        sh_fin[tid * 8 + 5] = d2;
        sh_z[tid] = z;
    }
    __syncthreads();

    {
        const int p  = tid & 127;
        const int ob = (tid >> 7) * 64;
        float f0 = sh_fin[p*8+0], f1 = sh_fin[p*8+1], f2 = sh_fin[p*8+2];
        float f3 = sh_fin[p*8+3], f4 = sh_fin[p*8+4], f5 = sh_fin[p*8+5];
        #pragma unroll 8
        for (int o = ob; o < ob + 64; o += 2) {
            float a0 = sh_b0[o],     a1 = sh_b0[o+1];
            a0 = fmaf(f0, sh_w0[0*HID + o], a0);  a1 = fmaf(f0, sh_w0[0*HID + o+1], a1);
            a0 = fmaf(f1, sh_w0[1*HID + o], a0);  a1 = fmaf(f1, sh_w0[1*HID + o+1], a1);
            a0 = fmaf(f2, sh_w0[2*HID + o], a0);  a1 = fmaf(f2, sh_w0[2*HID + o+1], a1);
            a0 = fmaf(f3, sh_w0[3*HID + o], a0);  a1 = fmaf(f3, sh_w0[3*HID + o+1], a1);
            a0 = fmaf(f4, sh_w0[4*HID + o], a0);  a1 = fmaf(f4, sh_w0[4*HID + o+1], a1);
            a0 = fmaf(f5, sh_w0[5*HID + o], a0);  a1 = fmaf(f5, sh_w0[5*HID + o+1], a1);
            *(__half2*)(sh_h1 + p * 136 + o) =
                __floats2half2_rn(fmaxf(a0, 0.f), fmaxf(a1, 0.f));
        }
    }
    __syncthreads();

    const int mw = w & 3, nw = w >> 2;
    const int mbase = 32 * mw, nbase = 64 * nw;
    float c1[2][8][4];
    #pragma unroll
    for (int mt = 0; mt < 2; mt++)
        #pragma unroll
        for (int nt = 0; nt < 8; nt++)
            #pragma unroll
            for (int q = 0; q < 4; q++) c1[mt][nt][q] = 0.f;

    #pragma unroll
    for (int ks = 0; ks < 8; ks++) {
        const int kofs = 16 * ks;
        uint32_t a[2][4];
        #pragma unroll
        for (int mt = 0; mt < 2; mt++)
            ldsm4(a[mt][0], a[mt][1], a[mt][2], a[mt][3],
                  sh_h1 + (mbase + 16*mt + aRow) * 136 + kofs + aCol);
        #pragma unroll
        for (int p = 0; p < 4; p++) {
            uint32_t bb[4];
            ldsm4(bb[0], bb[1], bb[2], bb[3],
                  sh_w1 + (nbase + 16*p + bRow) * 136 + kofs + bCol);
            mma_f16(c1[0][2*p],   a[0][0], a[0][1], a[0][2], a[0][3], bb[0], bb[1]);
            mma_f16(c1[1][2*p],   a[1][0], a[1][1], a[1][2], a[1][3], bb[0], bb[1]);
            mma_f16(c1[0][2*p+1], a[0][0], a[0][1], a[0][2], a[0][3], bb[2], bb[3]);
            mma_f16(c1[1][2*p+1], a[1][0], a[1][1], a[1][2], a[1][3], bb[2], bb[3]);
        }
    }
    __syncthreads();

    #pragma unroll
    for (int nt = 0; nt < 8; nt++) {
        const int n0 = nbase + 8*nt + 2*tig;
        float bb0 = sh_b1[n0], bb1 = sh_b1[n0 + 1];
        #pragma unroll
        for (int mt = 0; mt < 2; mt++) {
            int p0 = mbase + 16*mt + gid;
            *(__half2*)(sh_h1 + p0 * 136 + n0) =
                __floats2half2_rn(fmaxf(c1[mt][nt][0] + bb0, 0.f),
                                  fmaxf(c1[mt][nt][1] + bb1, 0.f));
            *(__half2*)(sh_h1 + (p0 + 8) * 136 + n0) =
                __floats2half2_rn(fmaxf(c1[mt][nt][2] + bb0, 0.f),
                                  fmaxf(c1[mt][nt][3] + bb1, 0.f));
        }
    }
    __syncthreads();

    float d2[4][4];
    #pragma unroll
    for (int nt = 0; nt < 4; nt++)
        #pragma unroll
        for (int q = 0; q < 4; q++) d2[nt][q] = 0.f;

    #pragma unroll
    for (int ks = 0; ks < 8; ks++) {
        const int kofs = 16 * ks;
        uint32_t a0, a1, a2, a3;
        ldsm4(a0, a1, a2, a3, sh_h1 + (16*w + aRow) * 136 + kofs + aCol);
        #pragma unroll
        for (int p = 0; p < 2; p++) {
            uint32_t bb[4];
            ldsm4(bb[0], bb[1], bb[2], bb[3],
                  sh_w2 + (16*p + bRow) * 136 + kofs + bCol);
            mma_f16(d2[2*p],   a0, a1, a2, a3, bb[0], bb[1]);
            mma_f16(d2[2*p+1], a0, a1, a2, a3, bb[2], bb[3]);
        }
    }

    #pragma unroll
    for (int nt = 0; nt < 4; nt++) {
        const int n0 = 8*nt + 2*tig;
        const float bb0 = sh_b2[n0], bb1 = sh_b2[n0 + 1];
        #pragma unroll
        for (int rr = 0; rr < 2; rr++) {
            const int p = 16*w + gid + 8*rr;
            const int pix = pbase + p;
            const bool mask = sh_z[p] > 0.f;
            float v0 = mask ? (d2[nt][2*rr]     + bb0) : 1.0f;
            float v1 = mask ? (d2[nt][2*rr + 1] + bb1) : 1.0f;
            float x0 = (n0     < CIN) ? v0 : 0.f;
            float x1 = (n0 + 1 < CIN) ? v1 : 0.f;
            *(__half2*)(g_xh + (size_t)pix * 32 + n0) = __floats2half2_rn(x0, x1);
            if (n0 + 1 >= CIN) {
                int b = pix >> 18;
                int y = (pix >> 9) & 511;
                int x = pix & 511;
                if (n0 >= CIN)
                    g_rgb[((b*3 + (n0 - CIN)) * NH + y) * NW + x] = v0;
                g_rgb[((b*3 + (n0 + 1 - CIN)) * NH + y) * NW + x] = v1;
            }
        }
    }
}

// ---------------------------------------------------------------------------
// conv13: double-buffered cp.async (unchanged from passing R13).
static constexpr int C13_BUF_HALVES = 612 * 40 + 9 * 64 * 40;   // 47520
static constexpr int C13_SMEM_BYTES = C13_BUF_HALVES * 2 * 2;   // 190080

__global__ __launch_bounds__(256, 1)
void conv13_kernel(int nchunks, int mode)
{
    extern __shared__ __half c13sm[];

    const int tid  = threadIdx.x;
    const int w    = tid >> 5;
    const int lane = tid & 31;
    const int gid  = lane >> 2;
    const int tig  = lane & 3;
    const int aRow = lane & 15;
    const int aCol = (lane >> 4) * 8;
    const int bRow = (lane & 7) + 8 * (lane >> 4);
    const int bCol = 8 * ((lane >> 3) & 1);

    const int x0 = blockIdx.x * 16, y0 = blockIdx.y * 32, b = blockIdx.z;

    const __half* wsrc = (mode == 0) ? w1h : w3h;

    auto stage = [&](int ch, int bsel) {
        __half* in_s = c13sm + bsel * C13_BUF_HALVES;
        __half* w_s  = in_s + 612 * 40;
        for (int t = tid; t < 612 * 8; t += 256) {
            int tpx = t >> 3, ci4 = t & 7;
            int yy = tpx / 18, xx = tpx - yy * 18;
            int iy = y0 - 1 + yy, ix = x0 - 1 + xx;
            bool valid = (iy >= 0 && iy < NH && ix >= 0 && ix < NW);
            const __half* src;
            if (mode == 0) {
                size_t pix = valid ? ((size_t)(b * NH + iy) * NW + ix) : 0;
                src = g_xh + pix * 32 + ci4 * 4;
            } else {
                int ci = ch * 32 + ci4 * 4;
                if (ci < C2C) {
                    size_t pixd = valid ? ((size_t)(b * (NH/2) + (iy >> 1)) * (NW/2) + (ix >> 1)) : 0;
                    src = g_dh + pixd * 128 + ci;
                } else {
                    size_t pix = valid ? ((size_t)(b * NH + iy) * NW + ix) : 0;
                    src = g_e1h + pix * 64 + (ci - C2C);
                }
            }
            cp_async8z(in_s + tpx * 40 + ci4 * 4, src, valid);
        }
        const __half* wsrc_ch = wsrc + ch * 23040;
        for (int t = tid; t < 2880; t += 256)
            cp_async16(w_s + t * 8, wsrc_ch + t * 8);
    };

    float c[4][8][4];
    #pragma unroll
    for (int mt = 0; mt < 4; mt++)
        #pragma unroll
        for (int nt = 0; nt < 8; nt++)
            #pragma unroll
            for (int q = 0; q < 4; q++) c[mt][nt][q] = 0.f;

    stage(0, 0);
    cp_commit();

    for (int ch = 0; ch < nchunks; ch++) {
        const int bsel = ch & 1;
        if (ch + 1 < nchunks) {
            stage(ch + 1, bsel ^ 1);
            cp_commit();
            cp_wait<1>();
        } else {
            cp_wait<0>();
        }
        __syncthreads();

        const __half* in_s = c13sm + bsel * C13_BUF_HALVES;
        const __half* w_s  = in_s + 612 * 40;

        #pragma unroll
        for (int tap = 0; tap < 9; tap++) {
            const int ky = tap / 3, kx = tap - 3 * (tap / 3);
            #pragma unroll
            for (int g = 0; g < 2; g++) {
                uint32_t bb[4][4];
                #pragma unroll
                for (int p = 0; p < 4; p++)
                    ldsm4(bb[p][0], bb[p][1], bb[p][2], bb[p][3],
                          w_s + (tap * 64 + 16*p + bRow) * 40 + 16*g + bCol);
                #pragma unroll
                for (int mt = 0; mt < 4; mt++) {
                    uint32_t a0, a1, a2, a3;
                    ldsm4(a0, a1, a2, a3,
                          in_s + ((4*w + mt + ky) * 18 + kx + aRow) * 40 + 16*g + aCol);
                    #pragma unroll
                    for (int p = 0; p < 4; p++) {
                        mma_f16(c[mt][2*p],   a0, a1, a2, a3, bb[p][0], bb[p][1]);
                        mma_f16(c[mt][2*p+1], a0, a1, a2, a3, bb[p][2], bb[p][3]);
                    }
                }
            }
        }
        __syncthreads();
    }

    __half* dst = (mode == 0) ? g_e1h : g_mh;
    #pragma unroll
    for (int mt = 0; mt < 4; mt++) {
        const int y = y0 + 4 * w + mt;
        #pragma unroll
        for (int nt = 0; nt < 8; nt++) {
            const int co = 8 * nt + 2 * tig;
            size_t p1 = ((size_t)(b * NH + y) * NW + x0 + gid) * 64 + co;
            size_t p2 = ((size_t)(b * NH + y) * NW + x0 + gid + 8) * 64 + co;
            *(__half2*)(dst + p1) = __floats2half2_rn(fmaxf(c[mt][nt][0], 0.f),
                                                      fmaxf(c[mt][nt][1], 0.f));
            *(__half2*)(dst + p2) = __floats2half2_rn(fmaxf(c[mt][nt][2], 0.f),
                                                      fmaxf(c[mt][nt][3], 0.f));
        }
    }
}

// ---------------------------------------------------------------------------
// conv2: 64->128 stride-2 (pad_lo=0), parity-plane smem — now double-buffered
// cp.async over the 4 ci-chunks.
static constexpr int C2_BUF_HALVES = 1089 * 24 + 9 * 128 * 24;  // 53784
static constexpr int C2_SMEM_BYTES = C2_BUF_HALVES * 2 * 2;     // 215136

__global__ __launch_bounds__(512, 1)
void conv2_kernel()
{
    extern __shared__ __half c2sm[];

    const int tid  = threadIdx.x;
    const int w    = tid >> 5;
    const int lane = tid & 31;
    const int gid  = lane >> 2;
    const int tig  = lane & 3;
    const int aRow = lane & 15;
    const int aCol = (lane >> 4) * 8;
    const int bRow = (lane & 7) + 8 * (lane >> 4);
    const int bCol = 8 * ((lane >> 3) & 1);
    const int coh  = w >> 3;
    const int wy   = w & 7;

    const int x0 = blockIdx.x * 16, y0 = blockIdx.y * 16, b = blockIdx.z;

    auto stage = [&](int ch, int bsel) {
        __half* in_s = c2sm + bsel * C2_BUF_HALVES;
        __half* w_s  = in_s + 1089 * 24;
        for (int t = tid; t < 1089 * 4; t += 512) {
            int tpx = t >> 2, ci4 = t & 3;
            int yy = tpx / 33, xx = tpx - yy * 33;
            int iy = 2 * y0 + yy, ix = 2 * x0 + xx;     // pad_lo = 0
            int pos = yy * 33 + ((xx & 1) ? 17 + (xx >> 1) : (xx >> 1));
            bool valid = (iy < NH && ix < NW);
            size_t pix = valid ? ((size_t)(b * NH + iy) * NW + ix) : 0;
            const __half* src = g_e1h + pix * 64 + ch * 16 + ci4 * 4;
            cp_async8z(in_s + pos * 24 + ci4 * 4, src, valid);
        }
        const __half* wsrc_ch = w2h + ch * 27648;
        for (int t = tid; t < 3456; t += 512)
            cp_async16(w_s + t * 8, wsrc_ch + t * 8);
    };

    float c[2][8][4];
    #pragma unroll
    for (int mt = 0; mt < 2; mt++)
        #pragma unroll
        for (int nt = 0; nt < 8; nt++)
            #pragma unroll
            for (int q = 0; q < 4; q++) c[mt][nt][q] = 0.f;

    stage(0, 0);
    cp_commit();

    for (int ch = 0; ch < 4; ch++) {
        const int bsel = ch & 1;
        if (ch + 1 < 4) {
            stage(ch + 1, bsel ^ 1);
            cp_commit();
            cp_wait<1>();
        } else {
            cp_wait<0>();
        }
        __syncthreads();

        const __half* in_s = c2sm + bsel * C2_BUF_HALVES;
        const __half* w_s  = in_s + 1089 * 24;

        #pragma unroll
        for (int tap = 0; tap < 9; tap++) {
            const int ky = tap / 3, kx = tap - 3 * (tap / 3);
            const int colbase = (kx == 1) ? 17 : (kx >> 1);
            uint32_t a[2][4];
            #pragma unroll
            for (int mt = 0; mt < 2; mt++)
                ldsm4(a[mt][0], a[mt][1], a[mt][2], a[mt][3],
                      in_s + ((2*(2*wy + mt) + ky) * 33 + colbase + aRow) * 24 + aCol);
            #pragma unroll
            for (int p = 0; p < 4; p++) {
                uint32_t bb[4];
                ldsm4(bb[0], bb[1], bb[2], bb[3],
                      w_s + (tap * 128 + coh * 64 + 16*p + bRow) * 24 + bCol);
                mma_f16(c[0][2*p],   a[0][0], a[0][1], a[0][2], a[0][3], bb[0], bb[1]);
                mma_f16(c[1][2*p],   a[1][0], a[1][1], a[1][2], a[1][3], bb[0], bb[1]);
                mma_f16(c[0][2*p+1], a[0][0], a[0][1], a[0][2], a[0][3], bb[2], bb[3]);
                mma_f16(c[1][2*p+1], a[1][0], a[1][1], a[1][2], a[1][3], bb[2], bb[3]);
            }
        }
        __syncthreads();
    }

    #pragma unroll
    for (int mt = 0; mt < 2; mt++) {
        const int y = y0 + 2 * wy + mt;
        #pragma unroll
        for (int nt = 0; nt < 8; nt++) {
            const int co = coh * 64 + 8 * nt + 2 * tig;
            size_t p1 = ((size_t)(b * (NH/2) + y) * (NW/2) + x0 + gid) * 128 + co;
            size_t p2 = ((size_t)(b * (NH/2) + y) * (NW/2) + x0 + gid + 8) * 128 + co;
            *(__half2*)(g_dh + p1) = __floats2half2_rn(fmaxf(c[mt][nt][0], 0.f),
                                                       fmaxf(c[mt][nt][1], 0.f));
            *(__half2*)(g_dh + p2) = __floats2half2_rn(fmaxf(c[mt][nt][2], 0.f),
                                                       fmaxf(c[mt][nt][3], 0.f));
        }
    }
}

// ---------------------------------------------------------------------------
// conv4: 64->3 + rgb residual — double-buffered cp.async.
static constexpr int C4_BUF_HALVES = 324 * 24 + 9 * 8 * 24;     // 9504
static constexpr int C4_SMEM_BYTES = C4_BUF_HALVES * 2 * 2;     // 38016

__global__ __launch_bounds__(256)
void conv4_kernel(float* __restrict__ out)
{
    extern __shared__ __half c4sm[];

    const int tid  = threadIdx.x;
    const int w    = tid >> 5;
    const int lane = tid & 31;
    const int gid  = lane >> 2;
    const int tig  = lane & 3;

    const int x0 = blockIdx.x * 16, y0 = blockIdx.y * 16, b = blockIdx.z;

    auto stage = [&](int ch, int bsel) {
        __half* in_s = c4sm + bsel * C4_BUF_HALVES;
        __half* w_s  = in_s + 324 * 24;
        for (int t = tid; t < 324 * 4; t += 256) {
            int tpx = t >> 2, ci4 = t & 3;
            int yy = tpx / 18, xx = tpx - yy * 18;
            int iy = y0 - 1 + yy, ix = x0 - 1 + xx;
            bool valid = (iy >= 0 && iy < NH && ix >= 0 && ix < NW);
            size_t pix = valid ? ((size_t)(b * NH + iy) * NW + ix) : 0;
            const __half* src = g_mh + pix * 64 + ch * 16 + ci4 * 4;
            cp_async8z(in_s + tpx * 24 + ci4 * 4, src, valid);
        }
        const __half* wsrc_ch = w4h + ch * 1728;
        for (int t = tid; t < 216; t += 256)
            cp_async16(w_s + t * 8, wsrc_ch + t * 8);
    };

    float c[2][4];
    #pragma unroll
    for (int mt = 0; mt < 2; mt++)
        #pragma unroll
        for (int q = 0; q < 4; q++) c[mt][q] = 0.f;

    stage(0, 0);
    cp_commit();

    for (int ch = 0; ch < 4; ch++) {
        const int bsel = ch & 1;
        if (ch + 1 < 4) {
            stage(ch + 1, bsel ^ 1);
            cp_commit();
            cp_wait<1>();
        } else {
            cp_wait<0>();
        }
        __syncthreads();

        const __half* in_s = c4sm + bsel * C4_BUF_HALVES;
        const __half* w_s  = in_s + 324 * 24;

        #pragma unroll
        for (int tap = 0; tap < 9; tap++) {
            const int ky = tap / 3, kx = tap - 3 * (tap / 3);
            const __half* wb = w_s + (tap * 8 + gid) * 24 + 2 * tig;
            uint32_t b0 = *(const uint32_t*)(wb);
            uint32_t b1 = *(const uint32_t*)(wb + 8);
            #pragma unroll
            for (int mt = 0; mt < 2; mt++) {
                const int yl = 2 * w + mt;
                const __half* base = in_s + ((yl + ky) * 18 + kx) * 24 + 2 * tig;
                uint32_t a0 = *(const uint32_t*)(base + gid * 24);
                uint32_t a1 = *(const uint32_t*)(base + (gid + 8) * 24);
                uint32_t a2 = *(const uint32_t*)(base + gid * 24 + 8);
                uint32_t a3 = *(const uint32_t*)(base + (gid + 8) * 24 + 8);
                mma_f16(c[mt], a0, a1, a2, a3, b0, b1);
            }
        }
        __syncthreads();
    }

    if (tig < 2) {
        #pragma unroll
        for (int mt = 0; mt < 2; mt++) {
            const int y = y0 + 2 * w + mt;
            const int co0 = 2 * tig;
            const int x1 = x0 + gid, x2 = x0 + gid + 8;
            {
                int base = ((b*3 + co0) * NH + y) * NW;
                out[base + x1] = c[mt][0] + g_rgb[base + x1];
                out[base + x2] = c[mt][2] + g_rgb[base + x2];
            }
            if (co0 + 1 < 3) {
                int base = ((b*3 + co0 + 1) * NH + y) * NW;
                out[base + x1] = c[mt][1] + g_rgb[base + x1];
                out[base + x2] = c[mt][3] + g_rgb[base + x2];
            }
        }
    }
}

// ---------------------------------------------------------------------------
extern "C" void kernel_launch(void* const* d_in, const int* in_sizes, int n_in,
                              void* d_out, int out_size)
{
    const float* zbuf = (const float*)d_in[0];
    const float* ray  = (const float*)d_in[1];
    const float* w0 = (const float*)d_in[4];
    const float* b0 = (const float*)d_in[5];
    const float* w1 = (const float*)d_in[6];
    const float* b1 = (const float*)d_in[7];
    const float* w2 = (const float*)d_in[8];
    const float* b2 = (const float*)d_in[9];
    const float* k1 = (const float*)d_in[10];
    const float* k2 = (const float*)d_in[11];
    const float* k3 = (const float*)d_in[12];
    const float* k4 = (const float*)d_in[13];
    float* out = (float*)d_out;

    cudaFuncSetAttribute(mlp_kernel,
                         cudaFuncAttributeMaxDynamicSharedMemorySize, MLP_SMEM_BYTES);
    cudaFuncSetAttribute(conv13_kernel,
                         cudaFuncAttributeMaxDynamicSharedMemorySize, C13_SMEM_BYTES);
    cudaFuncSetAttribute(conv2_kernel,
                         cudaFuncAttributeMaxDynamicSharedMemorySize, C2_SMEM_BYTES);
    cudaFuncSetAttribute(conv4_kernel,
                         cudaFuncAttributeMaxDynamicSharedMemorySize, C4_SMEM_BYTES);

    const int prep_total = W1H_SZ + W2H_SZ + W3H_SZ + W4H_SZ + W1M_SZ + W2M_SZ;
    prep_weights<<<(prep_total + 255) / 256, 256>>>(k1, k2, k3, k4, w1, w2);

    mlp_kernel<<<(NB*NH*NW)/128, 256, MLP_SMEM_BYTES>>>(zbuf, ray, w0, b0, b1, b2);
    conv13_kernel<<<dim3(NW/16, NH/32, NB), 256, C13_SMEM_BYTES>>>(1, 0);
    conv2_kernel <<<dim3(16, 16, NB), 512, C2_SMEM_BYTES>>>();
    conv13_kernel<<<dim3(NW/16, NH/32, NB), 256, C13_SMEM_BYTES>>>(6, 1);
    conv4_kernel <<<dim3(NW/16, NH/16, NB), 256, C4_SMEM_BYTES>>>(out);
}